// round 1
// baseline (speedup 1.0000x reference)
#include <cuda_runtime.h>
#include <math.h>

#define NB 128          // batch (both feature sets)
#define S  49           // spatial tokens (7*7)
#define C  768          // channels
#define E  96           // inner dim
#define RTOT (2*NB*S)   // 12544 rows total (set a then set b)
#define EPSC 1e-8f
#define TS 100          // padded tile row stride (floats); 100 % 32 == 4 -> conflict-free

// ---------------- scratch (static device allocations; no cudaMalloc) ----------------
__device__ float g_X[(size_t)RTOT * C];   // transposed features [12544, 768]
__device__ float g_H[(size_t)RTOT * C];   // hidden buffer (reused per projection)
__device__ float g_Q[(size_t)RTOT * E];
__device__ float g_K[(size_t)RTOT * E];
__device__ float g_V[(size_t)RTOT * E];

// ---------------- transpose: [B,C,S] -> X[row=set*6272 + b*49 + s][c] ----------------
__global__ __launch_bounds__(256) void transpose_kernel(const float* __restrict__ fa,
                                                        const float* __restrict__ fb) {
    __shared__ float t[32][S + 1];
    int ct = blockIdx.x;      // 0..23 channel tile
    int b  = blockIdx.y;      // 0..127
    int set = blockIdx.z;     // 0: a, 1: b
    const float* F = set ? fb : fa;
    int c0 = ct * 32;
    const float* src = F + ((size_t)b * C + c0) * S;
    for (int idx = threadIdx.x; idx < 32 * S; idx += blockDim.x) {
        int i = idx / S, s = idx % S;
        t[i][s] = src[i * S + s];
    }
    __syncthreads();
    int rowbase = set * NB * S + b * S;
    for (int idx = threadIdx.x; idx < S * 32; idx += blockDim.x) {
        int s = idx >> 5, i = idx & 31;
        g_X[(size_t)(rowbase + s) * C + c0 + i] = t[i][s];
    }
}

// ---------------- SGEMM NN: C[M,N] = op(A[M,K] @ B[K,N]) ----------------
// BM=128, BN=64, BK=16, 256 threads, per-thread 8x4.
template <bool RELU>
__global__ __launch_bounds__(256) void gemm_nn(const float* __restrict__ A,
                                               const float* __restrict__ B,
                                               float* __restrict__ Cmat,
                                               int M, int N, int K) {
    __shared__ float sA[16][132];   // A tile transposed: sA[k][m]
    __shared__ float sB[16][64];
    int tid = threadIdx.x;
    int tx = tid & 15, ty = tid >> 4;
    int m0 = blockIdx.y * 128;
    int n0 = blockIdx.x * 64;

    float acc[8][4];
#pragma unroll
    for (int i = 0; i < 8; i++)
#pragma unroll
        for (int j = 0; j < 4; j++) acc[i][j] = 0.f;

    for (int kt = 0; kt < K; kt += 16) {
        // load A tile (128x16) as 512 float4, transpose to sA[k][m]
#pragma unroll
        for (int l = 0; l < 2; l++) {
            int f = tid * 2 + l;
            int m = f >> 2, j4 = f & 3;
            float4 v = make_float4(0.f, 0.f, 0.f, 0.f);
            if (m0 + m < M)
                v = *(const float4*)&A[(size_t)(m0 + m) * K + kt + j4 * 4];
            sA[j4 * 4 + 0][m] = v.x;
            sA[j4 * 4 + 1][m] = v.y;
            sA[j4 * 4 + 2][m] = v.z;
            sA[j4 * 4 + 3][m] = v.w;
        }
        // load B tile (16x64) as 256 float4
        {
            int j = tid >> 4, n4 = tid & 15;
            float4 v = make_float4(0.f, 0.f, 0.f, 0.f);
            if (n0 + n4 * 4 + 3 < N)
                v = *(const float4*)&B[(size_t)(kt + j) * N + n0 + n4 * 4];
            *(float4*)&sB[j][n4 * 4] = v;
        }
        __syncthreads();
#pragma unroll
        for (int j = 0; j < 16; j++) {
            float4 a0 = *(const float4*)&sA[j][ty * 8];
            float4 a1 = *(const float4*)&sA[j][ty * 8 + 4];
            float4 b0 = *(const float4*)&sB[j][tx * 4];
            float av[8] = {a0.x, a0.y, a0.z, a0.w, a1.x, a1.y, a1.z, a1.w};
            float bv[4] = {b0.x, b0.y, b0.z, b0.w};
#pragma unroll
            for (int i = 0; i < 8; i++)
#pragma unroll
                for (int jj = 0; jj < 4; jj++)
                    acc[i][jj] = fmaf(av[i], bv[jj], acc[i][jj]);
        }
        __syncthreads();
    }
    if (n0 + tx * 4 + 3 < N) {
#pragma unroll
        for (int i = 0; i < 8; i++) {
            int m = m0 + ty * 8 + i;
            if (m < M) {
                float4 v;
                v.x = acc[i][0]; v.y = acc[i][1]; v.z = acc[i][2]; v.w = acc[i][3];
                if (RELU) {
                    v.x = fmaxf(v.x, 0.f); v.y = fmaxf(v.y, 0.f);
                    v.z = fmaxf(v.z, 0.f); v.w = fmaxf(v.w, 0.f);
                }
                *(float4*)&Cmat[(size_t)m * N + n0 + tx * 4] = v;
            }
        }
    }
}

// ---------------- per-pair attention + cosine ----------------
__device__ __forceinline__ void load_tile(float* dst, const float* __restrict__ src, int tid) {
    for (int idx = tid; idx < S * (E / 4); idx += 256) {
        int r = idx / (E / 4), c4 = idx % (E / 4);
        float4 v = *(const float4*)&src[r * E + c4 * 4];
        *(float4*)&dst[r * TS + c4 * 4] = v;
    }
}

// One direction: scores = Q@K^T * scale, softmax rows, aligned = P@V,
// sum_q cos(Vc[q], aligned[q]).  Result valid on tid 0.
__device__ float compute_dir(const float* __restrict__ sQ, const float* __restrict__ sK,
                             const float* __restrict__ sV, const float* __restrict__ sVc,
                             float* __restrict__ sS, float* __restrict__ wsum, int tid) {
    int w = tid >> 5, lane = tid & 31;
    const float scale = 0.10206207261596577f;  // 1/sqrt(96)

    // scores + softmax (warp w owns rows q = w, w+8, ...)
    for (int q = w; q < S; q += 8) {
        const float4* q4 = (const float4*)(sQ + q * TS);
        int k1 = lane + 32;
        bool v1 = (k1 < S);
        const float4* k0p = (const float4*)(sK + lane * TS);
        const float4* k1p = (const float4*)(sK + (v1 ? k1 : (S - 1)) * TS);
        float a0 = 0.f, a1 = 0.f;
#pragma unroll
        for (int e = 0; e < E / 4; e++) {
            float4 qv = q4[e];
            float4 kv0 = k0p[e];
            float4 kv1 = k1p[e];
            a0 = fmaf(qv.x, kv0.x, a0); a0 = fmaf(qv.y, kv0.y, a0);
            a0 = fmaf(qv.z, kv0.z, a0); a0 = fmaf(qv.w, kv0.w, a0);
            a1 = fmaf(qv.x, kv1.x, a1); a1 = fmaf(qv.y, kv1.y, a1);
            a1 = fmaf(qv.z, kv1.z, a1); a1 = fmaf(qv.w, kv1.w, a1);
        }
        a0 *= scale; a1 *= scale;
        float mx = fmaxf(a0, v1 ? a1 : -1e30f);
#pragma unroll
        for (int o = 16; o; o >>= 1) mx = fmaxf(mx, __shfl_xor_sync(0xffffffffu, mx, o));
        float p0 = __expf(a0 - mx);
        float p1 = v1 ? __expf(a1 - mx) : 0.f;
        float sum = p0 + p1;
#pragma unroll
        for (int o = 16; o; o >>= 1) sum += __shfl_xor_sync(0xffffffffu, sum, o);
        float inv = __fdividef(1.f, sum);
        sS[q * 52 + lane] = p0 * inv;
        if (v1) sS[q * 52 + k1] = p1 * inv;
    }
    // no block sync needed: same warp writes & reads its own sS rows

    float csum = 0.f;
    bool act = (lane < E / 4);
    int c = act ? lane : (E / 4 - 1);
    for (int q = w; q < S; q += 8) {
        float4 acc = make_float4(0.f, 0.f, 0.f, 0.f);
        const float* prow = sS + q * 52;
#pragma unroll
        for (int k = 0; k < S; k++) {
            float p = prow[k];
            float4 vv = *(const float4*)(sV + k * TS + c * 4);
            acc.x = fmaf(p, vv.x, acc.x);
            acc.y = fmaf(p, vv.y, acc.y);
            acc.z = fmaf(p, vv.z, acc.z);
            acc.w = fmaf(p, vv.w, acc.w);
        }
        float4 vc = *(const float4*)(sVc + q * TS + c * 4);
        float num = acc.x * vc.x + acc.y * vc.y + acc.z * vc.z + acc.w * vc.w;
        float da  = acc.x * acc.x + acc.y * acc.y + acc.z * acc.z + acc.w * acc.w;
        float dc  = vc.x * vc.x + vc.y * vc.y + vc.z * vc.z + vc.w * vc.w;
        if (!act) { num = 0.f; da = 0.f; dc = 0.f; }
#pragma unroll
        for (int o = 16; o; o >>= 1) {
            num += __shfl_xor_sync(0xffffffffu, num, o);
            da  += __shfl_xor_sync(0xffffffffu, da, o);
            dc  += __shfl_xor_sync(0xffffffffu, dc, o);
        }
        if (lane == 0) {
            float na = fmaxf(sqrtf(da), EPSC);
            float nc = fmaxf(sqrtf(dc), EPSC);
            csum += num / (na * nc);
        }
    }
    if (lane == 0) wsum[w] = csum;
    __syncthreads();
    float tot = 0.f;
    if (tid == 0) {
#pragma unroll
        for (int i = 0; i < 8; i++) tot += wsum[i];
    }
    return tot;
}

__global__ __launch_bounds__(256) void pair_kernel(float* __restrict__ out) {
    extern __shared__ float sm[];
    float* sQ  = sm;
    float* sK  = sQ + S * TS;
    float* sV  = sK + S * TS;
    float* sVc = sV + S * TS;
    float* sS  = sVc + S * TS;   // S * 52
    float* wsum = sS + S * 52;   // 8

    int a = blockIdx.x, b = blockIdx.y;
    int tid = threadIdx.x;

    size_t offA = (size_t)a * S * E;                 // rows of set a
    size_t offB = (size_t)(NB + b) * S * E;          // rows of set b (offset 6272*E)

    // direction 1 (ba): Q=QB[b], K=KA[a], V=VA[a], Vc=VB[b]
    load_tile(sQ,  g_Q + offB, tid);
    load_tile(sK,  g_K + offA, tid);
    load_tile(sV,  g_V + offA, tid);
    load_tile(sVc, g_V + offB, tid);
    __syncthreads();
    float r1 = compute_dir(sQ, sK, sV, sVc, sS, wsum, tid);
    __syncthreads();

    // direction 2 (ab): Q=QA[a], K=KB[b], V=VB[b](=sVc), Vc=VA[a](=sV)
    load_tile(sQ, g_Q + offA, tid);
    load_tile(sK, g_K + offB, tid);
    __syncthreads();
    float r2 = compute_dir(sQ, sK, sVc, sV, sS, wsum, tid);

    if (tid == 0) out[b * NB + a] = (r1 + r2) * (1.0f / S);
}

// ---------------- launch ----------------
extern "C" void kernel_launch(void* const* d_in, const int* in_sizes, int n_in,
                              void* d_out, int out_size) {
    const float* fa  = (const float*)d_in[0];
    const float* fb  = (const float*)d_in[1];
    const float* Wq1 = (const float*)d_in[2];
    const float* Wq2 = (const float*)d_in[3];
    const float* Wk1 = (const float*)d_in[4];
    const float* Wk2 = (const float*)d_in[5];
    const float* Wv1 = (const float*)d_in[6];
    const float* Wv2 = (const float*)d_in[7];
    float* out = (float*)d_out;

    void *pX, *pH, *pQ, *pK, *pV;
    cudaGetSymbolAddress(&pX, g_X);
    cudaGetSymbolAddress(&pH, g_H);
    cudaGetSymbolAddress(&pQ, g_Q);
    cudaGetSymbolAddress(&pK, g_K);
    cudaGetSymbolAddress(&pV, g_V);

    const int smem_pair = (4 * S * TS + S * 52 + 8) * (int)sizeof(float);  // ~88.6 KB
    cudaFuncSetAttribute(pair_kernel, cudaFuncAttributeMaxDynamicSharedMemorySize, smem_pair);

    transpose_kernel<<<dim3(24, 128, 2), 256>>>(fa, fb);

    dim3 g1(C / 64, RTOT / 128);         // (12, 98)
    dim3 g2((E + 63) / 64, RTOT / 128);  // (2, 98)

    gemm_nn<true ><<<g1, 256>>>((const float*)pX, Wq1, (float*)pH, RTOT, C, C);
    gemm_nn<false><<<g2, 256>>>((const float*)pH, Wq2, (float*)pQ, RTOT, E, C);

    gemm_nn<true ><<<g1, 256>>>((const float*)pX, Wk1, (float*)pH, RTOT, C, C);
    gemm_nn<false><<<g2, 256>>>((const float*)pH, Wk2, (float*)pK, RTOT, E, C);

    gemm_nn<true ><<<g1, 256>>>((const float*)pX, Wv1, (float*)pH, RTOT, C, C);
    gemm_nn<false><<<g2, 256>>>((const float*)pH, Wv2, (float*)pV, RTOT, E, C);

    pair_kernel<<<dim3(NB, NB), 256, smem_pair>>>(out);
}

// round 2
// speedup vs baseline: 1.4306x; 1.4306x over previous
#include <cuda_runtime.h>
#include <math.h>

#define NB 128
#define S  49
#define C  768
#define E  96
#define RTOT (2*NB*S)   // 12544
#define EPSC 1e-8f
#define TS 100          // padded tile stride (floats); lane-stride 100 ≡ 4 mod 32 -> conflict-free
#define SSTR 52         // P-matrix row stride

// ---------------- scratch ----------------
__device__ float g_X[(size_t)RTOT * C];
__device__ float g_H[(size_t)RTOT * C];
__device__ float g_Q[(size_t)RTOT * E];
__device__ float g_K[(size_t)RTOT * E];
__device__ float g_V[(size_t)RTOT * E];

// ---------------- transpose: [B,C,S] -> X[row][c] ----------------
__global__ __launch_bounds__(256) void transpose_kernel(const float* __restrict__ fa,
                                                        const float* __restrict__ fb) {
    __shared__ float t[32][S + 1];
    int ct = blockIdx.x, b = blockIdx.y, set = blockIdx.z;
    const float* F = set ? fb : fa;
    int c0 = ct * 32;
    const float* src = F + ((size_t)b * C + c0) * S;
    for (int idx = threadIdx.x; idx < 32 * S; idx += blockDim.x) {
        int i = idx / S, s = idx % S;
        t[i][s] = src[i * S + s];
    }
    __syncthreads();
    int rowbase = set * NB * S + b * S;
    for (int idx = threadIdx.x; idx < S * 32; idx += blockDim.x) {
        int s = idx >> 5, i = idx & 31;
        g_X[(size_t)(rowbase + s) * C + c0 + i] = t[i][s];
    }
}

// ---------------- big GEMM: 128x128x8 double-buffered, M=12544,N=768,K=768, ReLU ----------------
__global__ __launch_bounds__(256) void gemm1_relu(const float* __restrict__ A,
                                                  const float* __restrict__ B,
                                                  float* __restrict__ Cmat) {
    __shared__ float sA[2][8][128];
    __shared__ float sB[2][8][128];
    int tid = threadIdx.x;
    int m0 = blockIdx.y * 128, n0 = blockIdx.x * 128;
    int am = tid >> 1, ak = (tid & 1) * 4;
    int bk = tid >> 5, bn = (tid & 31) * 4;
    int tx = tid & 15, ty = tid >> 4;

    const float* Aptr = A + (size_t)(m0 + am) * C + ak;
    const float* Bptr = B + (size_t)bk * C + n0 + bn;

    float acc[8][8];
#pragma unroll
    for (int i = 0; i < 8; i++)
#pragma unroll
        for (int j = 0; j < 8; j++) acc[i][j] = 0.f;

    // preload tile 0
    {
        float4 a0 = *(const float4*)Aptr;
        float4 b0 = *(const float4*)Bptr;
        sA[0][ak + 0][am] = a0.x; sA[0][ak + 1][am] = a0.y;
        sA[0][ak + 2][am] = a0.z; sA[0][ak + 3][am] = a0.w;
        *(float4*)&sB[0][bk][bn] = b0;
    }
    __syncthreads();

    const int NT = C / 8;  // 96
    for (int t = 0; t < NT; t++) {
        int buf = t & 1;
        float4 an, bv;
        if (t < NT - 1) {
            an = *(const float4*)(Aptr + (t + 1) * 8);
            bv = *(const float4*)(Bptr + (size_t)(t + 1) * 8 * C);
        }
#pragma unroll
        for (int k = 0; k < 8; k++) {
            float4 af0 = *(const float4*)&sA[buf][k][ty * 8];
            float4 af1 = *(const float4*)&sA[buf][k][ty * 8 + 4];
            float4 bf0 = *(const float4*)&sB[buf][k][tx * 4];
            float4 bf1 = *(const float4*)&sB[buf][k][tx * 4 + 64];
            float av[8] = {af0.x, af0.y, af0.z, af0.w, af1.x, af1.y, af1.z, af1.w};
            float bw[8] = {bf0.x, bf0.y, bf0.z, bf0.w, bf1.x, bf1.y, bf1.z, bf1.w};
#pragma unroll
            for (int i = 0; i < 8; i++)
#pragma unroll
                for (int j = 0; j < 8; j++)
                    acc[i][j] = fmaf(av[i], bw[j], acc[i][j]);
        }
        if (t < NT - 1) {
            int nb = buf ^ 1;
            sA[nb][ak + 0][am] = an.x; sA[nb][ak + 1][am] = an.y;
            sA[nb][ak + 2][am] = an.z; sA[nb][ak + 3][am] = an.w;
            *(float4*)&sB[nb][bk][bn] = bv;
            __syncthreads();
        }
    }

#pragma unroll
    for (int i = 0; i < 8; i++) {
        int m = m0 + ty * 8 + i;
        float4 o0, o1;
        o0.x = fmaxf(acc[i][0], 0.f); o0.y = fmaxf(acc[i][1], 0.f);
        o0.z = fmaxf(acc[i][2], 0.f); o0.w = fmaxf(acc[i][3], 0.f);
        o1.x = fmaxf(acc[i][4], 0.f); o1.y = fmaxf(acc[i][5], 0.f);
        o1.z = fmaxf(acc[i][6], 0.f); o1.w = fmaxf(acc[i][7], 0.f);
        *(float4*)&Cmat[(size_t)m * C + n0 + tx * 4]      = o0;
        *(float4*)&Cmat[(size_t)m * C + n0 + tx * 4 + 64] = o1;
    }
}

// ---------------- small GEMM (K=768 -> N=96) ----------------
template <bool RELU>
__global__ __launch_bounds__(256) void gemm_nn(const float* __restrict__ A,
                                               const float* __restrict__ B,
                                               float* __restrict__ Cmat,
                                               int M, int N, int K) {
    __shared__ float sA[16][132];
    __shared__ float sB[16][64];
    int tid = threadIdx.x;
    int tx = tid & 15, ty = tid >> 4;
    int m0 = blockIdx.y * 128;
    int n0 = blockIdx.x * 64;

    float acc[8][4];
#pragma unroll
    for (int i = 0; i < 8; i++)
#pragma unroll
        for (int j = 0; j < 4; j++) acc[i][j] = 0.f;

    for (int kt = 0; kt < K; kt += 16) {
#pragma unroll
        for (int l = 0; l < 2; l++) {
            int f = tid * 2 + l;
            int m = f >> 2, j4 = f & 3;
            float4 v = make_float4(0.f, 0.f, 0.f, 0.f);
            if (m0 + m < M)
                v = *(const float4*)&A[(size_t)(m0 + m) * K + kt + j4 * 4];
            sA[j4 * 4 + 0][m] = v.x; sA[j4 * 4 + 1][m] = v.y;
            sA[j4 * 4 + 2][m] = v.z; sA[j4 * 4 + 3][m] = v.w;
        }
        {
            int j = tid >> 4, n4 = tid & 15;
            float4 v = make_float4(0.f, 0.f, 0.f, 0.f);
            if (n0 + n4 * 4 + 3 < N)
                v = *(const float4*)&B[(size_t)(kt + j) * N + n0 + n4 * 4];
            *(float4*)&sB[j][n4 * 4] = v;
        }
        __syncthreads();
#pragma unroll
        for (int j = 0; j < 16; j++) {
            float4 a0 = *(const float4*)&sA[j][ty * 8];
            float4 a1 = *(const float4*)&sA[j][ty * 8 + 4];
            float4 b0 = *(const float4*)&sB[j][tx * 4];
            float av[8] = {a0.x, a0.y, a0.z, a0.w, a1.x, a1.y, a1.z, a1.w};
            float bv[4] = {b0.x, b0.y, b0.z, b0.w};
#pragma unroll
            for (int i = 0; i < 8; i++)
#pragma unroll
                for (int jj = 0; jj < 4; jj++)
                    acc[i][jj] = fmaf(av[i], bv[jj], acc[i][jj]);
        }
        __syncthreads();
    }
    if (n0 + tx * 4 + 3 < N) {
#pragma unroll
        for (int i = 0; i < 8; i++) {
            int m = m0 + ty * 8 + i;
            if (m < M) {
                float4 v;
                v.x = fmaxf(acc[i][0], RELU ? 0.f : acc[i][0]);
                v.x = acc[i][0]; v.y = acc[i][1]; v.z = acc[i][2]; v.w = acc[i][3];
                if (RELU) {
                    v.x = fmaxf(v.x, 0.f); v.y = fmaxf(v.y, 0.f);
                    v.z = fmaxf(v.z, 0.f); v.w = fmaxf(v.w, 0.f);
                }
                *(float4*)&Cmat[(size_t)m * N + n0 + tx * 4] = v;
            }
        }
    }
}

// ---------------- pair kernel ----------------
__device__ __forceinline__ void load_tile(float* dst, const float* __restrict__ src, int tid) {
    for (int idx = tid; idx < S * (E / 4); idx += 256) {
        int r = idx / (E / 4), c4 = idx % (E / 4);
        float4 v = *(const float4*)&src[r * E + c4 * 4];
        *(float4*)&dst[r * TS + c4 * 4] = v;
    }
}

// One direction. Each warp owns 7 q-rows (warps 0..6: rows w*6..w*6+5 plus a
// duplicate of row w*6 in slot 6; warp 7: rows 42..48). Result valid on tid 0.
__device__ float compute_dir(const float* __restrict__ sQ, const float* __restrict__ sK,
                             const float* __restrict__ sV, const float* __restrict__ sVc,
                             float* __restrict__ sS, float* __restrict__ wsum,
                             int w, int lane, int tid) {
    const float scale = 0.10206207261596577f;  // 1/sqrt(96)
    int r0 = w * 6;
    int rr[7];
#pragma unroll
    for (int i = 0; i < 6; i++) rr[i] = r0 + i;
    rr[6] = (w == 7) ? 48 : r0;   // duplicate slot for w<7 (benign rewrite of own row)
    int nr = (w == 7) ? 7 : 6;    // rows counted in cosine

    // ---- scores + softmax ----
    int k1 = lane + 32;
    bool v1 = (k1 < S);
    const float4* kp0 = (const float4*)(sK + lane * TS);
    const float4* kp1 = (const float4*)(sK + (v1 ? k1 : 0) * TS);

    float acc0[7], acc1[7];
#pragma unroll
    for (int i = 0; i < 7; i++) { acc0[i] = 0.f; acc1[i] = 0.f; }

#pragma unroll 4
    for (int c = 0; c < E / 4; c++) {
        float4 kv0 = kp0[c];
        float4 kv1 = kp1[c];
#pragma unroll
        for (int i = 0; i < 7; i++) {
            float4 qv = *(const float4*)(sQ + rr[i] * TS + c * 4);
            acc0[i] = fmaf(qv.x, kv0.x, acc0[i]); acc0[i] = fmaf(qv.y, kv0.y, acc0[i]);
            acc0[i] = fmaf(qv.z, kv0.z, acc0[i]); acc0[i] = fmaf(qv.w, kv0.w, acc0[i]);
            acc1[i] = fmaf(qv.x, kv1.x, acc1[i]); acc1[i] = fmaf(qv.y, kv1.y, acc1[i]);
            acc1[i] = fmaf(qv.z, kv1.z, acc1[i]); acc1[i] = fmaf(qv.w, kv1.w, acc1[i]);
        }
    }

#pragma unroll
    for (int i = 0; i < 7; i++) {
        float a0 = acc0[i] * scale;
        float a1 = v1 ? acc1[i] * scale : -1e30f;
        float mx = fmaxf(a0, a1);
#pragma unroll
        for (int o = 16; o; o >>= 1) mx = fmaxf(mx, __shfl_xor_sync(0xffffffffu, mx, o));
        float p0 = __expf(a0 - mx);
        float p1 = v1 ? __expf(a1 - mx) : 0.f;
        float sum = p0 + p1;
#pragma unroll
        for (int o = 16; o; o >>= 1) sum += __shfl_xor_sync(0xffffffffu, sum, o);
        float inv = __fdividef(1.f, sum);
        sS[rr[i] * SSTR + lane] = p0 * inv;
        if (v1) sS[rr[i] * SSTR + k1] = p1 * inv;
    }
    // warps only touch their own sS rows -> no block sync needed

    // ---- P @ V + cosine ----
    bool act = (lane < E / 4);
    int c = act ? lane : 0;
    float4 av[7];
#pragma unroll
    for (int i = 0; i < 7; i++) av[i] = make_float4(0.f, 0.f, 0.f, 0.f);

    for (int k = 0; k < S; k++) {
        float4 vv = *(const float4*)(sV + k * TS + c * 4);
#pragma unroll
        for (int i = 0; i < 7; i++) {
            float p = sS[rr[i] * SSTR + k];
            av[i].x = fmaf(p, vv.x, av[i].x);
            av[i].y = fmaf(p, vv.y, av[i].y);
            av[i].z = fmaf(p, vv.z, av[i].z);
            av[i].w = fmaf(p, vv.w, av[i].w);
        }
    }

    float csum = 0.f;
    for (int i = 0; i < nr; i++) {
        float4 vc = *(const float4*)(sVc + rr[i] * TS + c * 4);
        float num = av[i].x * vc.x + av[i].y * vc.y + av[i].z * vc.z + av[i].w * vc.w;
        float da  = av[i].x * av[i].x + av[i].y * av[i].y + av[i].z * av[i].z + av[i].w * av[i].w;
        float dc  = vc.x * vc.x + vc.y * vc.y + vc.z * vc.z + vc.w * vc.w;
        if (!act) { num = 0.f; da = 0.f; dc = 0.f; }
#pragma unroll
        for (int o = 16; o; o >>= 1) {
            num += __shfl_xor_sync(0xffffffffu, num, o);
            da  += __shfl_xor_sync(0xffffffffu, da, o);
            dc  += __shfl_xor_sync(0xffffffffu, dc, o);
        }
        if (lane == 0) {
            float na = fmaxf(sqrtf(da), EPSC);
            float nc = fmaxf(sqrtf(dc), EPSC);
            csum += num / (na * nc);
        }
    }
    if (lane == 0) wsum[w] = csum;
    __syncthreads();
    float tot = 0.f;
    if (tid == 0) {
#pragma unroll
        for (int i = 0; i < 8; i++) tot += wsum[i];
    }
    return tot;
}

__global__ __launch_bounds__(256) void pair_kernel(float* __restrict__ out) {
    extern __shared__ float sm[];
    float* sQ   = sm;
    float* sK   = sQ + S * TS;
    float* sV   = sK + S * TS;
    float* sVc  = sV + S * TS;
    float* sS   = sVc + S * TS;
    float* wsum = sS + S * SSTR;

    int a = blockIdx.x, b = blockIdx.y;
    int tid = threadIdx.x, w = tid >> 5, lane = tid & 31;

    size_t offA = (size_t)a * S * E;
    size_t offB = (size_t)(NB + b) * S * E;

    load_tile(sQ,  g_Q + offB, tid);
    load_tile(sK,  g_K + offA, tid);
    load_tile(sV,  g_V + offA, tid);
    load_tile(sVc, g_V + offB, tid);
    __syncthreads();
    float r1 = compute_dir(sQ, sK, sV, sVc, sS, wsum, w, lane, tid);
    __syncthreads();

    load_tile(sQ, g_Q + offA, tid);
    load_tile(sK, g_K + offB, tid);
    __syncthreads();
    float r2 = compute_dir(sQ, sK, sVc, sV, sS, wsum, w, lane, tid);

    if (tid == 0) out[b * NB + a] = (r1 + r2) * (1.0f / S);
}

// ---------------- launch ----------------
extern "C" void kernel_launch(void* const* d_in, const int* in_sizes, int n_in,
                              void* d_out, int out_size) {
    const float* fa  = (const float*)d_in[0];
    const float* fb  = (const float*)d_in[1];
    const float* Wq1 = (const float*)d_in[2];
    const float* Wq2 = (const float*)d_in[3];
    const float* Wk1 = (const float*)d_in[4];
    const float* Wk2 = (const float*)d_in[5];
    const float* Wv1 = (const float*)d_in[6];
    const float* Wv2 = (const float*)d_in[7];
    float* out = (float*)d_out;

    void *pX, *pH, *pQ, *pK, *pV;
    cudaGetSymbolAddress(&pX, g_X);
    cudaGetSymbolAddress(&pH, g_H);
    cudaGetSymbolAddress(&pQ, g_Q);
    cudaGetSymbolAddress(&pK, g_K);
    cudaGetSymbolAddress(&pV, g_V);

    const int smem_pair = (4 * S * TS + S * SSTR + 8) * (int)sizeof(float);
    cudaFuncSetAttribute(pair_kernel, cudaFuncAttributeMaxDynamicSharedMemorySize, smem_pair);

    transpose_kernel<<<dim3(24, 128, 2), 256>>>(fa, fb);

    dim3 gBig(C / 128, RTOT / 128);      // (6, 98)
    dim3 g2((E + 63) / 64, RTOT / 128);  // (2, 98)

    gemm1_relu<<<gBig, 256>>>((const float*)pX, Wq1, (float*)pH);
    gemm_nn<false><<<g2, 256>>>((const float*)pH, Wq2, (float*)pQ, RTOT, E, C);

    gemm1_relu<<<gBig, 256>>>((const float*)pX, Wk1, (float*)pH);
    gemm_nn<false><<<g2, 256>>>((const float*)pH, Wk2, (float*)pK, RTOT, E, C);

    gemm1_relu<<<gBig, 256>>>((const float*)pX, Wv1, (float*)pH);
    gemm_nn<false><<<g2, 256>>>((const float*)pH, Wv2, (float*)pV, RTOT, E, C);

    pair_kernel<<<dim3(NB, NB), 256, smem_pair>>>(out);
}

// round 4
// speedup vs baseline: 1.6552x; 1.1570x over previous
#include <cuda_runtime.h>
#include <math.h>
#include <stdint.h>

#define NB 128
#define S  49
#define C  768
#define E  96
#define RTOT (2*NB*S)   // 12544
#define EPSC 1e-8f
#define TS 100          // pair-kernel tile stride; 100 % 32 == 4 -> conflict-free
#define SSTR 52

// ---------------- scratch ----------------
__device__ float g_X[(size_t)RTOT * C];
__device__ float g_H[(size_t)RTOT * C];
__device__ float g_Q[(size_t)RTOT * E];
__device__ float g_K[(size_t)RTOT * E];
__device__ float g_V[(size_t)RTOT * E];

// ---------------- helpers ----------------
__device__ __forceinline__ uint32_t f2tf32(float f) {
    uint32_t r; asm("cvt.rna.tf32.f32 %0, %1;" : "=r"(r) : "f"(f)); return r;
}

__device__ __forceinline__ void mma_tf32(float c[4], uint32_t a0, uint32_t a1, uint32_t a2, uint32_t a3,
                                         uint32_t b0, uint32_t b1) {
    asm volatile("mma.sync.aligned.m16n8k8.row.col.f32.tf32.tf32.f32 "
                 "{%0,%1,%2,%3}, {%4,%5,%6,%7}, {%8,%9}, {%0,%1,%2,%3};"
                 : "+f"(c[0]), "+f"(c[1]), "+f"(c[2]), "+f"(c[3])
                 : "r"(a0), "r"(a1), "r"(a2), "r"(a3), "r"(b0), "r"(b1));
}

// ---------------- transpose: [B,C,S] -> X[row][c] ----------------
__global__ __launch_bounds__(256) void transpose_kernel(const float* __restrict__ fa,
                                                        const float* __restrict__ fb) {
    __shared__ float t[32][S + 1];
    int ct = blockIdx.x, b = blockIdx.y, set = blockIdx.z;
    const float* F = set ? fb : fa;
    int c0 = ct * 32;
    const float* src = F + ((size_t)b * C + c0) * S;
    for (int idx = threadIdx.x; idx < 32 * S; idx += blockDim.x) {
        int i = idx / S, s = idx % S;
        t[i][s] = src[i * S + s];
    }
    __syncthreads();
    int rowbase = set * NB * S + b * S;
    for (int idx = threadIdx.x; idx < S * 32; idx += blockDim.x) {
        int s = idx >> 5, i = idx & 31;
        g_X[(size_t)(rowbase + s) * C + c0 + i] = t[i][s];
    }
}

// ---------------- big GEMM (tf32 tensor cores): H = relu(X @ W1), 12544x768x768 ----------------
// block tile 128x128, BK=16, 8 warps each 64(m) x 32(n). smem stride 20 -> conflict-free frags.
#define G1_STR 20
__global__ __launch_bounds__(256) void gemm1_relu_tc(const float* __restrict__ A,
                                                     const float* __restrict__ B,
                                                     float* __restrict__ Cmat) {
    __shared__ uint32_t sA[2][128][G1_STR];
    __shared__ uint32_t sB[2][128][G1_STR];   // transposed: [n][k]

    int tid = threadIdx.x;
    int w = tid >> 5, lane = tid & 31;
    int g = lane >> 2, tig = lane & 3;
    int warpM = w >> 2, warpN = w & 3;            // 2 x 4 warps
    int mW = warpM * 64, nW = warpN * 32;
    int m0 = blockIdx.y * 128, n0 = blockIdx.x * 128;

    // gmem load assignment
    int arow = tid >> 1, ak8 = (tid & 1) * 8;     // A: 128 rows x 16 k
    int bkr = tid >> 4, bn8 = (tid & 15) * 8;     // B: 16 k x 128 n
    const float* Aptr = A + (size_t)(m0 + arow) * C + ak8;
    const float* Bptr = B + (size_t)bkr * C + n0 + bn8;

    float acc[4][4][4];
#pragma unroll
    for (int i = 0; i < 4; i++)
#pragma unroll
        for (int j = 0; j < 4; j++)
#pragma unroll
            for (int k = 0; k < 4; k++) acc[i][j][k] = 0.f;

    float4 ra0, ra1, rb0, rb1;
    // preload tile 0
    ra0 = *(const float4*)Aptr;           ra1 = *(const float4*)(Aptr + 4);
    rb0 = *(const float4*)Bptr;           rb1 = *(const float4*)(Bptr + 4);
    {
        uint32_t* d = &sA[0][arow][ak8];
        d[0]=f2tf32(ra0.x); d[1]=f2tf32(ra0.y); d[2]=f2tf32(ra0.z); d[3]=f2tf32(ra0.w);
        d[4]=f2tf32(ra1.x); d[5]=f2tf32(ra1.y); d[6]=f2tf32(ra1.z); d[7]=f2tf32(ra1.w);
        float bv[8] = {rb0.x,rb0.y,rb0.z,rb0.w,rb1.x,rb1.y,rb1.z,rb1.w};
#pragma unroll
        for (int j = 0; j < 8; j++) {
            int jj = (j + (tid & 15)) & 7;        // stagger to spread banks
            sB[0][bn8 + jj][bkr] = f2tf32(bv[jj]);
        }
    }
    __syncthreads();

    const int NT = C / 16;  // 48
    for (int t = 0; t < NT; t++) {
        int buf = t & 1;
        if (t < NT - 1) {
            const float* Ap = Aptr + (t + 1) * 16;
            const float* Bp = Bptr + (size_t)(t + 1) * 16 * C;
            ra0 = *(const float4*)Ap; ra1 = *(const float4*)(Ap + 4);
            rb0 = *(const float4*)Bp; rb1 = *(const float4*)(Bp + 4);
        }
#pragma unroll
        for (int ks = 0; ks < 16; ks += 8) {
            uint32_t afr[4][4];
#pragma unroll
            for (int mt = 0; mt < 4; mt++) {
                int r = mW + mt * 16 + g;
                afr[mt][0] = sA[buf][r    ][ks + tig];
                afr[mt][1] = sA[buf][r + 8][ks + tig];
                afr[mt][2] = sA[buf][r    ][ks + tig + 4];
                afr[mt][3] = sA[buf][r + 8][ks + tig + 4];
            }
            uint32_t bfr[4][2];
#pragma unroll
            for (int nt = 0; nt < 4; nt++) {
                int ncol = nW + nt * 8 + g;
                bfr[nt][0] = sB[buf][ncol][ks + tig];
                bfr[nt][1] = sB[buf][ncol][ks + tig + 4];
            }
#pragma unroll
            for (int mt = 0; mt < 4; mt++)
#pragma unroll
                for (int nt = 0; nt < 4; nt++)
                    mma_tf32(acc[mt][nt], afr[mt][0], afr[mt][1], afr[mt][2], afr[mt][3],
                             bfr[nt][0], bfr[nt][1]);
        }
        if (t < NT - 1) {
            int nb = buf ^ 1;
            uint32_t* d = &sA[nb][arow][ak8];
            d[0]=f2tf32(ra0.x); d[1]=f2tf32(ra0.y); d[2]=f2tf32(ra0.z); d[3]=f2tf32(ra0.w);
            d[4]=f2tf32(ra1.x); d[5]=f2tf32(ra1.y); d[6]=f2tf32(ra1.z); d[7]=f2tf32(ra1.w);
            float bv[8] = {rb0.x,rb0.y,rb0.z,rb0.w,rb1.x,rb1.y,rb1.z,rb1.w};
#pragma unroll
            for (int j = 0; j < 8; j++) {
                int jj = (j + (tid & 15)) & 7;
                sB[nb][bn8 + jj][bkr] = f2tf32(bv[jj]);
            }
            __syncthreads();
        }
    }

    // epilogue: ReLU + store (c0,c1 contiguous; c2,c3 at row+8)
#pragma unroll
    for (int mt = 0; mt < 4; mt++) {
        int r = m0 + mW + mt * 16 + g;
#pragma unroll
        for (int nt = 0; nt < 4; nt++) {
            int cc = n0 + nW + nt * 8 + tig * 2;
            float2 lo, hi;
            lo.x = fmaxf(acc[mt][nt][0], 0.f); lo.y = fmaxf(acc[mt][nt][1], 0.f);
            hi.x = fmaxf(acc[mt][nt][2], 0.f); hi.y = fmaxf(acc[mt][nt][3], 0.f);
            *(float2*)&Cmat[(size_t)r * C + cc]       = lo;
            *(float2*)&Cmat[(size_t)(r + 8) * C + cc] = hi;
        }
    }
}

// ---------------- small GEMM (K=768 -> N=96), fp32 ----------------
template <bool RELU>
__global__ __launch_bounds__(256) void gemm_nn(const float* __restrict__ A,
                                               const float* __restrict__ B,
                                               float* __restrict__ Cmat,
                                               int M, int N, int K) {
    __shared__ float sA[16][132];
    __shared__ float sB[16][64];
    int tid = threadIdx.x;
    int tx = tid & 15, ty = tid >> 4;
    int m0 = blockIdx.y * 128;
    int n0 = blockIdx.x * 64;

    float acc[8][4];
#pragma unroll
    for (int i = 0; i < 8; i++)
#pragma unroll
        for (int j = 0; j < 4; j++) acc[i][j] = 0.f;

    for (int kt = 0; kt < K; kt += 16) {
#pragma unroll
        for (int l = 0; l < 2; l++) {
            int f = tid * 2 + l;
            int m = f >> 2, j4 = f & 3;
            float4 v = make_float4(0.f, 0.f, 0.f, 0.f);
            if (m0 + m < M)
                v = *(const float4*)&A[(size_t)(m0 + m) * K + kt + j4 * 4];
            sA[j4 * 4 + 0][m] = v.x; sA[j4 * 4 + 1][m] = v.y;
            sA[j4 * 4 + 2][m] = v.z; sA[j4 * 4 + 3][m] = v.w;
        }
        {
            int j = tid >> 4, n4 = tid & 15;
            float4 v = make_float4(0.f, 0.f, 0.f, 0.f);
            if (n0 + n4 * 4 + 3 < N)
                v = *(const float4*)&B[(size_t)(kt + j) * N + n0 + n4 * 4];
            *(float4*)&sB[j][n4 * 4] = v;
        }
        __syncthreads();
#pragma unroll
        for (int j = 0; j < 16; j++) {
            float4 a0 = *(const float4*)&sA[j][ty * 8];
            float4 a1 = *(const float4*)&sA[j][ty * 8 + 4];
            float4 b0 = *(const float4*)&sB[j][tx * 4];
            float av[8] = {a0.x, a0.y, a0.z, a0.w, a1.x, a1.y, a1.z, a1.w};
            float bv[4] = {b0.x, b0.y, b0.z, b0.w};
#pragma unroll
            for (int i = 0; i < 8; i++)
#pragma unroll
                for (int jj = 0; jj < 4; jj++)
                    acc[i][jj] = fmaf(av[i], bv[jj], acc[i][jj]);
        }
        __syncthreads();
    }
    if (n0 + tx * 4 + 3 < N) {
#pragma unroll
        for (int i = 0; i < 8; i++) {
            int m = m0 + ty * 8 + i;
            if (m < M) {
                float4 v;
                v.x = acc[i][0]; v.y = acc[i][1]; v.z = acc[i][2]; v.w = acc[i][3];
                if (RELU) {
                    v.x = fmaxf(v.x, 0.f); v.y = fmaxf(v.y, 0.f);
                    v.z = fmaxf(v.z, 0.f); v.w = fmaxf(v.w, 0.f);
                }
                *(float4*)&Cmat[(size_t)m * N + n0 + tx * 4] = v;
            }
        }
    }
}

// ---------------- pair kernel (unchanged from R2) ----------------
__device__ __forceinline__ void load_tile(float* dst, const float* __restrict__ src, int tid) {
    for (int idx = tid; idx < S * (E / 4); idx += 256) {
        int r = idx / (E / 4), c4 = idx % (E / 4);
        float4 v = *(const float4*)&src[r * E + c4 * 4];
        *(float4*)&dst[r * TS + c4 * 4] = v;
    }
}

__device__ float compute_dir(const float* __restrict__ sQ, const float* __restrict__ sK,
                             const float* __restrict__ sV, const float* __restrict__ sVc,
                             float* __restrict__ sS, float* __restrict__ wsum,
                             int w, int lane, int tid) {
    const float scale = 0.10206207261596577f;  // 1/sqrt(96)
    int r0 = w * 6;
    int rr[7];
#pragma unroll
    for (int i = 0; i < 6; i++) rr[i] = r0 + i;
    rr[6] = (w == 7) ? 48 : r0;
    int nr = (w == 7) ? 7 : 6;

    int k1 = lane + 32;
    bool v1 = (k1 < S);
    const float4* kp0 = (const float4*)(sK + lane * TS);
    const float4* kp1 = (const float4*)(sK + (v1 ? k1 : 0) * TS);

    float acc0[7], acc1[7];
#pragma unroll
    for (int i = 0; i < 7; i++) { acc0[i] = 0.f; acc1[i] = 0.f; }

#pragma unroll 4
    for (int c = 0; c < E / 4; c++) {
        float4 kv0 = kp0[c];
        float4 kv1 = kp1[c];
#pragma unroll
        for (int i = 0; i < 7; i++) {
            float4 qv = *(const float4*)(sQ + rr[i] * TS + c * 4);
            acc0[i] = fmaf(qv.x, kv0.x, acc0[i]); acc0[i] = fmaf(qv.y, kv0.y, acc0[i]);
            acc0[i] = fmaf(qv.z, kv0.z, acc0[i]); acc0[i] = fmaf(qv.w, kv0.w, acc0[i]);
            acc1[i] = fmaf(qv.x, kv1.x, acc1[i]); acc1[i] = fmaf(qv.y, kv1.y, acc1[i]);
            acc1[i] = fmaf(qv.z, kv1.z, acc1[i]); acc1[i] = fmaf(qv.w, kv1.w, acc1[i]);
        }
    }

#pragma unroll
    for (int i = 0; i < 7; i++) {
        float a0 = acc0[i] * scale;
        float a1 = v1 ? acc1[i] * scale : -1e30f;
        float mx = fmaxf(a0, a1);
#pragma unroll
        for (int o = 16; o; o >>= 1) mx = fmaxf(mx, __shfl_xor_sync(0xffffffffu, mx, o));
        float p0 = __expf(a0 - mx);
        float p1 = v1 ? __expf(a1 - mx) : 0.f;
        float sum = p0 + p1;
#pragma unroll
        for (int o = 16; o; o >>= 1) sum += __shfl_xor_sync(0xffffffffu, sum, o);
        float inv = __fdividef(1.f, sum);
        sS[rr[i] * SSTR + lane] = p0 * inv;
        if (v1) sS[rr[i] * SSTR + k1] = p1 * inv;
    }

    bool act = (lane < E / 4);
    int c = act ? lane : 0;
    float4 av[7];
#pragma unroll
    for (int i = 0; i < 7; i++) av[i] = make_float4(0.f, 0.f, 0.f, 0.f);

    for (int k = 0; k < S; k++) {
        float4 vv = *(const float4*)(sV + k * TS + c * 4);
#pragma unroll
        for (int i = 0; i < 7; i++) {
            float p = sS[rr[i] * SSTR + k];
            av[i].x = fmaf(p, vv.x, av[i].x);
            av[i].y = fmaf(p, vv.y, av[i].y);
            av[i].z = fmaf(p, vv.z, av[i].z);
            av[i].w = fmaf(p, vv.w, av[i].w);
        }
    }

    float csum = 0.f;
    for (int i = 0; i < nr; i++) {
        float4 vc = *(const float4*)(sVc + rr[i] * TS + c * 4);
        float num = av[i].x * vc.x + av[i].y * vc.y + av[i].z * vc.z + av[i].w * vc.w;
        float da  = av[i].x * av[i].x + av[i].y * av[i].y + av[i].z * av[i].z + av[i].w * av[i].w;
        float dc  = vc.x * vc.x + vc.y * vc.y + vc.z * vc.z + vc.w * vc.w;
        if (!act) { num = 0.f; da = 0.f; dc = 0.f; }
#pragma unroll
        for (int o = 16; o; o >>= 1) {
            num += __shfl_xor_sync(0xffffffffu, num, o);
            da  += __shfl_xor_sync(0xffffffffu, da, o);
            dc  += __shfl_xor_sync(0xffffffffu, dc, o);
        }
        if (lane == 0) {
            float na = fmaxf(sqrtf(da), EPSC);
            float nc = fmaxf(sqrtf(dc), EPSC);
            csum += num / (na * nc);
        }
    }
    if (lane == 0) wsum[w] = csum;
    __syncthreads();
    float tot = 0.f;
    if (tid == 0) {
#pragma unroll
        for (int i = 0; i < 8; i++) tot += wsum[i];
    }
    return tot;
}

__global__ __launch_bounds__(256) void pair_kernel(float* __restrict__ out) {
    extern __shared__ float sm[];
    float* sQ   = sm;
    float* sK   = sQ + S * TS;
    float* sV   = sK + S * TS;
    float* sVc  = sV + S * TS;
    float* sS   = sVc + S * TS;
    float* wsum = sS + S * SSTR;

    int a = blockIdx.x, b = blockIdx.y;
    int tid = threadIdx.x, w = tid >> 5, lane = tid & 31;

    size_t offA = (size_t)a * S * E;
    size_t offB = (size_t)(NB + b) * S * E;

    load_tile(sQ,  g_Q + offB, tid);
    load_tile(sK,  g_K + offA, tid);
    load_tile(sV,  g_V + offA, tid);
    load_tile(sVc, g_V + offB, tid);
    __syncthreads();
    float r1 = compute_dir(sQ, sK, sV, sVc, sS, wsum, w, lane, tid);
    __syncthreads();

    load_tile(sQ, g_Q + offA, tid);
    load_tile(sK, g_K + offB, tid);
    __syncthreads();
    float r2 = compute_dir(sQ, sK, sVc, sV, sS, wsum, w, lane, tid);

    if (tid == 0) out[b * NB + a] = (r1 + r2) * (1.0f / S);
}

// ---------------- launch ----------------
extern "C" void kernel_launch(void* const* d_in, const int* in_sizes, int n_in,
                              void* d_out, int out_size) {
    const float* fa  = (const float*)d_in[0];
    const float* fb  = (const float*)d_in[1];
    const float* Wq1 = (const float*)d_in[2];
    const float* Wq2 = (const float*)d_in[3];
    const float* Wk1 = (const float*)d_in[4];
    const float* Wk2 = (const float*)d_in[5];
    const float* Wv1 = (const float*)d_in[6];
    const float* Wv2 = (const float*)d_in[7];
    float* out = (float*)d_out;

    void *pX, *pH, *pQ, *pK, *pV;
    cudaGetSymbolAddress(&pX, g_X);
    cudaGetSymbolAddress(&pH, g_H);
    cudaGetSymbolAddress(&pQ, g_Q);
    cudaGetSymbolAddress(&pK, g_K);
    cudaGetSymbolAddress(&pV, g_V);

    const int smem_pair = (4 * S * TS + S * SSTR + 8) * (int)sizeof(float);
    cudaFuncSetAttribute(pair_kernel, cudaFuncAttributeMaxDynamicSharedMemorySize, smem_pair);

    transpose_kernel<<<dim3(24, 128, 2), 256>>>(fa, fb);

    dim3 gBig(C / 128, RTOT / 128);      // (6, 98)
    dim3 g2((E + 63) / 64, RTOT / 128);  // (2, 98)

    gemm1_relu_tc<<<gBig, 256>>>((const float*)pX, Wq1, (float*)pH);
    gemm_nn<false><<<g2, 256>>>((const float*)pH, Wq2, (float*)pQ, RTOT, E, C);

    gemm1_relu_tc<<<gBig, 256>>>((const float*)pX, Wk1, (float*)pH);
    gemm_nn<false><<<g2, 256>>>((const float*)pH, Wk2, (float*)pK, RTOT, E, C);

    gemm1_relu_tc<<<gBig, 256>>>((const float*)pX, Wv1, (float*)pH);
    gemm_nn<false><<<g2, 256>>>((const float*)pH, Wv2, (float*)pV, RTOT, E, C);

    pair_kernel<<<dim3(NB, NB), 256, smem_pair>>>(out);
}

// round 5
// speedup vs baseline: 1.8837x; 1.1381x over previous
#include <cuda_runtime.h>
#include <math.h>
#include <stdint.h>

#define NB 128
#define S  49
#define C  768
#define E  96
#define RTOT (2*NB*S)   // 12544
#define EPSC 1e-8f

#define QS  100   // Q/K smem stride (words), ≡4 mod 32
#define PS  60    // P smem stride, ≡28 mod 32
#define VS  60    // Vt smem stride
#define ALS 100   // aligned smem stride
#define VTG 64    // g_Vt padded cols

// ---------------- scratch ----------------
__device__ uint32_t g_X[(size_t)RTOT * C];        // tf32 transposed features
__device__ float    g_H[(size_t)RTOT * C];
__device__ float    g_Q[(size_t)RTOT * E];
__device__ float    g_K[(size_t)RTOT * E];
__device__ float    g_V[(size_t)RTOT * E];
__device__ uint32_t g_Vt[(size_t)2 * NB * E * VTG]; // tf32 V-transposed per image
__device__ uint32_t g_Wt[(size_t)C * C];          // tf32 weight staging

// ---------------- helpers ----------------
__device__ __forceinline__ uint32_t f2tf32(float f) {
    uint32_t r; asm("cvt.rna.tf32.f32 %0, %1;" : "=r"(r) : "f"(f)); return r;
}
__device__ __forceinline__ void mma_tf32(float c[4], uint32_t a0, uint32_t a1, uint32_t a2, uint32_t a3,
                                         uint32_t b0, uint32_t b1) {
    asm volatile("mma.sync.aligned.m16n8k8.row.col.f32.tf32.tf32.f32 "
                 "{%0,%1,%2,%3}, {%4,%5,%6,%7}, {%8,%9}, {%0,%1,%2,%3};"
                 : "+f"(c[0]), "+f"(c[1]), "+f"(c[2]), "+f"(c[3])
                 : "r"(a0), "r"(a1), "r"(a2), "r"(a3), "r"(b0), "r"(b1));
}

// ---------------- transpose: [B,C,S] -> X[row][c] (tf32) ----------------
__global__ __launch_bounds__(256) void transpose_kernel(const float* __restrict__ fa,
                                                        const float* __restrict__ fb) {
    __shared__ float t[32][S + 1];
    int ct = blockIdx.x, b = blockIdx.y, set = blockIdx.z;
    const float* F = set ? fb : fa;
    int c0 = ct * 32;
    const float* src = F + ((size_t)b * C + c0) * S;
    for (int idx = threadIdx.x; idx < 32 * S; idx += blockDim.x) {
        int i = idx / S, s = idx % S;
        t[i][s] = src[i * S + s];
    }
    __syncthreads();
    int rowbase = set * NB * S + b * S;
    for (int idx = threadIdx.x; idx < S * 32; idx += blockDim.x) {
        int s = idx >> 5, i = idx & 31;
        g_X[(size_t)(rowbase + s) * C + c0 + i] = f2tf32(t[i][s]);
    }
}

// ---------------- weight -> tf32 staging ----------------
__global__ __launch_bounds__(256) void convw_kernel(const float* __restrict__ W) {
    int i = (blockIdx.x * 256 + threadIdx.x) * 4;
    float4 v = *(const float4*)&W[i];
    uint4 u = make_uint4(f2tf32(v.x), f2tf32(v.y), f2tf32(v.z), f2tf32(v.w));
    *(uint4*)&g_Wt[i] = u;
}

// ---------------- V transpose per image: g_V[img][k][e] -> g_Vt[img][e][64] tf32 ----------------
__global__ __launch_bounds__(256) void vtrans_kernel() {
    __shared__ float sm[E][S + 1];
    int img = blockIdx.x;
    const float* src = g_V + (size_t)img * S * E;
    for (int idx = threadIdx.x; idx < S * E; idx += 256) {
        int k = idx / E, e = idx % E;
        sm[e][k] = src[idx];
    }
    __syncthreads();
    uint32_t* dst = g_Vt + (size_t)img * E * VTG;
    for (int idx = threadIdx.x; idx < E * VTG; idx += 256) {
        int e = idx / VTG, k = idx % VTG;
        dst[idx] = (k < S) ? f2tf32(sm[e][k]) : 0u;
    }
}

// ---------------- big GEMM (tf32 TC, no cvt): H = relu(X @ W1) ----------------
__global__ __launch_bounds__(256) void gemm1_relu_tc(const uint32_t* __restrict__ A,
                                                     const uint32_t* __restrict__ B,
                                                     float* __restrict__ Cmat) {
    __shared__ uint32_t sA[2][128][20];
    __shared__ uint32_t sB[2][16][132];

    int tid = threadIdx.x;
    int w = tid >> 5, lane = tid & 31;
    int g = lane >> 2, tig = lane & 3;
    int warpM = w >> 2, warpN = w & 3;
    int mW = warpM * 64, nW = warpN * 32;
    int m0 = blockIdx.y * 128, n0 = blockIdx.x * 128;

    int arow = tid >> 1, ak8 = (tid & 1) * 8;
    int bkr = tid >> 4, bn8 = (tid & 15) * 8;
    const uint32_t* Aptr = A + (size_t)(m0 + arow) * C + ak8;
    const uint32_t* Bptr = B + (size_t)bkr * C + n0 + bn8;

    float acc[4][4][4];
#pragma unroll
    for (int i = 0; i < 4; i++)
#pragma unroll
        for (int j = 0; j < 4; j++)
#pragma unroll
            for (int k = 0; k < 4; k++) acc[i][j][k] = 0.f;

    uint4 ra0, ra1, rb0, rb1;
    ra0 = *(const uint4*)Aptr;       ra1 = *(const uint4*)(Aptr + 4);
    rb0 = *(const uint4*)Bptr;       rb1 = *(const uint4*)(Bptr + 4);
    *(uint4*)&sA[0][arow][ak8]     = ra0;
    *(uint4*)&sA[0][arow][ak8 + 4] = ra1;
    *(uint4*)&sB[0][bkr][bn8]      = rb0;
    *(uint4*)&sB[0][bkr][bn8 + 4]  = rb1;
    __syncthreads();

    const int NT = C / 16;  // 48
    for (int t = 0; t < NT; t++) {
        int buf = t & 1;
        if (t < NT - 1) {
            const uint32_t* Ap = Aptr + (t + 1) * 16;
            const uint32_t* Bp = Bptr + (size_t)(t + 1) * 16 * C;
            ra0 = *(const uint4*)Ap; ra1 = *(const uint4*)(Ap + 4);
            rb0 = *(const uint4*)Bp; rb1 = *(const uint4*)(Bp + 4);
        }
#pragma unroll
        for (int ks = 0; ks < 16; ks += 8) {
            uint32_t afr[4][4];
#pragma unroll
            for (int mt = 0; mt < 4; mt++) {
                int r = mW + mt * 16 + g;
                afr[mt][0] = sA[buf][r    ][ks + tig];
                afr[mt][1] = sA[buf][r + 8][ks + tig];
                afr[mt][2] = sA[buf][r    ][ks + tig + 4];
                afr[mt][3] = sA[buf][r + 8][ks + tig + 4];
            }
            uint32_t bfr[4][2];
#pragma unroll
            for (int nt = 0; nt < 4; nt++) {
                int ncol = nW + nt * 8 + g;
                bfr[nt][0] = sB[buf][ks + tig    ][ncol];
                bfr[nt][1] = sB[buf][ks + tig + 4][ncol];
            }
#pragma unroll
            for (int mt = 0; mt < 4; mt++)
#pragma unroll
                for (int nt = 0; nt < 4; nt++)
                    mma_tf32(acc[mt][nt], afr[mt][0], afr[mt][1], afr[mt][2], afr[mt][3],
                             bfr[nt][0], bfr[nt][1]);
        }
        if (t < NT - 1) {
            int nb = buf ^ 1;
            *(uint4*)&sA[nb][arow][ak8]     = ra0;
            *(uint4*)&sA[nb][arow][ak8 + 4] = ra1;
            *(uint4*)&sB[nb][bkr][bn8]      = rb0;
            *(uint4*)&sB[nb][bkr][bn8 + 4]  = rb1;
            __syncthreads();
        }
    }

#pragma unroll
    for (int mt = 0; mt < 4; mt++) {
        int r = m0 + mW + mt * 16 + g;
#pragma unroll
        for (int nt = 0; nt < 4; nt++) {
            int cc = n0 + nW + nt * 8 + tig * 2;
            float2 lo, hi;
            lo.x = fmaxf(acc[mt][nt][0], 0.f); lo.y = fmaxf(acc[mt][nt][1], 0.f);
            hi.x = fmaxf(acc[mt][nt][2], 0.f); hi.y = fmaxf(acc[mt][nt][3], 0.f);
            *(float2*)&Cmat[(size_t)r * C + cc]       = lo;
            *(float2*)&Cmat[(size_t)(r + 8) * C + cc] = hi;
        }
    }
}

// ---------------- small GEMM (K=768 -> N=96), fp32 ----------------
__global__ __launch_bounds__(256) void gemm_nn(const float* __restrict__ A,
                                               const float* __restrict__ B,
                                               float* __restrict__ Cmat,
                                               int M, int N, int K) {
    __shared__ float sA[16][132];
    __shared__ float sB[16][64];
    int tid = threadIdx.x;
    int tx = tid & 15, ty = tid >> 4;
    int m0 = blockIdx.y * 128;
    int n0 = blockIdx.x * 64;

    float acc[8][4];
#pragma unroll
    for (int i = 0; i < 8; i++)
#pragma unroll
        for (int j = 0; j < 4; j++) acc[i][j] = 0.f;

    for (int kt = 0; kt < K; kt += 16) {
#pragma unroll
        for (int l = 0; l < 2; l++) {
            int f = tid * 2 + l;
            int m = f >> 2, j4 = f & 3;
            float4 v = *(const float4*)&A[(size_t)(m0 + m) * K + kt + j4 * 4];
            sA[j4 * 4 + 0][m] = v.x; sA[j4 * 4 + 1][m] = v.y;
            sA[j4 * 4 + 2][m] = v.z; sA[j4 * 4 + 3][m] = v.w;
        }
        {
            int j = tid >> 4, n4 = tid & 15;
            float4 v = make_float4(0.f, 0.f, 0.f, 0.f);
            if (n0 + n4 * 4 + 3 < N)
                v = *(const float4*)&B[(size_t)(kt + j) * N + n0 + n4 * 4];
            *(float4*)&sB[j][n4 * 4] = v;
        }
        __syncthreads();
#pragma unroll
        for (int j = 0; j < 16; j++) {
            float4 a0 = *(const float4*)&sA[j][ty * 8];
            float4 a1 = *(const float4*)&sA[j][ty * 8 + 4];
            float4 b0 = *(const float4*)&sB[j][tx * 4];
            float av[8] = {a0.x, a0.y, a0.z, a0.w, a1.x, a1.y, a1.z, a1.w};
            float bv[4] = {b0.x, b0.y, b0.z, b0.w};
#pragma unroll
            for (int i = 0; i < 8; i++)
#pragma unroll
                for (int jj = 0; jj < 4; jj++)
                    acc[i][jj] = fmaf(av[i], bv[jj], acc[i][jj]);
        }
        __syncthreads();
    }
    if (n0 + tx * 4 + 3 < N) {
#pragma unroll
        for (int i = 0; i < 8; i++) {
            int m = m0 + ty * 8 + i;
            float4 v;
            v.x = acc[i][0]; v.y = acc[i][1]; v.z = acc[i][2]; v.w = acc[i][3];
            *(float4*)&Cmat[(size_t)m * N + n0 + tx * 4] = v;
        }
    }
}

// ---------------- pair kernel: tensor-core attention + cosine ----------------
__global__ __launch_bounds__(256, 2) void pair_tc(float* __restrict__ out) {
    extern __shared__ uint32_t smbuf[];
    uint32_t* uQ  = smbuf;               // 49*100 (A-frag reads may spill into uK: benign, ignored rows)
    uint32_t* uK  = uQ + S * QS;         // 49*100
    uint32_t* uVt = uK + S * QS;         // 96*60
    uint32_t* uP  = uVt + E * VS;        // 64*60
    float*    fAl = (float*)(uP + 64 * PS);  // 64*100
    float*    wsum = fAl + 64 * ALS;     // 8

    int a = blockIdx.x, b = blockIdx.y;
    int tid = threadIdx.x, w = tid >> 5, lane = tid & 31;
    int g = lane >> 2, tig = lane & 3;
    const float scale = 0.10206207261596577f;  // 1/sqrt(96)

    float res0 = 0.f, res1 = 0.f;

#pragma unroll 1
    for (int dir = 0; dir < 2; dir++) {
        int qi = dir ? a : (NB + b);   // Q image
        int ki = dir ? (NB + b) : a;   // K image (= V image for PV)
        // cosine ref = V of the Q image (fp32, from global)

        // ---- loads ----
        {
            const float* q = g_Q + (size_t)qi * S * E;
            const float* k = g_K + (size_t)ki * S * E;
            for (int idx = tid; idx < S * (E / 4); idx += 256) {
                int r = idx / (E / 4), c4 = (idx % (E / 4)) * 4;
                float4 v = *(const float4*)&q[r * E + c4];
                *(uint4*)&uQ[r * QS + c4] = make_uint4(f2tf32(v.x), f2tf32(v.y), f2tf32(v.z), f2tf32(v.w));
                float4 u = *(const float4*)&k[r * E + c4];
                *(uint4*)&uK[r * QS + c4] = make_uint4(f2tf32(u.x), f2tf32(u.y), f2tf32(u.z), f2tf32(u.w));
            }
            const uint32_t* vt = g_Vt + (size_t)ki * E * VTG;
            for (int idx = tid; idx < E * (VS / 4); idx += 256) {
                int r = idx / (VS / 4), c4 = (idx % (VS / 4)) * 4;
                *(uint4*)&uVt[r * VS + c4] = *(const uint4*)&vt[r * VTG + c4];
            }
        }
        __syncthreads();

        // ---- scores: S = Q @ K^T (64x56 padded), write raw floats to uP ----
        for (int t = w; t < 28; t += 8) {
            int mt = t / 7, nt = t % 7;
            int ra = mt * 16 + g;
            int nc = nt * 8 + g;
            float c[4] = {0.f, 0.f, 0.f, 0.f};
#pragma unroll
            for (int ks = 0; ks < E; ks += 8) {
                uint32_t a0 = uQ[ra * QS + ks + tig];
                uint32_t a1 = uQ[(ra + 8) * QS + ks + tig];
                uint32_t a2 = uQ[ra * QS + ks + tig + 4];
                uint32_t a3 = uQ[(ra + 8) * QS + ks + tig + 4];
                uint32_t b0 = uK[nc * QS + ks + tig];
                uint32_t b1 = uK[nc * QS + ks + tig + 4];
                mma_tf32(c, a0, a1, a2, a3, b0, b1);
            }
            float* Pf = (float*)uP;
            Pf[ra * PS + nt * 8 + tig * 2]           = c[0];
            Pf[ra * PS + nt * 8 + tig * 2 + 1]       = c[1];
            Pf[(ra + 8) * PS + nt * 8 + tig * 2]     = c[2];
            Pf[(ra + 8) * PS + nt * 8 + tig * 2 + 1] = c[3];
        }
        __syncthreads();

        // ---- softmax rows (write P back as tf32; zero pad cols 49..55) ----
        {
            float* Pf = (float*)uP;
            for (int r = w; r < S; r += 8) {
                float s0 = Pf[r * PS + lane] * scale;
                int l1 = lane + 32;
                bool v1 = (l1 < S);
                float s1 = v1 ? Pf[r * PS + l1] * scale : -1e30f;
                float mx = fmaxf(s0, s1);
#pragma unroll
                for (int o = 16; o; o >>= 1) mx = fmaxf(mx, __shfl_xor_sync(0xffffffffu, mx, o));
                float p0 = __expf(s0 - mx);
                float p1 = v1 ? __expf(s1 - mx) : 0.f;
                float su = p0 + p1;
#pragma unroll
                for (int o = 16; o; o >>= 1) su += __shfl_xor_sync(0xffffffffu, su, o);
                float inv = __fdividef(1.f, su);
                uP[r * PS + lane] = f2tf32(p0 * inv);
                if (v1) uP[r * PS + l1] = f2tf32(p1 * inv);
                else if (l1 < 56) uP[r * PS + l1] = 0u;
            }
        }
        __syncthreads();

        // ---- PV: aligned = P(64x56) @ V(56x96) via Vt B-frags ----
        float alc[6][4];
#pragma unroll
        for (int i = 0; i < 6; i++)
#pragma unroll
            for (int j = 0; j < 4; j++) alc[i][j] = 0.f;
#pragma unroll
        for (int ti = 0; ti < 6; ti++) {
            int t = w + ti * 8;
            int mt = t / 12, et = t % 12;
            int ra = mt * 16 + g;
            int nc = et * 8 + g;
#pragma unroll
            for (int ks = 0; ks < 56; ks += 8) {
                uint32_t a0 = uP[ra * PS + ks + tig];
                uint32_t a1 = uP[(ra + 8) * PS + ks + tig];
                uint32_t a2 = uP[ra * PS + ks + tig + 4];
                uint32_t a3 = uP[(ra + 8) * PS + ks + tig + 4];
                uint32_t b0 = uVt[nc * VS + ks + tig];
                uint32_t b1 = uVt[nc * VS + ks + tig + 4];
                mma_tf32(alc[ti], a0, a1, a2, a3, b0, b1);
            }
        }
        __syncthreads();
#pragma unroll
        for (int ti = 0; ti < 6; ti++) {
            int t = w + ti * 8;
            int mt = t / 12, et = t % 12;
            int ra = mt * 16 + g;
            fAl[ra * ALS + et * 8 + tig * 2]           = alc[ti][0];
            fAl[ra * ALS + et * 8 + tig * 2 + 1]       = alc[ti][1];
            fAl[(ra + 8) * ALS + et * 8 + tig * 2]     = alc[ti][2];
            fAl[(ra + 8) * ALS + et * 8 + tig * 2 + 1] = alc[ti][3];
        }
        __syncthreads();

        // ---- cosine(aligned, Vref) summed over q-rows ----
        {
            const float* vref = g_V + (size_t)qi * S * E;
            float csum = 0.f;
            bool act = (lane < E / 4);
            int cc = act ? lane : 0;
            for (int r = w; r < S; r += 8) {
                float4 al = *(const float4*)&fAl[r * ALS + cc * 4];
                float4 vc = *(const float4*)&vref[r * E + cc * 4];
                float num = al.x * vc.x + al.y * vc.y + al.z * vc.z + al.w * vc.w;
                float da  = al.x * al.x + al.y * al.y + al.z * al.z + al.w * al.w;
                float dc  = vc.x * vc.x + vc.y * vc.y + vc.z * vc.z + vc.w * vc.w;
                if (!act) { num = 0.f; da = 0.f; dc = 0.f; }
#pragma unroll
                for (int o = 16; o; o >>= 1) {
                    num += __shfl_xor_sync(0xffffffffu, num, o);
                    da  += __shfl_xor_sync(0xffffffffu, da, o);
                    dc  += __shfl_xor_sync(0xffffffffu, dc, o);
                }
                if (lane == 0) {
                    float na = fmaxf(sqrtf(da), EPSC);
                    float nc = fmaxf(sqrtf(dc), EPSC);
                    csum += num / (na * nc);
                }
            }
            if (lane == 0) wsum[w] = csum;
        }
        __syncthreads();
        if (tid == 0) {
            float tot = 0.f;
#pragma unroll
            for (int i = 0; i < 8; i++) tot += wsum[i];
            if (dir == 0) res0 = tot; else res1 = tot;
        }
        __syncthreads();
    }
    if (tid == 0) out[b * NB + a] = (res0 + res1) * (1.0f / S);
}

// ---------------- launch ----------------
extern "C" void kernel_launch(void* const* d_in, const int* in_sizes, int n_in,
                              void* d_out, int out_size) {
    const float* fa  = (const float*)d_in[0];
    const float* fb  = (const float*)d_in[1];
    const float* Wq1 = (const float*)d_in[2];
    const float* Wq2 = (const float*)d_in[3];
    const float* Wk1 = (const float*)d_in[4];
    const float* Wk2 = (const float*)d_in[5];
    const float* Wv1 = (const float*)d_in[6];
    const float* Wv2 = (const float*)d_in[7];
    float* out = (float*)d_out;

    void *pX, *pH, *pQ, *pK, *pV, *pWt;
    cudaGetSymbolAddress(&pX, g_X);
    cudaGetSymbolAddress(&pH, g_H);
    cudaGetSymbolAddress(&pQ, g_Q);
    cudaGetSymbolAddress(&pK, g_K);
    cudaGetSymbolAddress(&pV, g_V);
    cudaGetSymbolAddress(&pWt, g_Wt);

    const int smem_pair = (S * QS * 2 + E * VS + 64 * PS + 64 * ALS + 8) * (int)sizeof(uint32_t);
    cudaFuncSetAttribute(pair_tc, cudaFuncAttributeMaxDynamicSharedMemorySize, smem_pair);

    transpose_kernel<<<dim3(24, 128, 2), 256>>>(fa, fb);

    dim3 gBig(C / 128, RTOT / 128);      // (6, 98)
    dim3 g2((E + 63) / 64, RTOT / 128);  // (2, 98)
    int convBlocks = C * C / (256 * 4);  // 576

    convw_kernel<<<convBlocks, 256>>>(Wq1);
    gemm1_relu_tc<<<gBig, 256>>>((const uint32_t*)pX, (const uint32_t*)pWt, (float*)pH);
    gemm_nn<<<g2, 256>>>((const float*)pH, Wq2, (float*)pQ, RTOT, E, C);

    convw_kernel<<<convBlocks, 256>>>(Wk1);
    gemm1_relu_tc<<<gBig, 256>>>((const uint32_t*)pX, (const uint32_t*)pWt, (float*)pH);
    gemm_nn<<<g2, 256>>>((const float*)pH, Wk2, (float*)pK, RTOT, E, C);

    convw_kernel<<<convBlocks, 256>>>(Wv1);
    gemm1_relu_tc<<<gBig, 256>>>((const uint32_t*)pX, (const uint32_t*)pWt, (float*)pH);
    gemm_nn<<<g2, 256>>>((const float*)pH, Wv2, (float*)pV, RTOT, E, C);

    vtrans_kernel<<<2 * NB, 256>>>();

    pair_tc<<<dim3(NB, NB), 256, smem_pair>>>(out);
}

// round 6
// speedup vs baseline: 2.3040x; 1.2231x over previous
#include <cuda_runtime.h>
#include <math.h>
#include <stdint.h>

#define NB 128
#define S  49
#define C  768
#define E  96
#define RTOT (2*NB*S)   // 12544
#define EPSC 1e-8f

#define QS  100   // Q/K smem stride (words)
#define PS  60    // P smem stride
#define VS  60    // Vt smem stride
#define ALS 100   // aligned smem stride
#define VTG 64    // g_Vt padded cols

// ---------------- scratch ----------------
__device__ uint32_t g_X [(size_t)RTOT * C];    // tf32 transposed features
__device__ uint32_t g_Ht[(size_t)RTOT * C];    // tf32 hidden
__device__ uint32_t g_Q [(size_t)RTOT * E];    // tf32 Q
__device__ uint32_t g_K [(size_t)RTOT * E];    // tf32 K
__device__ float    g_V [(size_t)RTOT * E];    // fp32 V (cosine reference)
__device__ uint32_t g_Vt[(size_t)2 * NB * E * VTG]; // tf32 V-transposed per image
__device__ uint32_t g_Wt[(size_t)C * C];       // tf32 W1 staging
__device__ uint32_t g_W2t[(size_t)C * E];      // tf32 W2 staging

// ---------------- helpers ----------------
__device__ __forceinline__ uint32_t f2tf32(float f) {
    uint32_t r; asm("cvt.rna.tf32.f32 %0, %1;" : "=r"(r) : "f"(f)); return r;
}
__device__ __forceinline__ void mma_tf32(float c[4], uint32_t a0, uint32_t a1, uint32_t a2, uint32_t a3,
                                         uint32_t b0, uint32_t b1) {
    asm volatile("mma.sync.aligned.m16n8k8.row.col.f32.tf32.tf32.f32 "
                 "{%0,%1,%2,%3}, {%4,%5,%6,%7}, {%8,%9}, {%0,%1,%2,%3};"
                 : "+f"(c[0]), "+f"(c[1]), "+f"(c[2]), "+f"(c[3])
                 : "r"(a0), "r"(a1), "r"(a2), "r"(a3), "r"(b0), "r"(b1));
}

// ---------------- transpose: [B,C,S] -> X[row][c] (tf32) ----------------
__global__ __launch_bounds__(256) void transpose_kernel(const float* __restrict__ fa,
                                                        const float* __restrict__ fb) {
    __shared__ float t[32][S + 1];
    int ct = blockIdx.x, b = blockIdx.y, set = blockIdx.z;
    const float* F = set ? fb : fa;
    int c0 = ct * 32;
    const float* src = F + ((size_t)b * C + c0) * S;
    for (int idx = threadIdx.x; idx < 32 * S; idx += blockDim.x) {
        int i = idx / S, s = idx % S;
        t[i][s] = src[i * S + s];
    }
    __syncthreads();
    int rowbase = set * NB * S + b * S;
    for (int idx = threadIdx.x; idx < S * 32; idx += blockDim.x) {
        int s = idx >> 5, i = idx & 31;
        g_X[(size_t)(rowbase + s) * C + c0 + i] = f2tf32(t[i][s]);
    }
}

// ---------------- float -> tf32 staging ----------------
__global__ __launch_bounds__(256) void convw_kernel(const float* __restrict__ W,
                                                    uint32_t* __restrict__ dst) {
    int i = (blockIdx.x * 256 + threadIdx.x) * 4;
    float4 v = *(const float4*)&W[i];
    *(uint4*)&dst[i] = make_uint4(f2tf32(v.x), f2tf32(v.y), f2tf32(v.z), f2tf32(v.w));
}

// ---------------- V transpose per image: g_V[img][k][e] -> g_Vt[img][e][64] tf32 ----------------
__global__ __launch_bounds__(256) void vtrans_kernel() {
    __shared__ float sm[E][S + 1];
    int img = blockIdx.x;
    const float* src = g_V + (size_t)img * S * E;
    for (int idx = threadIdx.x; idx < S * E; idx += 256) {
        int k = idx / E, e = idx % E;
        sm[e][k] = src[idx];
    }
    __syncthreads();
    uint32_t* dst = g_Vt + (size_t)img * E * VTG;
    for (int idx = threadIdx.x; idx < E * VTG; idx += 256) {
        int e = idx / VTG, k = idx % VTG;
        dst[idx] = (k < S) ? f2tf32(sm[e][k]) : 0u;
    }
}

// ---------------- GEMM1 (tf32 TC): Ht = tf32(relu(X @ W1)) ----------------
__global__ __launch_bounds__(256) void gemm1_relu_tc(const uint32_t* __restrict__ A,
                                                     const uint32_t* __restrict__ B,
                                                     uint32_t* __restrict__ Hout) {
    __shared__ uint32_t sA[2][128][20];
    __shared__ uint32_t sB[2][16][132];

    int tid = threadIdx.x;
    int w = tid >> 5, lane = tid & 31;
    int g = lane >> 2, tig = lane & 3;
    int warpM = w >> 2, warpN = w & 3;
    int mW = warpM * 64, nW = warpN * 32;
    int m0 = blockIdx.y * 128, n0 = blockIdx.x * 128;

    int arow = tid >> 1, ak8 = (tid & 1) * 8;
    int bkr = tid >> 4, bn8 = (tid & 15) * 8;
    const uint32_t* Aptr = A + (size_t)(m0 + arow) * C + ak8;
    const uint32_t* Bptr = B + (size_t)bkr * C + n0 + bn8;

    float acc[4][4][4];
#pragma unroll
    for (int i = 0; i < 4; i++)
#pragma unroll
        for (int j = 0; j < 4; j++)
#pragma unroll
            for (int k = 0; k < 4; k++) acc[i][j][k] = 0.f;

    uint4 ra0, ra1, rb0, rb1;
    ra0 = *(const uint4*)Aptr;       ra1 = *(const uint4*)(Aptr + 4);
    rb0 = *(const uint4*)Bptr;       rb1 = *(const uint4*)(Bptr + 4);
    *(uint4*)&sA[0][arow][ak8]     = ra0;
    *(uint4*)&sA[0][arow][ak8 + 4] = ra1;
    *(uint4*)&sB[0][bkr][bn8]      = rb0;
    *(uint4*)&sB[0][bkr][bn8 + 4]  = rb1;
    __syncthreads();

    const int NT = C / 16;  // 48
    for (int t = 0; t < NT; t++) {
        int buf = t & 1;
        if (t < NT - 1) {
            const uint32_t* Ap = Aptr + (t + 1) * 16;
            const uint32_t* Bp = Bptr + (size_t)(t + 1) * 16 * C;
            ra0 = *(const uint4*)Ap; ra1 = *(const uint4*)(Ap + 4);
            rb0 = *(const uint4*)Bp; rb1 = *(const uint4*)(Bp + 4);
        }
#pragma unroll
        for (int ks = 0; ks < 16; ks += 8) {
            uint32_t afr[4][4];
#pragma unroll
            for (int mt = 0; mt < 4; mt++) {
                int r = mW + mt * 16 + g;
                afr[mt][0] = sA[buf][r    ][ks + tig];
                afr[mt][1] = sA[buf][r + 8][ks + tig];
                afr[mt][2] = sA[buf][r    ][ks + tig + 4];
                afr[mt][3] = sA[buf][r + 8][ks + tig + 4];
            }
            uint32_t bfr[4][2];
#pragma unroll
            for (int nt = 0; nt < 4; nt++) {
                int ncol = nW + nt * 8 + g;
                bfr[nt][0] = sB[buf][ks + tig    ][ncol];
                bfr[nt][1] = sB[buf][ks + tig + 4][ncol];
            }
#pragma unroll
            for (int mt = 0; mt < 4; mt++)
#pragma unroll
                for (int nt = 0; nt < 4; nt++)
                    mma_tf32(acc[mt][nt], afr[mt][0], afr[mt][1], afr[mt][2], afr[mt][3],
                             bfr[nt][0], bfr[nt][1]);
        }
        if (t < NT - 1) {
            int nb = buf ^ 1;
            *(uint4*)&sA[nb][arow][ak8]     = ra0;
            *(uint4*)&sA[nb][arow][ak8 + 4] = ra1;
            *(uint4*)&sB[nb][bkr][bn8]      = rb0;
            *(uint4*)&sB[nb][bkr][bn8 + 4]  = rb1;
            __syncthreads();
        }
    }

#pragma unroll
    for (int mt = 0; mt < 4; mt++) {
        int r = m0 + mW + mt * 16 + g;
#pragma unroll
        for (int nt = 0; nt < 4; nt++) {
            int cc = n0 + nW + nt * 8 + tig * 2;
            uint2 lo, hi;
            lo.x = f2tf32(fmaxf(acc[mt][nt][0], 0.f)); lo.y = f2tf32(fmaxf(acc[mt][nt][1], 0.f));
            hi.x = f2tf32(fmaxf(acc[mt][nt][2], 0.f)); hi.y = f2tf32(fmaxf(acc[mt][nt][3], 0.f));
            *(uint2*)&Hout[(size_t)r * C + cc]       = lo;
            *(uint2*)&Hout[(size_t)(r + 8) * C + cc] = hi;
        }
    }
}

// ---------------- GEMM2 (tf32 TC): out = Ht @ W2, BM=64, BN=96 ----------------
template <bool TF32OUT>
__global__ __launch_bounds__(256) void gemm2_tc(const uint32_t* __restrict__ A,
                                                const uint32_t* __restrict__ B,  // [C][E] tf32
                                                void* __restrict__ outp) {
    __shared__ uint32_t sA[2][64][20];
    __shared__ uint32_t sB[2][16][100];

    int tid = threadIdx.x;
    int w = tid >> 5, lane = tid & 31;
    int g = lane >> 2, tig = lane & 3;
    int warpM = w >> 2, warpN = w & 3;     // 2 x 4
    int mW = warpM * 32, nW = warpN * 24;
    int m0 = blockIdx.y * 64;

    int arow = tid >> 2, ak = (tid & 3) * 4;
    const uint32_t* Aptr = A + (size_t)(m0 + arow) * C + ak;

    float acc[2][3][4];
#pragma unroll
    for (int i = 0; i < 2; i++)
#pragma unroll
        for (int j = 0; j < 3; j++)
#pragma unroll
            for (int k = 0; k < 4; k++) acc[i][j][k] = 0.f;

    uint4 pa, pb0, pb1;
    int bi0 = tid, bi1 = tid + 256;            // of 384 uint4 B elements
    int br0 = bi0 / 24, bc0 = (bi0 % 24) * 4;
    int br1 = bi1 / 24, bc1 = (bi1 % 24) * 4;
    bool hb1 = (bi1 < 384);

    // preload tile 0
    *(uint4*)&sA[0][arow][ak] = *(const uint4*)Aptr;
    *(uint4*)&sB[0][br0][bc0] = *(const uint4*)&B[(size_t)br0 * E + bc0];
    if (hb1) *(uint4*)&sB[0][br1][bc1] = *(const uint4*)&B[(size_t)br1 * E + bc1];
    __syncthreads();

    const int NT = C / 16;  // 48
    for (int t = 0; t < NT; t++) {
        int buf = t & 1;
        if (t < NT - 1) {
            int kt = (t + 1) * 16;
            pa  = *(const uint4*)(Aptr + kt);
            pb0 = *(const uint4*)&B[(size_t)(kt + br0) * E + bc0];
            if (hb1) pb1 = *(const uint4*)&B[(size_t)(kt + br1) * E + bc1];
        }
#pragma unroll
        for (int ks = 0; ks < 16; ks += 8) {
            uint32_t afr[2][4];
#pragma unroll
            for (int mt = 0; mt < 2; mt++) {
                int r = mW + mt * 16 + g;
                afr[mt][0] = sA[buf][r    ][ks + tig];
                afr[mt][1] = sA[buf][r + 8][ks + tig];
                afr[mt][2] = sA[buf][r    ][ks + tig + 4];
                afr[mt][3] = sA[buf][r + 8][ks + tig + 4];
            }
#pragma unroll
            for (int nt = 0; nt < 3; nt++) {
                int ncol = nW + nt * 8 + g;
                uint32_t b0 = sB[buf][ks + tig    ][ncol];
                uint32_t b1 = sB[buf][ks + tig + 4][ncol];
#pragma unroll
                for (int mt = 0; mt < 2; mt++)
                    mma_tf32(acc[mt][nt], afr[mt][0], afr[mt][1], afr[mt][2], afr[mt][3], b0, b1);
            }
        }
        if (t < NT - 1) {
            int nb = buf ^ 1;
            *(uint4*)&sA[nb][arow][ak] = pa;
            *(uint4*)&sB[nb][br0][bc0] = pb0;
            if (hb1) *(uint4*)&sB[nb][br1][bc1] = pb1;
            __syncthreads();
        }
    }

#pragma unroll
    for (int mt = 0; mt < 2; mt++) {
        int r = m0 + mW + mt * 16 + g;
#pragma unroll
        for (int nt = 0; nt < 3; nt++) {
            int cc = nW + nt * 8 + tig * 2;
            if (TF32OUT) {
                uint32_t* o = (uint32_t*)outp;
                uint2 lo, hi;
                lo.x = f2tf32(acc[mt][nt][0]); lo.y = f2tf32(acc[mt][nt][1]);
                hi.x = f2tf32(acc[mt][nt][2]); hi.y = f2tf32(acc[mt][nt][3]);
                *(uint2*)&o[(size_t)r * E + cc]       = lo;
                *(uint2*)&o[(size_t)(r + 8) * E + cc] = hi;
            } else {
                float* o = (float*)outp;
                float2 lo, hi;
                lo.x = acc[mt][nt][0]; lo.y = acc[mt][nt][1];
                hi.x = acc[mt][nt][2]; hi.y = acc[mt][nt][3];
                *(float2*)&o[(size_t)r * E + cc]       = lo;
                *(float2*)&o[(size_t)(r + 8) * E + cc] = hi;
            }
        }
    }
}

// ---------------- pair kernel: tensor-core attention + cosine ----------------
__global__ __launch_bounds__(256, 2) void pair_tc(float* __restrict__ out) {
    extern __shared__ uint32_t smbuf[];
    uint32_t* uQ  = smbuf;                   // 49*100 (A-frag pad rows spill into uK: benign)
    uint32_t* uK  = uQ + S * QS;             // 49*100
    uint32_t* uVt = uK + S * QS;             // 96*60
    uint32_t* uP  = uVt + E * VS;            // 64*60
    float*    fAl = (float*)(uP + 64 * PS);  // 64*100
    float*    wsum = fAl + 64 * ALS;         // 8

    int a = blockIdx.x, b = blockIdx.y;
    int tid = threadIdx.x, w = tid >> 5, lane = tid & 31;
    int g = lane >> 2, tig = lane & 3;
    const float scale = 0.10206207261596577f;  // 1/sqrt(96)

    int mt = w >> 1, half = w & 1;
    int raQ = mt * 16 + g;

    float res0 = 0.f, res1 = 0.f;

#pragma unroll 1
    for (int dir = 0; dir < 2; dir++) {
        int qi = dir ? a : (NB + b);   // Q image
        int ki = dir ? (NB + b) : a;   // K/V image

        // ---- loads (raw tf32 copies, no cvt) ----
        {
            const uint32_t* q = g_Q + (size_t)qi * S * E;
            const uint32_t* k = g_K + (size_t)ki * S * E;
            for (int idx = tid; idx < S * (E / 4); idx += 256) {
                int r = idx / (E / 4), c4 = (idx % (E / 4)) * 4;
                *(uint4*)&uQ[r * QS + c4] = *(const uint4*)&q[r * E + c4];
                *(uint4*)&uK[r * QS + c4] = *(const uint4*)&k[r * E + c4];
            }
            const uint32_t* vt = g_Vt + (size_t)ki * E * VTG;
            for (int idx = tid; idx < E * (VS / 4); idx += 256) {
                int r = idx / (VS / 4), c4 = (idx % (VS / 4)) * 4;
                *(uint4*)&uVt[r * VS + c4] = *(const uint4*)&vt[r * VTG + c4];
            }
        }
        __syncthreads();

        // ---- scores: warp (mt, half): A-frags loaded once per ks, swept over nt ----
        {
            float sc[4][4];
#pragma unroll
            for (int i = 0; i < 4; i++)
#pragma unroll
                for (int j = 0; j < 4; j++) sc[i][j] = 0.f;
            int ntBeg = half * 4;
            int ntCnt = half ? 3 : 4;
#pragma unroll
            for (int ks = 0; ks < E; ks += 8) {
                uint32_t a0 = uQ[raQ * QS + ks + tig];
                uint32_t a1 = uQ[(raQ + 8) * QS + ks + tig];
                uint32_t a2 = uQ[raQ * QS + ks + tig + 4];
                uint32_t a3 = uQ[(raQ + 8) * QS + ks + tig + 4];
#pragma unroll
                for (int n2 = 0; n2 < 4; n2++) {
                    if (n2 < ntCnt) {
                        int nc = (ntBeg + n2) * 8 + g;
                        uint32_t b0 = uK[nc * QS + ks + tig];
                        uint32_t b1 = uK[nc * QS + ks + tig + 4];
                        mma_tf32(sc[n2], a0, a1, a2, a3, b0, b1);
                    }
                }
            }
            float* Pf = (float*)uP;
#pragma unroll
            for (int n2 = 0; n2 < 4; n2++) {
                if (n2 < ntCnt) {
                    int cc = (ntBeg + n2) * 8 + tig * 2;
                    Pf[raQ * PS + cc]           = sc[n2][0];
                    Pf[raQ * PS + cc + 1]       = sc[n2][1];
                    Pf[(raQ + 8) * PS + cc]     = sc[n2][2];
                    Pf[(raQ + 8) * PS + cc + 1] = sc[n2][3];
                }
            }
        }
        __syncthreads();

        // ---- softmax rows (P back as tf32; zero pad cols 49..55) ----
        {
            float* Pf = (float*)uP;
            for (int r = w; r < S; r += 8) {
                float s0 = Pf[r * PS + lane] * scale;
                int l1 = lane + 32;
                bool v1 = (l1 < S);
                float s1 = v1 ? Pf[r * PS + l1] * scale : -1e30f;
                float mx = fmaxf(s0, s1);
#pragma unroll
                for (int o = 16; o; o >>= 1) mx = fmaxf(mx, __shfl_xor_sync(0xffffffffu, mx, o));
                float p0 = __expf(s0 - mx);
                float p1 = v1 ? __expf(s1 - mx) : 0.f;
                float su = p0 + p1;
#pragma unroll
                for (int o = 16; o; o >>= 1) su += __shfl_xor_sync(0xffffffffu, su, o);
                float inv = __fdividef(1.f, su);
                uP[r * PS + lane] = f2tf32(p0 * inv);
                if (v1) uP[r * PS + l1] = f2tf32(p1 * inv);
                else if (l1 < 56) uP[r * PS + l1] = 0u;
            }
        }
        __syncthreads();

        // ---- PV: warp (mt, half): A(P)-frags loaded once per ks, swept over 6 et ----
        {
            float alc[6][4];
#pragma unroll
            for (int i = 0; i < 6; i++)
#pragma unroll
                for (int j = 0; j < 4; j++) alc[i][j] = 0.f;
            int etBeg = half * 6;
#pragma unroll
            for (int ks = 0; ks < 56; ks += 8) {
                uint32_t a0 = uP[raQ * PS + ks + tig];
                uint32_t a1 = uP[(raQ + 8) * PS + ks + tig];
                uint32_t a2 = uP[raQ * PS + ks + tig + 4];
                uint32_t a3 = uP[(raQ + 8) * PS + ks + tig + 4];
#pragma unroll
                for (int e = 0; e < 6; e++) {
                    int nc = (etBeg + e) * 8 + g;
                    uint32_t b0 = uVt[nc * VS + ks + tig];
                    uint32_t b1 = uVt[nc * VS + ks + tig + 4];
                    mma_tf32(alc[e], a0, a1, a2, a3, b0, b1);
                }
            }
            __syncthreads();
#pragma unroll
            for (int e = 0; e < 6; e++) {
                int cc = (etBeg + e) * 8 + tig * 2;
                fAl[raQ * ALS + cc]           = alc[e][0];
                fAl[raQ * ALS + cc + 1]       = alc[e][1];
                fAl[(raQ + 8) * ALS + cc]     = alc[e][2];
                fAl[(raQ + 8) * ALS + cc + 1] = alc[e][3];
            }
        }
        __syncthreads();

        // ---- cosine(aligned, Vref) ----
        {
            const float* vref = g_V + (size_t)qi * S * E;
            float csum = 0.f;
            bool act = (lane < E / 4);
            int cc = act ? lane : 0;
            for (int r = w; r < S; r += 8) {
                float4 al = *(const float4*)&fAl[r * ALS + cc * 4];
                float4 vc = *(const float4*)&vref[r * E + cc * 4];
                float num = al.x * vc.x + al.y * vc.y + al.z * vc.z + al.w * vc.w;
                float da  = al.x * al.x + al.y * al.y + al.z * al.z + al.w * al.w;
                float dc  = vc.x * vc.x + vc.y * vc.y + vc.z * vc.z + vc.w * vc.w;
                if (!act) { num = 0.f; da = 0.f; dc = 0.f; }
#pragma unroll
                for (int o = 16; o; o >>= 1) {
                    num += __shfl_xor_sync(0xffffffffu, num, o);
                    da  += __shfl_xor_sync(0xffffffffu, da, o);
                    dc  += __shfl_xor_sync(0xffffffffu, dc, o);
                }
                if (lane == 0) {
                    float na = fmaxf(sqrtf(da), EPSC);
                    float nc = fmaxf(sqrtf(dc), EPSC);
                    csum += num / (na * nc);
                }
            }
            if (lane == 0) wsum[w] = csum;
        }
        __syncthreads();
        if (tid == 0) {
            float tot = 0.f;
#pragma unroll
            for (int i = 0; i < 8; i++) tot += wsum[i];
            if (dir == 0) res0 = tot; else res1 = tot;
        }
        __syncthreads();
    }
    if (tid == 0) out[b * NB + a] = (res0 + res1) * (1.0f / S);
}

// ---------------- launch ----------------
extern "C" void kernel_launch(void* const* d_in, const int* in_sizes, int n_in,
                              void* d_out, int out_size) {
    const float* fa  = (const float*)d_in[0];
    const float* fb  = (const float*)d_in[1];
    const float* Wq1 = (const float*)d_in[2];
    const float* Wq2 = (const float*)d_in[3];
    const float* Wk1 = (const float*)d_in[4];
    const float* Wk2 = (const float*)d_in[5];
    const float* Wv1 = (const float*)d_in[6];
    const float* Wv2 = (const float*)d_in[7];
    float* out = (float*)d_out;

    void *pX, *pHt, *pQ, *pK, *pV, *pWt, *pW2t;
    cudaGetSymbolAddress(&pX, g_X);
    cudaGetSymbolAddress(&pHt, g_Ht);
    cudaGetSymbolAddress(&pQ, g_Q);
    cudaGetSymbolAddress(&pK, g_K);
    cudaGetSymbolAddress(&pV, g_V);
    cudaGetSymbolAddress(&pWt, g_Wt);
    cudaGetSymbolAddress(&pW2t, g_W2t);

    const int smem_pair = (S * QS * 2 + E * VS + 64 * PS + 64 * ALS + 8) * (int)sizeof(uint32_t);
    cudaFuncSetAttribute(pair_tc, cudaFuncAttributeMaxDynamicSharedMemorySize, smem_pair);

    transpose_kernel<<<dim3(24, 128, 2), 256>>>(fa, fb);

    dim3 gBig(C / 128, RTOT / 128);      // (6, 98)
    dim3 g2(1, RTOT / 64);               // (1, 196)
    int convW1 = C * C / (256 * 4);      // 576
    int convW2 = C * E / (256 * 4);      // 72

    convw_kernel<<<convW1, 256>>>(Wq1, (uint32_t*)pWt);
    convw_kernel<<<convW2, 256>>>(Wq2, (uint32_t*)pW2t);
    gemm1_relu_tc<<<gBig, 256>>>((const uint32_t*)pX, (const uint32_t*)pWt, (uint32_t*)pHt);
    gemm2_tc<true><<<g2, 256>>>((const uint32_t*)pHt, (const uint32_t*)pW2t, pQ);

    convw_kernel<<<convW1, 256>>>(Wk1, (uint32_t*)pWt);
    convw_kernel<<<convW2, 256>>>(Wk2, (uint32_t*)pW2t);
    gemm1_relu_tc<<<gBig, 256>>>((const uint32_t*)pX, (const uint32_t*)pWt, (uint32_t*)pHt);
    gemm2_tc<true><<<g2, 256>>>((const uint32_t*)pHt, (const uint32_t*)pW2t, pK);

    convw_kernel<<<convW1, 256>>>(Wv1, (uint32_t*)pWt);
    convw_kernel<<<convW2, 256>>>(Wv2, (uint32_t*)pW2t);
    gemm1_relu_tc<<<gBig, 256>>>((const uint32_t*)pX, (const uint32_t*)pWt, (uint32_t*)pHt);
    gemm2_tc<false><<<g2, 256>>>((const uint32_t*)pHt, (const uint32_t*)pW2t, pV);

    vtrans_kernel<<<2 * NB, 256>>>();

    pair_tc<<<dim3(NB, NB), 256, smem_pair>>>(out);
}

// round 7
// speedup vs baseline: 2.7254x; 1.1829x over previous
#include <cuda_runtime.h>
#include <math.h>
#include <stdint.h>

#define NB 128
#define S  49
#define C  768
#define E  96
#define RTOT (2*NB*S)   // 12544
#define EPSC 1e-8f

#define QS  100   // Q/K smem stride (words)
#define PS  60    // P smem stride
#define VS  60    // Vt smem stride
#define VTG 64    // g_Vt padded cols

// ---------------- scratch ----------------
__device__ uint32_t g_X  [(size_t)RTOT * C];        // tf32 transposed features
__device__ uint32_t g_Ht [(size_t)3 * RTOT * C];    // tf32 hidden (3 projections)
__device__ uint32_t g_Q  [(size_t)RTOT * E];        // tf32 Q
__device__ uint32_t g_K  [(size_t)RTOT * E];        // tf32 K
__device__ float    g_V  [(size_t)RTOT * E];        // fp32 V (cosine reference)
__device__ uint32_t g_Vt [(size_t)2 * NB * E * VTG];// tf32 V-transposed per image
__device__ uint32_t g_Wt [(size_t)3 * C * C];       // tf32 W1 staging (q,k,v)
__device__ uint32_t g_W2t[(size_t)3 * C * E];       // tf32 W2 staging (q,k,v)

// ---------------- helpers ----------------
__device__ __forceinline__ uint32_t f2tf32(float f) {
    uint32_t r; asm("cvt.rna.tf32.f32 %0, %1;" : "=r"(r) : "f"(f)); return r;
}
__device__ __forceinline__ void mma_tf32(float c[4], uint32_t a0, uint32_t a1, uint32_t a2, uint32_t a3,
                                         uint32_t b0, uint32_t b1) {
    asm volatile("mma.sync.aligned.m16n8k8.row.col.f32.tf32.tf32.f32 "
                 "{%0,%1,%2,%3}, {%4,%5,%6,%7}, {%8,%9}, {%0,%1,%2,%3};"
                 : "+f"(c[0]), "+f"(c[1]), "+f"(c[2]), "+f"(c[3])
                 : "r"(a0), "r"(a1), "r"(a2), "r"(a3), "r"(b0), "r"(b1));
}

// ---------------- transpose: [B,C,S] -> X[row][c] (tf32) ----------------
__global__ __launch_bounds__(256) void transpose_kernel(const float* __restrict__ fa,
                                                        const float* __restrict__ fb) {
    __shared__ float t[32][S + 1];
    int ct = blockIdx.x, b = blockIdx.y, set = blockIdx.z;
    const float* F = set ? fb : fa;
    int c0 = ct * 32;
    const float* src = F + ((size_t)b * C + c0) * S;
    for (int idx = threadIdx.x; idx < 32 * S; idx += blockDim.x) {
        int i = idx / S, s = idx % S;
        t[i][s] = src[i * S + s];
    }
    __syncthreads();
    int rowbase = set * NB * S + b * S;
    for (int idx = threadIdx.x; idx < S * 32; idx += blockDim.x) {
        int s = idx >> 5, i = idx & 31;
        g_X[(size_t)(rowbase + s) * C + c0 + i] = f2tf32(t[i][s]);
    }
}

// ---------------- all 6 weights -> tf32 staging (one launch) ----------------
__global__ __launch_bounds__(256) void convw_all(const float* __restrict__ w0, const float* __restrict__ w1,
                                                 const float* __restrict__ w2, const float* __restrict__ w3,
                                                 const float* __restrict__ w4, const float* __restrict__ w5) {
    int y = blockIdx.y;
    const float* src;
    uint32_t* dst;
    int nblk;
    if (y < 3) {
        src = (y == 0) ? w0 : (y == 1) ? w1 : w2;
        dst = g_Wt + (size_t)y * C * C;
        nblk = C * C / 1024;            // 576
    } else {
        src = (y == 3) ? w3 : (y == 4) ? w4 : w5;
        dst = g_W2t + (size_t)(y - 3) * C * E;
        nblk = C * E / 1024;            // 72
    }
    if (blockIdx.x >= nblk) return;
    int i = (blockIdx.x * 256 + threadIdx.x) * 4;
    float4 v = *(const float4*)&src[i];
    *(uint4*)&dst[i] = make_uint4(f2tf32(v.x), f2tf32(v.y), f2tf32(v.z), f2tf32(v.w));
}

// ---------------- V transpose per image ----------------
__global__ __launch_bounds__(256) void vtrans_kernel() {
    __shared__ float sm[E][S + 1];
    int img = blockIdx.x;
    const float* src = g_V + (size_t)img * S * E;
    for (int idx = threadIdx.x; idx < S * E; idx += 256) {
        int k = idx / E, e = idx % E;
        sm[e][k] = src[idx];
    }
    __syncthreads();
    uint32_t* dst = g_Vt + (size_t)img * E * VTG;
    for (int idx = threadIdx.x; idx < E * VTG; idx += 256) {
        int e = idx / VTG, k = idx % VTG;
        dst[idx] = (k < S) ? f2tf32(sm[e][k]) : 0u;
    }
}

// ---------------- GEMM1 (tf32 TC, z=projection): Ht_z = tf32(relu(X @ W1_z)) ----------------
__global__ __launch_bounds__(256) void gemm1_relu_tc(const uint32_t* __restrict__ A) {
    const uint32_t* B = g_Wt + (size_t)blockIdx.z * C * C;
    uint32_t* Hout = g_Ht + (size_t)blockIdx.z * RTOT * C;

    __shared__ uint32_t sA[2][128][20];
    __shared__ uint32_t sB[2][16][132];

    int tid = threadIdx.x;
    int w = tid >> 5, lane = tid & 31;
    int g = lane >> 2, tig = lane & 3;
    int warpM = w >> 2, warpN = w & 3;
    int mW = warpM * 64, nW = warpN * 32;
    int m0 = blockIdx.y * 128, n0 = blockIdx.x * 128;

    int arow = tid >> 1, ak8 = (tid & 1) * 8;
    int bkr = tid >> 4, bn8 = (tid & 15) * 8;
    const uint32_t* Aptr = A + (size_t)(m0 + arow) * C + ak8;
    const uint32_t* Bptr = B + (size_t)bkr * C + n0 + bn8;

    float acc[4][4][4];
#pragma unroll
    for (int i = 0; i < 4; i++)
#pragma unroll
        for (int j = 0; j < 4; j++)
#pragma unroll
            for (int k = 0; k < 4; k++) acc[i][j][k] = 0.f;

    uint4 ra0, ra1, rb0, rb1;
    ra0 = *(const uint4*)Aptr;       ra1 = *(const uint4*)(Aptr + 4);
    rb0 = *(const uint4*)Bptr;       rb1 = *(const uint4*)(Bptr + 4);
    *(uint4*)&sA[0][arow][ak8]     = ra0;
    *(uint4*)&sA[0][arow][ak8 + 4] = ra1;
    *(uint4*)&sB[0][bkr][bn8]      = rb0;
    *(uint4*)&sB[0][bkr][bn8 + 4]  = rb1;
    __syncthreads();

    const int NT = C / 16;  // 48
    for (int t = 0; t < NT; t++) {
        int buf = t & 1;
        if (t < NT - 1) {
            const uint32_t* Ap = Aptr + (t + 1) * 16;
            const uint32_t* Bp = Bptr + (size_t)(t + 1) * 16 * C;
            ra0 = *(const uint4*)Ap; ra1 = *(const uint4*)(Ap + 4);
            rb0 = *(const uint4*)Bp; rb1 = *(const uint4*)(Bp + 4);
        }
#pragma unroll
        for (int ks = 0; ks < 16; ks += 8) {
            uint32_t afr[4][4];
#pragma unroll
            for (int mt = 0; mt < 4; mt++) {
                int r = mW + mt * 16 + g;
                afr[mt][0] = sA[buf][r    ][ks + tig];
                afr[mt][1] = sA[buf][r + 8][ks + tig];
                afr[mt][2] = sA[buf][r    ][ks + tig + 4];
                afr[mt][3] = sA[buf][r + 8][ks + tig + 4];
            }
            uint32_t bfr[4][2];
#pragma unroll
            for (int nt = 0; nt < 4; nt++) {
                int ncol = nW + nt * 8 + g;
                bfr[nt][0] = sB[buf][ks + tig    ][ncol];
                bfr[nt][1] = sB[buf][ks + tig + 4][ncol];
            }
#pragma unroll
            for (int mt = 0; mt < 4; mt++)
#pragma unroll
                for (int nt = 0; nt < 4; nt++)
                    mma_tf32(acc[mt][nt], afr[mt][0], afr[mt][1], afr[mt][2], afr[mt][3],
                             bfr[nt][0], bfr[nt][1]);
        }
        if (t < NT - 1) {
            int nb = buf ^ 1;
            *(uint4*)&sA[nb][arow][ak8]     = ra0;
            *(uint4*)&sA[nb][arow][ak8 + 4] = ra1;
            *(uint4*)&sB[nb][bkr][bn8]      = rb0;
            *(uint4*)&sB[nb][bkr][bn8 + 4]  = rb1;
            __syncthreads();
        }
    }

#pragma unroll
    for (int mt = 0; mt < 4; mt++) {
        int r = m0 + mW + mt * 16 + g;
#pragma unroll
        for (int nt = 0; nt < 4; nt++) {
            int cc = n0 + nW + nt * 8 + tig * 2;
            uint2 lo, hi;
            lo.x = f2tf32(fmaxf(acc[mt][nt][0], 0.f)); lo.y = f2tf32(fmaxf(acc[mt][nt][1], 0.f));
            hi.x = f2tf32(fmaxf(acc[mt][nt][2], 0.f)); hi.y = f2tf32(fmaxf(acc[mt][nt][3], 0.f));
            *(uint2*)&Hout[(size_t)r * C + cc]       = lo;
            *(uint2*)&Hout[(size_t)(r + 8) * C + cc] = hi;
        }
    }
}

// ---------------- GEMM2 (tf32 TC, z=projection): {Q,K} tf32, V fp32 ----------------
__global__ __launch_bounds__(256) void gemm2_tc() {
    int z = blockIdx.z;
    const uint32_t* A = g_Ht + (size_t)z * RTOT * C;
    const uint32_t* B = g_W2t + (size_t)z * C * E;

    __shared__ uint32_t sA[2][64][20];
    __shared__ uint32_t sB[2][16][100];

    int tid = threadIdx.x;
    int w = tid >> 5, lane = tid & 31;
    int g = lane >> 2, tig = lane & 3;
    int warpM = w >> 2, warpN = w & 3;     // 2 x 4
    int mW = warpM * 32, nW = warpN * 24;
    int m0 = blockIdx.y * 64;

    int arow = tid >> 2, ak = (tid & 3) * 4;
    const uint32_t* Aptr = A + (size_t)(m0 + arow) * C + ak;

    float acc[2][3][4];
#pragma unroll
    for (int i = 0; i < 2; i++)
#pragma unroll
        for (int j = 0; j < 3; j++)
#pragma unroll
            for (int k = 0; k < 4; k++) acc[i][j][k] = 0.f;

    uint4 pa, pb0, pb1;
    int bi0 = tid, bi1 = tid + 256;
    int br0 = bi0 / 24, bc0 = (bi0 % 24) * 4;
    int br1 = bi1 / 24, bc1 = (bi1 % 24) * 4;
    bool hb1 = (bi1 < 384);

    *(uint4*)&sA[0][arow][ak] = *(const uint4*)Aptr;
    *(uint4*)&sB[0][br0][bc0] = *(const uint4*)&B[(size_t)br0 * E + bc0];
    if (hb1) *(uint4*)&sB[0][br1][bc1] = *(const uint4*)&B[(size_t)br1 * E + bc1];
    __syncthreads();

    const int NT = C / 16;  // 48
    for (int t = 0; t < NT; t++) {
        int buf = t & 1;
        if (t < NT - 1) {
            int kt = (t + 1) * 16;
            pa  = *(const uint4*)(Aptr + kt);
            pb0 = *(const uint4*)&B[(size_t)(kt + br0) * E + bc0];
            if (hb1) pb1 = *(const uint4*)&B[(size_t)(kt + br1) * E + bc1];
        }
#pragma unroll
        for (int ks = 0; ks < 16; ks += 8) {
            uint32_t afr[2][4];
#pragma unroll
            for (int mt = 0; mt < 2; mt++) {
                int r = mW + mt * 16 + g;
                afr[mt][0] = sA[buf][r    ][ks + tig];
                afr[mt][1] = sA[buf][r + 8][ks + tig];
                afr[mt][2] = sA[buf][r    ][ks + tig + 4];
                afr[mt][3] = sA[buf][r + 8][ks + tig + 4];
            }
#pragma unroll
            for (int nt = 0; nt < 3; nt++) {
                int ncol = nW + nt * 8 + g;
                uint32_t b0 = sB[buf][ks + tig    ][ncol];
                uint32_t b1 = sB[buf][ks + tig + 4][ncol];
#pragma unroll
                for (int mt = 0; mt < 2; mt++)
                    mma_tf32(acc[mt][nt], afr[mt][0], afr[mt][1], afr[mt][2], afr[mt][3], b0, b1);
            }
        }
        if (t < NT - 1) {
            int nb = buf ^ 1;
            *(uint4*)&sA[nb][arow][ak] = pa;
            *(uint4*)&sB[nb][br0][bc0] = pb0;
            if (hb1) *(uint4*)&sB[nb][br1][bc1] = pb1;
            __syncthreads();
        }
    }

#pragma unroll
    for (int mt = 0; mt < 2; mt++) {
        int r = m0 + mW + mt * 16 + g;
#pragma unroll
        for (int nt = 0; nt < 3; nt++) {
            int cc = nW + nt * 8 + tig * 2;
            if (z < 2) {
                uint32_t* o = (z == 0) ? g_Q : g_K;
                uint2 lo, hi;
                lo.x = f2tf32(acc[mt][nt][0]); lo.y = f2tf32(acc[mt][nt][1]);
                hi.x = f2tf32(acc[mt][nt][2]); hi.y = f2tf32(acc[mt][nt][3]);
                *(uint2*)&o[(size_t)r * E + cc]       = lo;
                *(uint2*)&o[(size_t)(r + 8) * E + cc] = hi;
            } else {
                float2 lo, hi;
                lo.x = acc[mt][nt][0]; lo.y = acc[mt][nt][1];
                hi.x = acc[mt][nt][2]; hi.y = acc[mt][nt][3];
                *(float2*)&g_V[(size_t)r * E + cc]       = lo;
                *(float2*)&g_V[(size_t)(r + 8) * E + cc] = hi;
            }
        }
    }
}

// ---------------- pair kernel: TC attention, register-resident cosine ----------------
__global__ __launch_bounds__(256, 2) void pair_tc(float* __restrict__ out) {
    extern __shared__ uint32_t smbuf[];
    uint32_t* uQ   = smbuf;                   // 49*100 (pad-row frag reads spill into uK: benign)
    uint32_t* uK   = uQ + S * QS;             // 49*100 (pad-row reads spill into uVt: benign)
    uint32_t* uVt  = uK + S * QS;             // 96*60
    uint32_t* uP   = uVt + E * VS;            // 64*60
    float*    wsum = (float*)(uP + 64 * PS);  // 8
    float*    part = (float*)uQ;              // [49][8] overlays uQ (dead after scores)

    int a = blockIdx.x, b = blockIdx.y;
    int tid = threadIdx.x, w = tid >> 5, lane = tid & 31;
    int g = lane >> 2, tig = lane & 3;
    const float scale = 0.10206207261596577f;  // 1/sqrt(96)

    int mt = w >> 1, half = w & 1;
    int raQ = mt * 16 + g;

    float res0 = 0.f, res1 = 0.f;

#pragma unroll 1
    for (int dir = 0; dir < 2; dir++) {
        int qi = dir ? a : (NB + b);   // Q image
        int ki = dir ? (NB + b) : a;   // K/V image

        // ---- loads ----
        {
            const uint32_t* q = g_Q + (size_t)qi * S * E;
            const uint32_t* k = g_K + (size_t)ki * S * E;
            for (int idx = tid; idx < S * (E / 4); idx += 256) {
                int r = idx / (E / 4), c4 = (idx % (E / 4)) * 4;
                *(uint4*)&uQ[r * QS + c4] = *(const uint4*)&q[r * E + c4];
                *(uint4*)&uK[r * QS + c4] = *(const uint4*)&k[r * E + c4];
            }
            const uint32_t* vt = g_Vt + (size_t)ki * E * VTG;
            for (int idx = tid; idx < E * (VS / 4); idx += 256) {
                int r = idx / (VS / 4), c4 = (idx % (VS / 4)) * 4;
                *(uint4*)&uVt[r * VS + c4] = *(const uint4*)&vt[r * VTG + c4];
            }
        }
        __syncthreads();

        // ---- scores ----
        {
            float sc[4][4];
#pragma unroll
            for (int i = 0; i < 4; i++)
#pragma unroll
                for (int j = 0; j < 4; j++) sc[i][j] = 0.f;
            int ntBeg = half * 4;
            int ntCnt = half ? 3 : 4;
#pragma unroll
            for (int ks = 0; ks < E; ks += 8) {
                uint32_t a0 = uQ[raQ * QS + ks + tig];
                uint32_t a1 = uQ[(raQ + 8) * QS + ks + tig];
                uint32_t a2 = uQ[raQ * QS + ks + tig + 4];
                uint32_t a3 = uQ[(raQ + 8) * QS + ks + tig + 4];
#pragma unroll
                for (int n2 = 0; n2 < 4; n2++) {
                    if (n2 < ntCnt) {
                        int nc = (ntBeg + n2) * 8 + g;
                        uint32_t b0 = uK[nc * QS + ks + tig];
                        uint32_t b1 = uK[nc * QS + ks + tig + 4];
                        mma_tf32(sc[n2], a0, a1, a2, a3, b0, b1);
                    }
                }
            }
            float* Pf = (float*)uP;
#pragma unroll
            for (int n2 = 0; n2 < 4; n2++) {
                if (n2 < ntCnt) {
                    int cc = (ntBeg + n2) * 8 + tig * 2;
                    Pf[raQ * PS + cc]           = sc[n2][0];
                    Pf[raQ * PS + cc + 1]       = sc[n2][1];
                    Pf[(raQ + 8) * PS + cc]     = sc[n2][2];
                    Pf[(raQ + 8) * PS + cc + 1] = sc[n2][3];
                }
            }
        }
        __syncthreads();

        // ---- softmax rows (P back as tf32; zero pad cols 49..55) ----
        {
            float* Pf = (float*)uP;
            for (int r = w; r < S; r += 8) {
                float s0 = Pf[r * PS + lane] * scale;
                int l1 = lane + 32;
                bool v1 = (l1 < S);
                float s1 = v1 ? Pf[r * PS + l1] * scale : -1e30f;
                float mx = fmaxf(s0, s1);
#pragma unroll
                for (int o = 16; o; o >>= 1) mx = fmaxf(mx, __shfl_xor_sync(0xffffffffu, mx, o));
                float p0 = __expf(s0 - mx);
                float p1 = v1 ? __expf(s1 - mx) : 0.f;
                float su = p0 + p1;
#pragma unroll
                for (int o = 16; o; o >>= 1) su += __shfl_xor_sync(0xffffffffu, su, o);
                float inv = __fdividef(1.f, su);
                uP[r * PS + lane] = f2tf32(p0 * inv);
                if (v1) uP[r * PS + l1] = f2tf32(p1 * inv);
                else if (l1 < 56) uP[r * PS + l1] = 0u;
            }
        }
        __syncthreads();

        // ---- PV (registers) + cosine partials straight from accumulators ----
        {
            float alc[6][4];
#pragma unroll
            for (int i = 0; i < 6; i++)
#pragma unroll
                for (int j = 0; j < 4; j++) alc[i][j] = 0.f;
            int etBeg = half * 6;
#pragma unroll
            for (int ks = 0; ks < 56; ks += 8) {
                uint32_t a0 = uP[raQ * PS + ks + tig];
                uint32_t a1 = uP[(raQ + 8) * PS + ks + tig];
                uint32_t a2 = uP[raQ * PS + ks + tig + 4];
                uint32_t a3 = uP[(raQ + 8) * PS + ks + tig + 4];
#pragma unroll
                for (int e = 0; e < 6; e++) {
                    int nc = (etBeg + e) * 8 + g;
                    uint32_t b0 = uVt[nc * VS + ks + tig];
                    uint32_t b1 = uVt[nc * VS + ks + tig + 4];
                    mma_tf32(alc[e], a0, a1, a2, a3, b0, b1);
                }
            }

            const float* vref = g_V + (size_t)qi * S * E;
            int r0 = raQ, r1 = raQ + 8;
            bool ok0 = (r0 < S), ok1 = (r1 < S);
            float n0 = 0.f, d0 = 0.f, c0 = 0.f;
            float n1 = 0.f, d1 = 0.f, c1 = 0.f;
#pragma unroll
            for (int e = 0; e < 6; e++) {
                int col = (etBeg + e) * 8 + tig * 2;
                if (ok0) {
                    float2 vc = *(const float2*)&vref[r0 * E + col];
                    n0 += alc[e][0] * vc.x + alc[e][1] * vc.y;
                    d0 += alc[e][0] * alc[e][0] + alc[e][1] * alc[e][1];
                    c0 += vc.x * vc.x + vc.y * vc.y;
                }
                if (ok1) {
                    float2 vc = *(const float2*)&vref[r1 * E + col];
                    n1 += alc[e][2] * vc.x + alc[e][3] * vc.y;
                    d1 += alc[e][2] * alc[e][2] + alc[e][3] * alc[e][3];
                    c1 += vc.x * vc.x + vc.y * vc.y;
                }
            }
            // quad reduce over tig
#pragma unroll
            for (int o = 1; o <= 2; o <<= 1) {
                n0 += __shfl_xor_sync(0xffffffffu, n0, o);
                d0 += __shfl_xor_sync(0xffffffffu, d0, o);
                c0 += __shfl_xor_sync(0xffffffffu, c0, o);
                n1 += __shfl_xor_sync(0xffffffffu, n1, o);
                d1 += __shfl_xor_sync(0xffffffffu, d1, o);
                c1 += __shfl_xor_sync(0xffffffffu, c1, o);
            }
            if (tig == 0) {
                if (ok0) {
                    part[r0 * 8 + half * 3 + 0] = n0;
                    part[r0 * 8 + half * 3 + 1] = d0;
                    part[r0 * 8 + half * 3 + 2] = c0;
                }
                if (ok1) {
                    part[r1 * 8 + half * 3 + 0] = n1;
                    part[r1 * 8 + half * 3 + 1] = d1;
                    part[r1 * 8 + half * 3 + 2] = c1;
                }
            }
        }
        __syncthreads();

        // ---- per-row cosine + block reduction ----
        {
            float cosv = 0.f;
            if (tid < S) {
                const float* p = &part[tid * 8];
                float num = p[0] + p[3];
                float da  = p[1] + p[4];
                float dc  = p[2] + p[5];
                float na = fmaxf(sqrtf(da), EPSC);
                float nc = fmaxf(sqrtf(dc), EPSC);
                cosv = num / (na * nc);
            }
#pragma unroll
            for (int o = 16; o; o >>= 1) cosv += __shfl_xor_sync(0xffffffffu, cosv, o);
            if (lane == 0) wsum[w] = cosv;
        }
        __syncthreads();
        if (tid == 0) {
            float tot = wsum[0] + wsum[1];   // only warps 0,1 hold tid<49
            if (dir == 0) res0 = tot; else res1 = tot;
        }
        __syncthreads();
    }
    if (tid == 0) out[b * NB + a] = (res0 + res1) * (1.0f / S);
}

// ---------------- launch ----------------
extern "C" void kernel_launch(void* const* d_in, const int* in_sizes, int n_in,
                              void* d_out, int out_size) {
    const float* fa  = (const float*)d_in[0];
    const float* fb  = (const float*)d_in[1];
    const float* Wq1 = (const float*)d_in[2];
    const float* Wq2 = (const float*)d_in[3];
    const float* Wk1 = (const float*)d_in[4];
    const float* Wk2 = (const float*)d_in[5];
    const float* Wv1 = (const float*)d_in[6];
    const float* Wv2 = (const float*)d_in[7];
    float* out = (float*)d_out;

    void* pX;
    cudaGetSymbolAddress(&pX, g_X);

    const int smem_pair = (S * QS * 2 + E * VS + 64 * PS + 8) * (int)sizeof(uint32_t);  // ~77.7 KB
    cudaFuncSetAttribute(pair_tc, cudaFuncAttributeMaxDynamicSharedMemorySize, smem_pair);

    transpose_kernel<<<dim3(24, 128, 2), 256>>>(fa, fb);
    convw_all<<<dim3(576, 6), 256>>>(Wq1, Wk1, Wv1, Wq2, Wk2, Wv2);

    gemm1_relu_tc<<<dim3(C / 128, RTOT / 128, 3), 256>>>((const uint32_t*)pX);
    gemm2_tc<<<dim3(1, RTOT / 64, 3), 256>>>();

    vtrans_kernel<<<2 * NB, 256>>>();

    pair_tc<<<dim3(NB, NB), 256, smem_pair>>>(out);
}

// round 8
// speedup vs baseline: 3.1268x; 1.1473x over previous
#include <cuda_runtime.h>
#include <math.h>
#include <stdint.h>

#define NB 128
#define S  49
#define C  768
#define E  96
#define RTOT (2*NB*S)   // 12544
#define EPSC 1e-8f

#define QS  100   // Q/K smem stride (words); 100=4*25, quads distinct
#define PS  60    // P stride (overlaid on uQ)
#define VS  60    // Vt stride
#define VTG 64    // g_Vt padded cols

// ---------------- scratch ----------------
__device__ uint32_t g_X  [(size_t)RTOT * C];        // tf32 transposed features
__device__ uint32_t g_Ht [(size_t)3 * RTOT * C];    // tf32 hidden (3 projections)
__device__ uint32_t g_Q  [(size_t)RTOT * E];        // tf32 Q
__device__ uint32_t g_K  [(size_t)RTOT * E];        // tf32 K
__device__ float    g_V  [(size_t)RTOT * E];        // fp32 V (cosine reference)
__device__ uint32_t g_Vt [(size_t)2 * NB * E * VTG];// tf32 V-transposed per image
__device__ uint32_t g_Wt [(size_t)3 * C * C];       // tf32 W1 staging (q,k,v)
__device__ uint32_t g_W2t[(size_t)3 * C * E];       // tf32 W2 staging (q,k,v)

// ---------------- helpers ----------------
__device__ __forceinline__ uint32_t f2tf32(float f) {
    uint32_t r; asm("cvt.rna.tf32.f32 %0, %1;" : "=r"(r) : "f"(f)); return r;
}
__device__ __forceinline__ void mma_tf32(float c[4], uint32_t a0, uint32_t a1, uint32_t a2, uint32_t a3,
                                         uint32_t b0, uint32_t b1) {
    asm volatile("mma.sync.aligned.m16n8k8.row.col.f32.tf32.tf32.f32 "
                 "{%0,%1,%2,%3}, {%4,%5,%6,%7}, {%8,%9}, {%0,%1,%2,%3};"
                 : "+f"(c[0]), "+f"(c[1]), "+f"(c[2]), "+f"(c[3])
                 : "r"(a0), "r"(a1), "r"(a2), "r"(a3), "r"(b0), "r"(b1));
}

// ---------------- transpose: [B,C,S] -> X[row][c] (tf32) ----------------
__global__ __launch_bounds__(256) void transpose_kernel(const float* __restrict__ fa,
                                                        const float* __restrict__ fb) {
    __shared__ float t[32][S + 1];
    int ct = blockIdx.x, b = blockIdx.y, set = blockIdx.z;
    const float* F = set ? fb : fa;
    int c0 = ct * 32;
    const float* src = F + ((size_t)b * C + c0) * S;
    for (int idx = threadIdx.x; idx < 32 * S; idx += blockDim.x) {
        int i = idx / S, s = idx % S;
        t[i][s] = src[i * S + s];
    }
    __syncthreads();
    int rowbase = set * NB * S + b * S;
    for (int idx = threadIdx.x; idx < S * 32; idx += blockDim.x) {
        int s = idx >> 5, i = idx & 31;
        g_X[(size_t)(rowbase + s) * C + c0 + i] = f2tf32(t[i][s]);
    }
}

// ---------------- all 6 weights -> tf32 staging ----------------
__global__ __launch_bounds__(256) void convw_all(const float* __restrict__ w0, const float* __restrict__ w1,
                                                 const float* __restrict__ w2, const float* __restrict__ w3,
                                                 const float* __restrict__ w4, const float* __restrict__ w5) {
    int y = blockIdx.y;
    const float* src;
    uint32_t* dst;
    int nblk;
    if (y < 3) {
        src = (y == 0) ? w0 : (y == 1) ? w1 : w2;
        dst = g_Wt + (size_t)y * C * C;
        nblk = C * C / 1024;
    } else {
        src = (y == 3) ? w3 : (y == 4) ? w4 : w5;
        dst = g_W2t + (size_t)(y - 3) * C * E;
        nblk = C * E / 1024;
    }
    if (blockIdx.x >= nblk) return;
    int i = (blockIdx.x * 256 + threadIdx.x) * 4;
    float4 v = *(const float4*)&src[i];
    *(uint4*)&dst[i] = make_uint4(f2tf32(v.x), f2tf32(v.y), f2tf32(v.z), f2tf32(v.w));
}

// ---------------- V transpose per image ----------------
__global__ __launch_bounds__(256) void vtrans_kernel() {
    __shared__ float sm[E][S + 1];
    int img = blockIdx.x;
    const float* src = g_V + (size_t)img * S * E;
    for (int idx = threadIdx.x; idx < S * E; idx += 256) {
        int k = idx / E, e = idx % E;
        sm[e][k] = src[idx];
    }
    __syncthreads();
    uint32_t* dst = g_Vt + (size_t)img * E * VTG;
    for (int idx = threadIdx.x; idx < E * VTG; idx += 256) {
        int e = idx / VTG, k = idx % VTG;
        dst[idx] = (k < S) ? f2tf32(sm[e][k]) : 0u;
    }
}

// ---------------- GEMM1 (tf32 TC, z=projection): Ht_z = tf32(relu(X @ W1_z)) ----------------
__global__ __launch_bounds__(256) void gemm1_relu_tc(const uint32_t* __restrict__ A) {
    const uint32_t* B = g_Wt + (size_t)blockIdx.z * C * C;
    uint32_t* Hout = g_Ht + (size_t)blockIdx.z * RTOT * C;

    __shared__ uint32_t sA[2][128][20];
    __shared__ uint32_t sB[2][16][132];

    int tid = threadIdx.x;
    int w = tid >> 5, lane = tid & 31;
    int g = lane >> 2, tig = lane & 3;
    int warpM = w >> 2, warpN = w & 3;
    int mW = warpM * 64, nW = warpN * 32;
    int m0 = blockIdx.y * 128, n0 = blockIdx.x * 128;

    int arow = tid >> 1, ak8 = (tid & 1) * 8;
    int bkr = tid >> 4, bn8 = (tid & 15) * 8;
    const uint32_t* Aptr = A + (size_t)(m0 + arow) * C + ak8;
    const uint32_t* Bptr = B + (size_t)bkr * C + n0 + bn8;

    float acc[4][4][4];
#pragma unroll
    for (int i = 0; i < 4; i++)
#pragma unroll
        for (int j = 0; j < 4; j++)
#pragma unroll
            for (int k = 0; k < 4; k++) acc[i][j][k] = 0.f;

    uint4 ra0, ra1, rb0, rb1;
    ra0 = *(const uint4*)Aptr;       ra1 = *(const uint4*)(Aptr + 4);
    rb0 = *(const uint4*)Bptr;       rb1 = *(const uint4*)(Bptr + 4);
    *(uint4*)&sA[0][arow][ak8]     = ra0;
    *(uint4*)&sA[0][arow][ak8 + 4] = ra1;
    *(uint4*)&sB[0][bkr][bn8]      = rb0;
    *(uint4*)&sB[0][bkr][bn8 + 4]  = rb1;
    __syncthreads();

    const int NT = C / 16;  // 48
    for (int t = 0; t < NT; t++) {
        int buf = t & 1;
        if (t < NT - 1) {
            const uint32_t* Ap = Aptr + (t + 1) * 16;
            const uint32_t* Bp = Bptr + (size_t)(t + 1) * 16 * C;
            ra0 = *(const uint4*)Ap; ra1 = *(const uint4*)(Ap + 4);
            rb0 = *(const uint4*)Bp; rb1 = *(const uint4*)(Bp + 4);
        }
#pragma unroll
        for (int ks = 0; ks < 16; ks += 8) {
            uint32_t afr[4][4];
#pragma unroll
            for (int mt = 0; mt < 4; mt++) {
                int r = mW + mt * 16 + g;
                afr[mt][0] = sA[buf][r    ][ks + tig];
                afr[mt][1] = sA[buf][r + 8][ks + tig];
                afr[mt][2] = sA[buf][r    ][ks + tig + 4];
                afr[mt][3] = sA[buf][r + 8][ks + tig + 4];
            }
            uint32_t bfr[4][2];
#pragma unroll
            for (int nt = 0; nt < 4; nt++) {
                int ncol = nW + nt * 8 + g;
                bfr[nt][0] = sB[buf][ks + tig    ][ncol];
                bfr[nt][1] = sB[buf][ks + tig + 4][ncol];
            }
#pragma unroll
            for (int mt = 0; mt < 4; mt++)
#pragma unroll
                for (int nt = 0; nt < 4; nt++)
                    mma_tf32(acc[mt][nt], afr[mt][0], afr[mt][1], afr[mt][2], afr[mt][3],
                             bfr[nt][0], bfr[nt][1]);
        }
        if (t < NT - 1) {
            int nb = buf ^ 1;
            *(uint4*)&sA[nb][arow][ak8]     = ra0;
            *(uint4*)&sA[nb][arow][ak8 + 4] = ra1;
            *(uint4*)&sB[nb][bkr][bn8]      = rb0;
            *(uint4*)&sB[nb][bkr][bn8 + 4]  = rb1;
            __syncthreads();
        }
    }

#pragma unroll
    for (int mt = 0; mt < 4; mt++) {
        int r = m0 + mW + mt * 16 + g;
#pragma unroll
        for (int nt = 0; nt < 4; nt++) {
            int cc = n0 + nW + nt * 8 + tig * 2;
            uint2 lo, hi;
            lo.x = f2tf32(fmaxf(acc[mt][nt][0], 0.f)); lo.y = f2tf32(fmaxf(acc[mt][nt][1], 0.f));
            hi.x = f2tf32(fmaxf(acc[mt][nt][2], 0.f)); hi.y = f2tf32(fmaxf(acc[mt][nt][3], 0.f));
            *(uint2*)&Hout[(size_t)r * C + cc]       = lo;
            *(uint2*)&Hout[(size_t)(r + 8) * C + cc] = hi;
        }
    }
}

// ---------------- GEMM2 (tf32 TC, z=projection): {Q,K} tf32, V fp32 ----------------
__global__ __launch_bounds__(256) void gemm2_tc() {
    int z = blockIdx.z;
    const uint32_t* A = g_Ht + (size_t)z * RTOT * C;
    const uint32_t* B = g_W2t + (size_t)z * C * E;

    __shared__ uint32_t sA[2][64][20];
    __shared__ uint32_t sB[2][16][100];

    int tid = threadIdx.x;
    int w = tid >> 5, lane = tid & 31;
    int g = lane >> 2, tig = lane & 3;
    int warpM = w >> 2, warpN = w & 3;     // 2 x 4
    int mW = warpM * 32, nW = warpN * 24;
    int m0 = blockIdx.y * 64;

    int arow = tid >> 2, ak = (tid & 3) * 4;
    const uint32_t* Aptr = A + (size_t)(m0 + arow) * C + ak;

    float acc[2][3][4];
#pragma unroll
    for (int i = 0; i < 2; i++)
#pragma unroll
        for (int j = 0; j < 3; j++)
#pragma unroll
            for (int k = 0; k < 4; k++) acc[i][j][k] = 0.f;

    uint4 pa, pb0, pb1;
    int bi0 = tid, bi1 = tid + 256;
    int br0 = bi0 / 24, bc0 = (bi0 % 24) * 4;
    int br1 = bi1 / 24, bc1 = (bi1 % 24) * 4;
    bool hb1 = (bi1 < 384);

    *(uint4*)&sA[0][arow][ak] = *(const uint4*)Aptr;
    *(uint4*)&sB[0][br0][bc0] = *(const uint4*)&B[(size_t)br0 * E + bc0];
    if (hb1) *(uint4*)&sB[0][br1][bc1] = *(const uint4*)&B[(size_t)br1 * E + bc1];
    __syncthreads();

    const int NT = C / 16;  // 48
    for (int t = 0; t < NT; t++) {
        int buf = t & 1;
        if (t < NT - 1) {
            int kt = (t + 1) * 16;
            pa  = *(const uint4*)(Aptr + kt);
            pb0 = *(const uint4*)&B[(size_t)(kt + br0) * E + bc0];
            if (hb1) pb1 = *(const uint4*)&B[(size_t)(kt + br1) * E + bc1];
        }
#pragma unroll
        for (int ks = 0; ks < 16; ks += 8) {
            uint32_t afr[2][4];
#pragma unroll
            for (int mt = 0; mt < 2; mt++) {
                int r = mW + mt * 16 + g;
                afr[mt][0] = sA[buf][r    ][ks + tig];
                afr[mt][1] = sA[buf][r + 8][ks + tig];
                afr[mt][2] = sA[buf][r    ][ks + tig + 4];
                afr[mt][3] = sA[buf][r + 8][ks + tig + 4];
            }
#pragma unroll
            for (int nt = 0; nt < 3; nt++) {
                int ncol = nW + nt * 8 + g;
                uint32_t b0 = sB[buf][ks + tig    ][ncol];
                uint32_t b1 = sB[buf][ks + tig + 4][ncol];
#pragma unroll
                for (int mt = 0; mt < 2; mt++)
                    mma_tf32(acc[mt][nt], afr[mt][0], afr[mt][1], afr[mt][2], afr[mt][3], b0, b1);
            }
        }
        if (t < NT - 1) {
            int nb = buf ^ 1;
            *(uint4*)&sA[nb][arow][ak] = pa;
            *(uint4*)&sB[nb][br0][bc0] = pb0;
            if (hb1) *(uint4*)&sB[nb][br1][bc1] = pb1;
            __syncthreads();
        }
    }

#pragma unroll
    for (int mt = 0; mt < 2; mt++) {
        int r = m0 + mW + mt * 16 + g;
#pragma unroll
        for (int nt = 0; nt < 3; nt++) {
            int cc = nW + nt * 8 + tig * 2;
            if (z < 2) {
                uint32_t* o = (z == 0) ? g_Q : g_K;
                uint2 lo, hi;
                lo.x = f2tf32(acc[mt][nt][0]); lo.y = f2tf32(acc[mt][nt][1]);
                hi.x = f2tf32(acc[mt][nt][2]); hi.y = f2tf32(acc[mt][nt][3]);
                *(uint2*)&o[(size_t)r * E + cc]       = lo;
                *(uint2*)&o[(size_t)(r + 8) * E + cc] = hi;
            } else {
                float2 lo, hi;
                lo.x = acc[mt][nt][0]; lo.y = acc[mt][nt][1];
                hi.x = acc[mt][nt][2]; hi.y = acc[mt][nt][3];
                *(float2*)&g_V[(size_t)r * E + cc]       = lo;
                *(float2*)&g_V[(size_t)(r + 8) * E + cc] = hi;
            }
        }
    }
}

// ---------------- pair kernel: TC attention, P overlaid on uQ, 3 blocks/SM ----------------
__global__ __launch_bounds__(256, 3) void pair_tc(float* __restrict__ out) {
    extern __shared__ uint32_t smbuf[];
    uint32_t* uQ   = smbuf;                   // 49*100 = 4900 (scores A; then P 64*60=3840 overlay)
    uint32_t* uK   = uQ + S * QS;             // 49*100 (scores B; then part[49*8] overlay)
    uint32_t* uVt  = uK + S * QS;             // 96*60
    float*    wsum = (float*)(uVt + E * VS);  // 8
    uint32_t* uP   = uQ;                      // P overlay
    float*    part = (float*)uK;              // cosine partials overlay

    int a = blockIdx.x, b = blockIdx.y;
    int tid = threadIdx.x, w = tid >> 5, lane = tid & 31;
    int g = lane >> 2, tig = lane & 3;
    const float scale = 0.10206207261596577f;  // 1/sqrt(96)

    int mt = w >> 1, half = w & 1;
    int raQ = mt * 16 + g;

    float res0 = 0.f, res1 = 0.f;

#pragma unroll 1
    for (int dir = 0; dir < 2; dir++) {
        int qi = dir ? a : (NB + b);   // Q image
        int ki = dir ? (NB + b) : a;   // K/V image

        // ---- loads ----
        {
            const uint32_t* q = g_Q + (size_t)qi * S * E;
            const uint32_t* k = g_K + (size_t)ki * S * E;
            for (int idx = tid; idx < S * (E / 4); idx += 256) {
                int r = idx / (E / 4), c4 = (idx % (E / 4)) * 4;
                *(uint4*)&uQ[r * QS + c4] = *(const uint4*)&q[r * E + c4];
                *(uint4*)&uK[r * QS + c4] = *(const uint4*)&k[r * E + c4];
            }
            const uint32_t* vt = g_Vt + (size_t)ki * E * VTG;
            for (int idx = tid; idx < E * (VS / 4); idx += 256) {
                int r = idx / (VS / 4), c4 = (idx % (VS / 4)) * 4;
                *(uint4*)&uVt[r * VS + c4] = *(const uint4*)&vt[r * VTG + c4];
            }
        }
        __syncthreads();

        // ---- scores (keep C-fragments in registers through the barrier) ----
        float sc[4][4];
        int ntBeg = half * 4;
        int ntCnt = half ? 3 : 4;
        {
#pragma unroll
            for (int i = 0; i < 4; i++)
#pragma unroll
                for (int j = 0; j < 4; j++) sc[i][j] = 0.f;
#pragma unroll
            for (int ks = 0; ks < E; ks += 8) {
                uint32_t a0 = uQ[raQ * QS + ks + tig];
                uint32_t a1 = uQ[(raQ + 8) * QS + ks + tig];
                uint32_t a2 = uQ[raQ * QS + ks + tig + 4];
                uint32_t a3 = uQ[(raQ + 8) * QS + ks + tig + 4];
#pragma unroll
                for (int n2 = 0; n2 < 4; n2++) {
                    if (n2 < ntCnt) {
                        int nc = (ntBeg + n2) * 8 + g;
                        uint32_t b0 = uK[nc * QS + ks + tig];
                        uint32_t b1 = uK[nc * QS + ks + tig + 4];
                        mma_tf32(sc[n2], a0, a1, a2, a3, b0, b1);
                    }
                }
            }
        }
        __syncthreads();   // uQ reads complete; safe to overlay P

        // ---- write raw scores into P (uQ overlay) ----
        {
            float* Pf = (float*)uP;
#pragma unroll
            for (int n2 = 0; n2 < 4; n2++) {
                if (n2 < ntCnt) {
                    int cc = (ntBeg + n2) * 8 + tig * 2;
                    Pf[raQ * PS + cc]           = sc[n2][0];
                    Pf[raQ * PS + cc + 1]       = sc[n2][1];
                    Pf[(raQ + 8) * PS + cc]     = sc[n2][2];
                    Pf[(raQ + 8) * PS + cc + 1] = sc[n2][3];
                }
            }
        }
        __syncthreads();

        // ---- softmax rows (P back as tf32; zero pad cols 49..55) ----
        {
            float* Pf = (float*)uP;
            for (int r = w; r < S; r += 8) {
                float s0 = Pf[r * PS + lane] * scale;
                int l1 = lane + 32;
                bool v1 = (l1 < S);
                float s1 = v1 ? Pf[r * PS + l1] * scale : -1e30f;
                float mx = fmaxf(s0, s1);
#pragma unroll
                for (int o = 16; o; o >>= 1) mx = fmaxf(mx, __shfl_xor_sync(0xffffffffu, mx, o));
                float p0 = __expf(s0 - mx);
                float p1 = v1 ? __expf(s1 - mx) : 0.f;
                float su = p0 + p1;
#pragma unroll
                for (int o = 16; o; o >>= 1) su += __shfl_xor_sync(0xffffffffu, su, o);
                float inv = __fdividef(1.f, su);
                uP[r * PS + lane] = f2tf32(p0 * inv);
                if (v1) uP[r * PS + l1] = f2tf32(p1 * inv);
                else if (l1 < 56) uP[r * PS + l1] = 0u;
            }
        }
        __syncthreads();

        // ---- PV + cosine partials straight from accumulators ----
        {
            float alc[6][4];
#pragma unroll
            for (int i = 0; i < 6; i++)
#pragma unroll
                for (int j = 0; j < 4; j++) alc[i][j] = 0.f;
            int etBeg = half * 6;
#pragma unroll
            for (int ks = 0; ks < 56; ks += 8) {
                uint32_t a0 = uP[raQ * PS + ks + tig];
                uint32_t a1 = uP[(raQ + 8) * PS + ks + tig];
                uint32_t a2 = uP[raQ * PS + ks + tig + 4];
                uint32_t a3 = uP[(raQ + 8) * PS + ks + tig + 4];
#pragma unroll
                for (int e = 0; e < 6; e++) {
                    int nc = (etBeg + e) * 8 + g;
                    uint32_t b0 = uVt[nc * VS + ks + tig];
                    uint32_t b1 = uVt[nc * VS + ks + tig + 4];
                    mma_tf32(alc[e], a0, a1, a2, a3, b0, b1);
                }
            }

            const float* vref = g_V + (size_t)qi * S * E;
            int r0 = raQ, r1 = raQ + 8;
            bool ok0 = (r0 < S), ok1 = (r1 < S);
            float n0 = 0.f, d0 = 0.f, c0 = 0.f;
            float n1 = 0.f, d1 = 0.f, c1 = 0.f;
#pragma unroll
            for (int e = 0; e < 6; e++) {
                int col = (etBeg + e) * 8 + tig * 2;
                if (ok0) {
                    float2 vc = *(const float2*)&vref[r0 * E + col];
                    n0 += alc[e][0] * vc.x + alc[e][1] * vc.y;
                    d0 += alc[e][0] * alc[e][0] + alc[e][1] * alc[e][1];
                    c0 += vc.x * vc.x + vc.y * vc.y;
                }
                if (ok1) {
                    float2 vc = *(const float2*)&vref[r1 * E + col];
                    n1 += alc[e][2] * vc.x + alc[e][3] * vc.y;
                    d1 += alc[e][2] * alc[e][2] + alc[e][3] * alc[e][3];
                    c1 += vc.x * vc.x + vc.y * vc.y;
                }
            }
#pragma unroll
            for (int o = 1; o <= 2; o <<= 1) {
                n0 += __shfl_xor_sync(0xffffffffu, n0, o);
                d0 += __shfl_xor_sync(0xffffffffu, d0, o);
                c0 += __shfl_xor_sync(0xffffffffu, c0, o);
                n1 += __shfl_xor_sync(0xffffffffu, n1, o);
                d1 += __shfl_xor_sync(0xffffffffu, d1, o);
                c1 += __shfl_xor_sync(0xffffffffu, c1, o);
            }
            if (tig == 0) {
                // part overlays uK (dead after scores) — no extra sync needed
                if (ok0) {
                    part[r0 * 8 + half * 3 + 0] = n0;
                    part[r0 * 8 + half * 3 + 1] = d0;
                    part[r0 * 8 + half * 3 + 2] = c0;
                }
                if (ok1) {
                    part[r1 * 8 + half * 3 + 0] = n1;
                    part[r1 * 8 + half * 3 + 1] = d1;
                    part[r1 * 8 + half * 3 + 2] = c1;
                }
            }
        }
        __syncthreads();

        // ---- per-row cosine + block reduction ----
        {
            float cosv = 0.f;
            if (tid < S) {
                const float* p = &part[tid * 8];
                float num = p[0] + p[3];
                float da  = p[1] + p[4];
                float dc  = p[2] + p[5];
                float na = fmaxf(sqrtf(da), EPSC);
                float nc = fmaxf(sqrtf(dc), EPSC);
                cosv = num / (na * nc);
            }
#pragma unroll
            for (int o = 16; o; o >>= 1) cosv += __shfl_xor_sync(0xffffffffu, cosv, o);
            if (lane == 0) wsum[w] = cosv;
        }
        __syncthreads();
        if (tid == 0) {
            float tot = wsum[0] + wsum[1];   // only warps 0,1 hold tid<49
            if (dir == 0) res0 = tot; else res1 = tot;
        }
        __syncthreads();
    }
    if (tid == 0) out[b * NB + a] = (res0 + res1) * (1.0f / S);
}

// ---------------- launch ----------------
extern "C" void kernel_launch(void* const* d_in, const int* in_sizes, int n_in,
                              void* d_out, int out_size) {
    const float* fa  = (const float*)d_in[0];
    const float* fb  = (const float*)d_in[1];
    const float* Wq1 = (const float*)d_in[2];
    const float* Wq2 = (const float*)d_in[3];
    const float* Wk1 = (const float*)d_in[4];
    const float* Wk2 = (const float*)d_in[5];
    const float* Wv1 = (const float*)d_in[6];
    const float* Wv2 = (const float*)d_in[7];
    float* out = (float*)d_out;

    void* pX;
    cudaGetSymbolAddress(&pX, g_X);

    const int smem_pair = (S * QS * 2 + E * VS + 8) * (int)sizeof(uint32_t);  // 62.3 KB
    cudaFuncSetAttribute(pair_tc, cudaFuncAttributeMaxDynamicSharedMemorySize, smem_pair);

    transpose_kernel<<<dim3(24, 128, 2), 256>>>(fa, fb);
    convw_all<<<dim3(576, 6), 256>>>(Wq1, Wk1, Wv1, Wq2, Wk2, Wv2);

    gemm1_relu_tc<<<dim3(C / 128, RTOT / 128, 3), 256>>>((const uint32_t*)pX);
    gemm2_tc<<<dim3(1, RTOT / 64, 3), 256>>>();

    vtrans_kernel<<<2 * NB, 256>>>();

    pair_tc<<<dim3(NB, NB), 256, smem_pair>>>(out);
}

// round 9
// speedup vs baseline: 4.4255x; 1.4153x over previous
#include <cuda_runtime.h>
#include <math.h>
#include <stdint.h>

#define NB 128
#define S  49
#define C  768
#define E  96
#define RTOT (2*NB*S)   // 12544
#define EPSC 1e-8f

#define QS 52    // Q/K smem stride (words of bf16x2); 52=4*13 -> conflict-free
#define PS 36    // P / Vt stride (words)
#define VTW 32   // g_Vt words per row (64 bf16)

// ---------------- scratch ----------------
__device__ uint32_t g_X  [(size_t)RTOT * C];        // tf32 transposed features
__device__ uint32_t g_Ht [(size_t)3 * RTOT * C];    // tf32 hidden (3 projections)
__device__ uint32_t g_Qb [(size_t)RTOT * (E/2)];    // bf16x2 Q
__device__ uint32_t g_Kb [(size_t)RTOT * (E/2)];    // bf16x2 K
__device__ float    g_V  [(size_t)RTOT * E];        // fp32 V (cosine reference)
__device__ uint32_t g_Vt [(size_t)2 * NB * E * VTW];// bf16x2 V-transposed per image
__device__ uint32_t g_Wt [(size_t)3 * C * C];       // tf32 W1 staging
__device__ uint32_t g_W2t[(size_t)3 * C * E];       // tf32 W2 staging

// ---------------- helpers ----------------
__device__ __forceinline__ uint32_t f2tf32(float f) {
    uint32_t r; asm("cvt.rna.tf32.f32 %0, %1;" : "=r"(r) : "f"(f)); return r;
}
__device__ __forceinline__ uint32_t pack_bf16x2(float lo, float hi) {
    uint32_t r; asm("cvt.rn.bf16x2.f32 %0, %1, %2;" : "=r"(r) : "f"(hi), "f"(lo)); return r;
}
__device__ __forceinline__ void mma_tf32(float c[4], uint32_t a0, uint32_t a1, uint32_t a2, uint32_t a3,
                                         uint32_t b0, uint32_t b1) {
    asm volatile("mma.sync.aligned.m16n8k8.row.col.f32.tf32.tf32.f32 "
                 "{%0,%1,%2,%3}, {%4,%5,%6,%7}, {%8,%9}, {%0,%1,%2,%3};"
                 : "+f"(c[0]), "+f"(c[1]), "+f"(c[2]), "+f"(c[3])
                 : "r"(a0), "r"(a1), "r"(a2), "r"(a3), "r"(b0), "r"(b1));
}
__device__ __forceinline__ void mma_bf16(float c[4], uint32_t a0, uint32_t a1, uint32_t a2, uint32_t a3,
                                         uint32_t b0, uint32_t b1) {
    asm volatile("mma.sync.aligned.m16n8k16.row.col.f32.bf16.bf16.f32 "
                 "{%0,%1,%2,%3}, {%4,%5,%6,%7}, {%8,%9}, {%0,%1,%2,%3};"
                 : "+f"(c[0]), "+f"(c[1]), "+f"(c[2]), "+f"(c[3])
                 : "r"(a0), "r"(a1), "r"(a2), "r"(a3), "r"(b0), "r"(b1));
}

// ---------------- transpose: [B,C,S] -> X[row][c] (tf32) ----------------
__global__ __launch_bounds__(256) void transpose_kernel(const float* __restrict__ fa,
                                                        const float* __restrict__ fb) {
    __shared__ float t[32][S + 1];
    int ct = blockIdx.x, b = blockIdx.y, set = blockIdx.z;
    const float* F = set ? fb : fa;
    int c0 = ct * 32;
    const float* src = F + ((size_t)b * C + c0) * S;
    for (int idx = threadIdx.x; idx < 32 * S; idx += blockDim.x) {
        int i = idx / S, s = idx % S;
        t[i][s] = src[i * S + s];
    }
    __syncthreads();
    int rowbase = set * NB * S + b * S;
    for (int idx = threadIdx.x; idx < S * 32; idx += blockDim.x) {
        int s = idx >> 5, i = idx & 31;
        g_X[(size_t)(rowbase + s) * C + c0 + i] = f2tf32(t[i][s]);
    }
}

// ---------------- all 6 weights -> tf32 staging ----------------
__global__ __launch_bounds__(256) void convw_all(const float* __restrict__ w0, const float* __restrict__ w1,
                                                 const float* __restrict__ w2, const float* __restrict__ w3,
                                                 const float* __restrict__ w4, const float* __restrict__ w5) {
    int y = blockIdx.y;
    const float* src;
    uint32_t* dst;
    int nblk;
    if (y < 3) {
        src = (y == 0) ? w0 : (y == 1) ? w1 : w2;
        dst = g_Wt + (size_t)y * C * C;
        nblk = C * C / 1024;
    } else {
        src = (y == 3) ? w3 : (y == 4) ? w4 : w5;
        dst = g_W2t + (size_t)(y - 3) * C * E;
        nblk = C * E / 1024;
    }
    if (blockIdx.x >= nblk) return;
    int i = (blockIdx.x * 256 + threadIdx.x) * 4;
    float4 v = *(const float4*)&src[i];
    *(uint4*)&dst[i] = make_uint4(f2tf32(v.x), f2tf32(v.y), f2tf32(v.z), f2tf32(v.w));
}

// ---------------- V transpose per image -> bf16x2 along k ----------------
__global__ __launch_bounds__(256) void vtrans_kernel() {
    __shared__ float sm[E][S + 1];
    int img = blockIdx.x;
    const float* src = g_V + (size_t)img * S * E;
    for (int idx = threadIdx.x; idx < S * E; idx += 256) {
        int k = idx / E, e = idx % E;
        sm[e][k] = src[idx];
    }
    __syncthreads();
    uint32_t* dst = g_Vt + (size_t)img * E * VTW;
    for (int idx = threadIdx.x; idx < E * VTW; idx += 256) {
        int e = idx / VTW, kw = idx % VTW;
        int k0 = kw * 2, k1 = kw * 2 + 1;
        float v0 = (k0 < S) ? sm[e][k0] : 0.f;
        float v1 = (k1 < S) ? sm[e][k1] : 0.f;
        dst[idx] = pack_bf16x2(v0, v1);
    }
}

// ---------------- GEMM1 (tf32 TC, z=projection): Ht_z = tf32(relu(X @ W1_z)) ----------------
__global__ __launch_bounds__(256) void gemm1_relu_tc(const uint32_t* __restrict__ A) {
    const uint32_t* B = g_Wt + (size_t)blockIdx.z * C * C;
    uint32_t* Hout = g_Ht + (size_t)blockIdx.z * RTOT * C;

    __shared__ uint32_t sA[2][128][20];
    __shared__ uint32_t sB[2][16][132];

    int tid = threadIdx.x;
    int w = tid >> 5, lane = tid & 31;
    int g = lane >> 2, tig = lane & 3;
    int warpM = w >> 2, warpN = w & 3;
    int mW = warpM * 64, nW = warpN * 32;
    int m0 = blockIdx.y * 128, n0 = blockIdx.x * 128;

    int arow = tid >> 1, ak8 = (tid & 1) * 8;
    int bkr = tid >> 4, bn8 = (tid & 15) * 8;
    const uint32_t* Aptr = A + (size_t)(m0 + arow) * C + ak8;
    const uint32_t* Bptr = B + (size_t)bkr * C + n0 + bn8;

    float acc[4][4][4];
#pragma unroll
    for (int i = 0; i < 4; i++)
#pragma unroll
        for (int j = 0; j < 4; j++)
#pragma unroll
            for (int k = 0; k < 4; k++) acc[i][j][k] = 0.f;

    uint4 ra0, ra1, rb0, rb1;
    ra0 = *(const uint4*)Aptr;       ra1 = *(const uint4*)(Aptr + 4);
    rb0 = *(const uint4*)Bptr;       rb1 = *(const uint4*)(Bptr + 4);
    *(uint4*)&sA[0][arow][ak8]     = ra0;
    *(uint4*)&sA[0][arow][ak8 + 4] = ra1;
    *(uint4*)&sB[0][bkr][bn8]      = rb0;
    *(uint4*)&sB[0][bkr][bn8 + 4]  = rb1;
    __syncthreads();

    const int NT = C / 16;  // 48
    for (int t = 0; t < NT; t++) {
        int buf = t & 1;
        if (t < NT - 1) {
            const uint32_t* Ap = Aptr + (t + 1) * 16;
            const uint32_t* Bp = Bptr + (size_t)(t + 1) * 16 * C;
            ra0 = *(const uint4*)Ap; ra1 = *(const uint4*)(Ap + 4);
            rb0 = *(const uint4*)Bp; rb1 = *(const uint4*)(Bp + 4);
        }
#pragma unroll
        for (int ks = 0; ks < 16; ks += 8) {
            uint32_t afr[4][4];
#pragma unroll
            for (int mt = 0; mt < 4; mt++) {
                int r = mW + mt * 16 + g;
                afr[mt][0] = sA[buf][r    ][ks + tig];
                afr[mt][1] = sA[buf][r + 8][ks + tig];
                afr[mt][2] = sA[buf][r    ][ks + tig + 4];
                afr[mt][3] = sA[buf][r + 8][ks + tig + 4];
            }
            uint32_t bfr[4][2];
#pragma unroll
            for (int nt = 0; nt < 4; nt++) {
                int ncol = nW + nt * 8 + g;
                bfr[nt][0] = sB[buf][ks + tig    ][ncol];
                bfr[nt][1] = sB[buf][ks + tig + 4][ncol];
            }
#pragma unroll
            for (int mt = 0; mt < 4; mt++)
#pragma unroll
                for (int nt = 0; nt < 4; nt++)
                    mma_tf32(acc[mt][nt], afr[mt][0], afr[mt][1], afr[mt][2], afr[mt][3],
                             bfr[nt][0], bfr[nt][1]);
        }
        if (t < NT - 1) {
            int nb = buf ^ 1;
            *(uint4*)&sA[nb][arow][ak8]     = ra0;
            *(uint4*)&sA[nb][arow][ak8 + 4] = ra1;
            *(uint4*)&sB[nb][bkr][bn8]      = rb0;
            *(uint4*)&sB[nb][bkr][bn8 + 4]  = rb1;
            __syncthreads();
        }
    }

#pragma unroll
    for (int mt = 0; mt < 4; mt++) {
        int r = m0 + mW + mt * 16 + g;
#pragma unroll
        for (int nt = 0; nt < 4; nt++) {
            int cc = n0 + nW + nt * 8 + tig * 2;
            uint2 lo, hi;
            lo.x = f2tf32(fmaxf(acc[mt][nt][0], 0.f)); lo.y = f2tf32(fmaxf(acc[mt][nt][1], 0.f));
            hi.x = f2tf32(fmaxf(acc[mt][nt][2], 0.f)); hi.y = f2tf32(fmaxf(acc[mt][nt][3], 0.f));
            *(uint2*)&Hout[(size_t)r * C + cc]       = lo;
            *(uint2*)&Hout[(size_t)(r + 8) * C + cc] = hi;
        }
    }
}

// ---------------- GEMM2 (tf32 TC): Q,K -> bf16x2; V -> fp32 ----------------
__global__ __launch_bounds__(256) void gemm2_tc() {
    int z = blockIdx.z;
    const uint32_t* A = g_Ht + (size_t)z * RTOT * C;
    const uint32_t* B = g_W2t + (size_t)z * C * E;

    __shared__ uint32_t sA[2][64][20];
    __shared__ uint32_t sB[2][16][100];

    int tid = threadIdx.x;
    int w = tid >> 5, lane = tid & 31;
    int g = lane >> 2, tig = lane & 3;
    int warpM = w >> 2, warpN = w & 3;
    int mW = warpM * 32, nW = warpN * 24;
    int m0 = blockIdx.y * 64;

    int arow = tid >> 2, ak = (tid & 3) * 4;
    const uint32_t* Aptr = A + (size_t)(m0 + arow) * C + ak;

    float acc[2][3][4];
#pragma unroll
    for (int i = 0; i < 2; i++)
#pragma unroll
        for (int j = 0; j < 3; j++)
#pragma unroll
            for (int k = 0; k < 4; k++) acc[i][j][k] = 0.f;

    uint4 pa, pb0, pb1;
    int bi0 = tid, bi1 = tid + 256;
    int br0 = bi0 / 24, bc0 = (bi0 % 24) * 4;
    int br1 = bi1 / 24, bc1 = (bi1 % 24) * 4;
    bool hb1 = (bi1 < 384);

    *(uint4*)&sA[0][arow][ak] = *(const uint4*)Aptr;
    *(uint4*)&sB[0][br0][bc0] = *(const uint4*)&B[(size_t)br0 * E + bc0];
    if (hb1) *(uint4*)&sB[0][br1][bc1] = *(const uint4*)&B[(size_t)br1 * E + bc1];
    __syncthreads();

    const int NT = C / 16;  // 48
    for (int t = 0; t < NT; t++) {
        int buf = t & 1;
        if (t < NT - 1) {
            int kt = (t + 1) * 16;
            pa  = *(const uint4*)(Aptr + kt);
            pb0 = *(const uint4*)&B[(size_t)(kt + br0) * E + bc0];
            if (hb1) pb1 = *(const uint4*)&B[(size_t)(kt + br1) * E + bc1];
        }
#pragma unroll
        for (int ks = 0; ks < 16; ks += 8) {
            uint32_t afr[2][4];
#pragma unroll
            for (int mt = 0; mt < 2; mt++) {
                int r = mW + mt * 16 + g;
                afr[mt][0] = sA[buf][r    ][ks + tig];
                afr[mt][1] = sA[buf][r + 8][ks + tig];
                afr[mt][2] = sA[buf][r    ][ks + tig + 4];
                afr[mt][3] = sA[buf][r + 8][ks + tig + 4];
            }
#pragma unroll
            for (int nt = 0; nt < 3; nt++) {
                int ncol = nW + nt * 8 + g;
                uint32_t b0 = sB[buf][ks + tig    ][ncol];
                uint32_t b1 = sB[buf][ks + tig + 4][ncol];
#pragma unroll
                for (int mt = 0; mt < 2; mt++)
                    mma_tf32(acc[mt][nt], afr[mt][0], afr[mt][1], afr[mt][2], afr[mt][3], b0, b1);
            }
        }
        if (t < NT - 1) {
            int nb = buf ^ 1;
            *(uint4*)&sA[nb][arow][ak] = pa;
            *(uint4*)&sB[nb][br0][bc0] = pb0;
            if (hb1) *(uint4*)&sB[nb][br1][bc1] = pb1;
            __syncthreads();
        }
    }

#pragma unroll
    for (int mt = 0; mt < 2; mt++) {
        int r = m0 + mW + mt * 16 + g;
#pragma unroll
        for (int nt = 0; nt < 3; nt++) {
            if (z < 2) {
                uint32_t* o = (z == 0) ? g_Qb : g_Kb;
                int cw = nW / 2 + nt * 4 + tig;   // bf16x2 word index
                o[(size_t)r * (E/2) + cw]       = pack_bf16x2(acc[mt][nt][0], acc[mt][nt][1]);
                o[(size_t)(r + 8) * (E/2) + cw] = pack_bf16x2(acc[mt][nt][2], acc[mt][nt][3]);
            } else {
                int cc = nW + nt * 8 + tig * 2;
                float2 lo, hi;
                lo.x = acc[mt][nt][0]; lo.y = acc[mt][nt][1];
                hi.x = acc[mt][nt][2]; hi.y = acc[mt][nt][3];
                *(float2*)&g_V[(size_t)r * E + cc]       = lo;
                *(float2*)&g_V[(size_t)(r + 8) * E + cc] = hi;
            }
        }
    }
}

// ---------------- pair kernel: bf16 TC attention, softmax-free ----------------
__global__ __launch_bounds__(256, 3) void pair_tc(float* __restrict__ out) {
    extern __shared__ uint32_t smbuf[];
    uint32_t* uQ   = smbuf;                   // 49*52 = 2548 (then P 64*36=2304 overlay)
    uint32_t* uK   = uQ + S * QS;             // 49*52 (then part[49*8] overlay)
    uint32_t* uVt  = uK + S * QS;             // 96*36 = 3456
    float*    wsum = (float*)(uVt + E * PS);  // 8
    uint32_t* uP   = uQ;                      // P overlay (bf16x2)
    float*    part = (float*)uK;              // cosine partials overlay

    int a = blockIdx.x, b = blockIdx.y;
    int tid = threadIdx.x, w = tid >> 5, lane = tid & 31;
    int g = lane >> 2, tig = lane & 3;
    const float scale = 0.10206207261596577f;  // 1/sqrt(96)

    int mt = w >> 1, half = w & 1;
    int raQ = mt * 16 + g;
    int ntBeg = half * 4;
    int ntCnt = half ? 3 : 4;

    float res0 = 0.f, res1 = 0.f;

#pragma unroll 1
    for (int dir = 0; dir < 2; dir++) {
        int qi = dir ? a : (NB + b);   // Q image
        int ki = dir ? (NB + b) : a;   // K/V image

        // ---- loads (bf16x2 raw copies) ----
        {
            const uint32_t* q = g_Qb + (size_t)qi * S * (E/2);
            const uint32_t* k = g_Kb + (size_t)ki * S * (E/2);
            for (int idx = tid; idx < S * 12; idx += 256) {
                int r = idx / 12, c4 = (idx % 12) * 4;
                *(uint4*)&uQ[r * QS + c4] = *(const uint4*)&q[r * (E/2) + c4];
                *(uint4*)&uK[r * QS + c4] = *(const uint4*)&k[r * (E/2) + c4];
            }
            const uint32_t* vt = g_Vt + (size_t)ki * E * VTW;
            for (int idx = tid; idx < E * 8; idx += 256) {
                int r = idx / 8, c4 = (idx % 8) * 4;
                *(uint4*)&uVt[r * PS + c4] = *(const uint4*)&vt[r * VTW + c4];
            }
        }
        __syncthreads();

        // ---- scores (bf16 m16n8k16, fp32 acc, kept in registers) ----
        float sc[4][4];
        {
#pragma unroll
            for (int i = 0; i < 4; i++)
#pragma unroll
                for (int j = 0; j < 4; j++) sc[i][j] = 0.f;
#pragma unroll
            for (int kk = 0; kk < 6; kk++) {
                int kw = kk * 8;
                uint32_t a0 = uQ[raQ * QS + kw + tig];
                uint32_t a1 = uQ[(raQ + 8) * QS + kw + tig];
                uint32_t a2 = uQ[raQ * QS + kw + tig + 4];
                uint32_t a3 = uQ[(raQ + 8) * QS + kw + tig + 4];
#pragma unroll
                for (int n2 = 0; n2 < 4; n2++) {
                    if (n2 < ntCnt) {
                        int nc = (ntBeg + n2) * 8 + g;
                        uint32_t b0 = uK[nc * QS + kw + tig];
                        uint32_t b1 = uK[nc * QS + kw + tig + 4];
                        mma_bf16(sc[n2], a0, a1, a2, a3, b0, b1);
                    }
                }
            }
        }
        __syncthreads();   // uQ/uK reads done; safe to overlay P

        // ---- exp (normalization cancels in cosine) + write bf16 P + zero pads ----
        {
#pragma unroll
            for (int n2 = 0; n2 < 4; n2++) {
                if (n2 < ntCnt) {
                    int nt = ntBeg + n2;
                    int wd = nt * 4 + tig;
                    float p0 = __expf(fminf(sc[n2][0] * scale, 40.f));
                    float p1 = __expf(fminf(sc[n2][1] * scale, 40.f));
                    float p2 = __expf(fminf(sc[n2][2] * scale, 40.f));
                    float p3 = __expf(fminf(sc[n2][3] * scale, 40.f));
                    // mask pad K-columns (col = wd*2 and wd*2+1; valid < 49)
                    int c0 = wd * 2, c1 = wd * 2 + 1;
                    if (c0 >= S) { p0 = 0.f; p2 = 0.f; }
                    if (c1 >= S) { p1 = 0.f; p3 = 0.f; }
                    uP[raQ * PS + wd]       = pack_bf16x2(p0, p1);
                    uP[(raQ + 8) * PS + wd] = pack_bf16x2(p2, p3);
                }
            }
            if (half == 1) {   // zero words 28..31 (cols 56..63) never covered by nt tiles
                uP[raQ * PS + 28 + tig]       = 0u;
                uP[(raQ + 8) * PS + 28 + tig] = 0u;
            }
        }
        __syncthreads();

        // ---- PV (bf16, K=64) + cosine partials from accumulators ----
        {
            float alc[6][4];
#pragma unroll
            for (int i = 0; i < 6; i++)
#pragma unroll
                for (int j = 0; j < 4; j++) alc[i][j] = 0.f;
            int etBeg = half * 6;
#pragma unroll
            for (int kk = 0; kk < 4; kk++) {
                int kw = kk * 8;
                uint32_t a0 = uP[raQ * PS + kw + tig];
                uint32_t a1 = uP[(raQ + 8) * PS + kw + tig];
                uint32_t a2 = uP[raQ * PS + kw + tig + 4];
                uint32_t a3 = uP[(raQ + 8) * PS + kw + tig + 4];
#pragma unroll
                for (int e = 0; e < 6; e++) {
                    int nc = (etBeg + e) * 8 + g;
                    uint32_t b0 = uVt[nc * PS + kw + tig];
                    uint32_t b1 = uVt[nc * PS + kw + tig + 4];
                    mma_bf16(alc[e], a0, a1, a2, a3, b0, b1);
                }
            }

            const float* vref = g_V + (size_t)qi * S * E;
            int r0 = raQ, r1 = raQ + 8;
            bool ok0 = (r0 < S), ok1 = (r1 < S);
            float n0 = 0.f, d0 = 0.f, c0 = 0.f;
            float n1 = 0.f, d1 = 0.f, c1 = 0.f;
#pragma unroll
            for (int e = 0; e < 6; e++) {
                int col = (etBeg + e) * 8 + tig * 2;
                if (ok0) {
                    float2 vc = *(const float2*)&vref[r0 * E + col];
                    n0 += alc[e][0] * vc.x + alc[e][1] * vc.y;
                    d0 += alc[e][0] * alc[e][0] + alc[e][1] * alc[e][1];
                    c0 += vc.x * vc.x + vc.y * vc.y;
                }
                if (ok1) {
                    float2 vc = *(const float2*)&vref[r1 * E + col];
                    n1 += alc[e][2] * vc.x + alc[e][3] * vc.y;
                    d1 += alc[e][2] * alc[e][2] + alc[e][3] * alc[e][3];
                    c1 += vc.x * vc.x + vc.y * vc.y;
                }
            }
#pragma unroll
            for (int o = 1; o <= 2; o <<= 1) {
                n0 += __shfl_xor_sync(0xffffffffu, n0, o);
                d0 += __shfl_xor_sync(0xffffffffu, d0, o);
                c0 += __shfl_xor_sync(0xffffffffu, c0, o);
                n1 += __shfl_xor_sync(0xffffffffu, n1, o);
                d1 += __shfl_xor_sync(0xffffffffu, d1, o);
                c1 += __shfl_xor_sync(0xffffffffu, c1, o);
            }
            if (tig == 0) {
                if (ok0) {
                    part[r0 * 8 + half * 3 + 0] = n0;
                    part[r0 * 8 + half * 3 + 1] = d0;
                    part[r0 * 8 + half * 3 + 2] = c0;
                }
                if (ok1) {
                    part[r1 * 8 + half * 3 + 0] = n1;
                    part[r1 * 8 + half * 3 + 1] = d1;
                    part[r1 * 8 + half * 3 + 2] = c1;
                }
            }
        }
        __syncthreads();

        // ---- per-row cosine + block reduction ----
        {
            float cosv = 0.f;
            if (tid < S) {
                const float* p = &part[tid * 8];
                float num = p[0] + p[3];
                float da  = p[1] + p[4];
                float dc  = p[2] + p[5];
                float na = fmaxf(sqrtf(da), EPSC);
                float nc = fmaxf(sqrtf(dc), EPSC);
                cosv = num / (na * nc);
            }
#pragma unroll
            for (int o = 16; o; o >>= 1) cosv += __shfl_xor_sync(0xffffffffu, cosv, o);
            if (lane == 0) wsum[w] = cosv;
        }
        __syncthreads();
        if (tid == 0) {
            float tot = wsum[0] + wsum[1];
            if (dir == 0) res0 = tot; else res1 = tot;
        }
        __syncthreads();
    }
    if (tid == 0) out[b * NB + a] = (res0 + res1) * (1.0f / S);
}

// ---------------- launch ----------------
extern "C" void kernel_launch(void* const* d_in, const int* in_sizes, int n_in,
                              void* d_out, int out_size) {
    const float* fa  = (const float*)d_in[0];
    const float* fb  = (const float*)d_in[1];
    const float* Wq1 = (const float*)d_in[2];
    const float* Wq2 = (const float*)d_in[3];
    const float* Wk1 = (const float*)d_in[4];
    const float* Wk2 = (const float*)d_in[5];
    const float* Wv1 = (const float*)d_in[6];
    const float* Wv2 = (const float*)d_in[7];
    float* out = (float*)d_out;

    void* pX;
    cudaGetSymbolAddress(&pX, g_X);

    const int smem_pair = (S * QS * 2 + E * PS + 8) * (int)sizeof(uint32_t);  // ~34.2 KB
    cudaFuncSetAttribute(pair_tc, cudaFuncAttributeMaxDynamicSharedMemorySize, smem_pair);

    transpose_kernel<<<dim3(24, 128, 2), 256>>>(fa, fb);
    convw_all<<<dim3(576, 6), 256>>>(Wq1, Wk1, Wv1, Wq2, Wk2, Wv2);

    gemm1_relu_tc<<<dim3(C / 128, RTOT / 128, 3), 256>>>((const uint32_t*)pX);
    gemm2_tc<<<dim3(1, RTOT / 64, 3), 256>>>();

    vtrans_kernel<<<2 * NB, 256>>>();

    pair_tc<<<dim3(NB, NB), 256, smem_pair>>>(out);
}

// round 10
// speedup vs baseline: 5.0002x; 1.1299x over previous
#include <cuda_runtime.h>
#include <math.h>
#include <stdint.h>

#define NB 128
#define S  49
#define C  768
#define CW (C/2)   // 384 packed bf16x2 words
#define E  96
#define RTOT (2*NB*S)   // 12544
#define EPSC 1e-8f

#define QS 52    // pair Q/K smem stride (words)
#define PS 36    // pair P / Vt stride
#define VTW 32   // g_Vt words per row

// ---------------- scratch ----------------
__device__ uint32_t g_X  [(size_t)RTOT * C];        // tf32 features (V chain)
__device__ uint32_t g_Xb [(size_t)RTOT * CW];       // bf16x2 features (Q/K chains)
__device__ uint32_t g_Ht [(size_t)RTOT * C];        // tf32 hidden (V)
__device__ uint32_t g_Hb [(size_t)2 * RTOT * CW];   // bf16x2 hidden (Q,K)
__device__ uint32_t g_Qb [(size_t)RTOT * (E/2)];    // bf16x2 Q
__device__ uint32_t g_Kb [(size_t)RTOT * (E/2)];    // bf16x2 K
__device__ float    g_V  [(size_t)RTOT * E];        // fp32 V (cosine ref)
__device__ uint32_t g_Vt [(size_t)2 * NB * E * VTW];// bf16x2 V-transposed
__device__ uint32_t g_Wt [(size_t)C * C];           // tf32 W1v
__device__ uint32_t g_W2t[(size_t)C * E];           // tf32 W2v
__device__ uint32_t g_W1b[(size_t)2 * C * CW];      // bf16x2 W1q/W1k transposed [n][kw]
__device__ uint32_t g_W2b[(size_t)2 * E * CW];      // bf16x2 W2q/W2k transposed [n][kw]

// ---------------- helpers ----------------
__device__ __forceinline__ uint32_t f2tf32(float f) {
    uint32_t r; asm("cvt.rna.tf32.f32 %0, %1;" : "=r"(r) : "f"(f)); return r;
}
__device__ __forceinline__ uint32_t pack_bf16x2(float lo, float hi) {
    uint32_t r; asm("cvt.rn.bf16x2.f32 %0, %1, %2;" : "=r"(r) : "f"(hi), "f"(lo)); return r;
}
__device__ __forceinline__ void mma_tf32(float c[4], uint32_t a0, uint32_t a1, uint32_t a2, uint32_t a3,
                                         uint32_t b0, uint32_t b1) {
    asm volatile("mma.sync.aligned.m16n8k8.row.col.f32.tf32.tf32.f32 "
                 "{%0,%1,%2,%3}, {%4,%5,%6,%7}, {%8,%9}, {%0,%1,%2,%3};"
                 : "+f"(c[0]), "+f"(c[1]), "+f"(c[2]), "+f"(c[3])
                 : "r"(a0), "r"(a1), "r"(a2), "r"(a3), "r"(b0), "r"(b1));
}
__device__ __forceinline__ void mma_bf16(float c[4], uint32_t a0, uint32_t a1, uint32_t a2, uint32_t a3,
                                         uint32_t b0, uint32_t b1) {
    asm volatile("mma.sync.aligned.m16n8k16.row.col.f32.bf16.bf16.f32 "
                 "{%0,%1,%2,%3}, {%4,%5,%6,%7}, {%8,%9}, {%0,%1,%2,%3};"
                 : "+f"(c[0]), "+f"(c[1]), "+f"(c[2]), "+f"(c[3])
                 : "r"(a0), "r"(a1), "r"(a2), "r"(a3), "r"(b0), "r"(b1));
}

// ---------------- transpose: [B,C,S] -> X (tf32) + Xb (bf16x2) ----------------
__global__ __launch_bounds__(256) void transpose_kernel(const float* __restrict__ fa,
                                                        const float* __restrict__ fb) {
    __shared__ float t[32][S + 1];
    int ct = blockIdx.x, b = blockIdx.y, set = blockIdx.z;
    const float* F = set ? fb : fa;
    int c0 = ct * 32;
    const float* src = F + ((size_t)b * C + c0) * S;
    for (int idx = threadIdx.x; idx < 32 * S; idx += blockDim.x) {
        int i = idx / S, s = idx % S;
        t[i][s] = src[i * S + s];
    }
    __syncthreads();
    int rowbase = set * NB * S + b * S;
    for (int idx = threadIdx.x; idx < S * 32; idx += blockDim.x) {
        int s = idx >> 5, i = idx & 31;
        g_X[(size_t)(rowbase + s) * C + c0 + i] = f2tf32(t[i][s]);
    }
    for (int idx = threadIdx.x; idx < S * 16; idx += blockDim.x) {
        int s = idx >> 4, i2 = idx & 15;
        g_Xb[(size_t)(rowbase + s) * CW + (c0 >> 1) + i2] = pack_bf16x2(t[2 * i2][s], t[2 * i2 + 1][s]);
    }
}

// ---------------- V-chain weights -> tf32 staging ----------------
__global__ __launch_bounds__(256) void convw_v(const float* __restrict__ W1v,
                                               const float* __restrict__ W2v) {
    int y = blockIdx.y;
    const float* src = y ? W2v : W1v;
    uint32_t* dst = y ? g_W2t : g_Wt;
    int nblk = y ? (C * E / 1024) : (C * C / 1024);
    if (blockIdx.x >= nblk) return;
    int i = (blockIdx.x * 256 + threadIdx.x) * 4;
    float4 v = *(const float4*)&src[i];
    *(uint4*)&dst[i] = make_uint4(f2tf32(v.x), f2tf32(v.y), f2tf32(v.z), f2tf32(v.w));
}

// ---------------- Q/K weights -> bf16x2 transposed [n][kw] ----------------
__global__ __launch_bounds__(256) void convwb(const float* __restrict__ Wa, const float* __restrict__ Wb,
                                              uint32_t* __restrict__ dstBase, int N, size_t zstride) {
    const float* W = blockIdx.z ? Wb : Wa;
    uint32_t* d = dstBase + blockIdx.z * zstride;
    int k0 = blockIdx.x * 32, n0 = blockIdx.y * 32;
    __shared__ float sm[32][33];
    for (int idx = threadIdx.x; idx < 1024; idx += 256) {
        int i = idx >> 5, j = idx & 31;
        sm[i][j] = W[(size_t)(k0 + i) * N + n0 + j];
    }
    __syncthreads();
    for (int idx = threadIdx.x; idx < 512; idx += 256) {
        int j = idx >> 4, i2 = idx & 15;
        d[(size_t)(n0 + j) * CW + (k0 >> 1) + i2] = pack_bf16x2(sm[2 * i2][j], sm[2 * i2 + 1][j]);
    }
}

// ---------------- V transpose per image -> bf16x2 along k ----------------
__global__ __launch_bounds__(256) void vtrans_kernel() {
    __shared__ float sm[E][S + 1];
    int img = blockIdx.x;
    const float* src = g_V + (size_t)img * S * E;
    for (int idx = threadIdx.x; idx < S * E; idx += 256) {
        int k = idx / E, e = idx % E;
        sm[e][k] = src[idx];
    }
    __syncthreads();
    uint32_t* dst = g_Vt + (size_t)img * E * VTW;
    for (int idx = threadIdx.x; idx < E * VTW; idx += 256) {
        int e = idx / VTW, kw = idx % VTW;
        int k0 = kw * 2, k1 = kw * 2 + 1;
        float v0 = (k0 < S) ? sm[e][k0] : 0.f;
        float v1 = (k1 < S) ? sm[e][k1] : 0.f;
        dst[idx] = pack_bf16x2(v0, v1);
    }
}

// ---------------- GEMM1 bf16 (Q,K chains): Hb_z = bf16(relu(Xb @ W1_z)) ----------------
__global__ __launch_bounds__(256) void gemm1_relu_bf16() {
    int z = blockIdx.z;
    const uint32_t* B = g_W1b + (size_t)z * C * CW;
    uint32_t* Hout = g_Hb + (size_t)z * RTOT * CW;

    __shared__ uint32_t sA[2][128][20];
    __shared__ uint32_t sB[2][128][20];

    int tid = threadIdx.x;
    int w = tid >> 5, lane = tid & 31;
    int g = lane >> 2, tig = lane & 3;
    int warpM = w >> 2, warpN = w & 3;
    int mW = warpM * 64, nW = warpN * 32;
    int m0 = blockIdx.y * 128, n0 = blockIdx.x * 128;

    int row = tid >> 1, wd = (tid & 1) * 8;
    const uint32_t* Aptr = g_Xb + (size_t)(m0 + row) * CW + wd;
    const uint32_t* Bptr = B + (size_t)(n0 + row) * CW + wd;

    float acc[4][4][4];
#pragma unroll
    for (int i = 0; i < 4; i++)
#pragma unroll
        for (int j = 0; j < 4; j++)
#pragma unroll
            for (int k = 0; k < 4; k++) acc[i][j][k] = 0.f;

    uint4 ra0, ra1, rb0, rb1;
    ra0 = *(const uint4*)Aptr;     ra1 = *(const uint4*)(Aptr + 4);
    rb0 = *(const uint4*)Bptr;     rb1 = *(const uint4*)(Bptr + 4);
    *(uint4*)&sA[0][row][wd]     = ra0;
    *(uint4*)&sA[0][row][wd + 4] = ra1;
    *(uint4*)&sB[0][row][wd]     = rb0;
    *(uint4*)&sB[0][row][wd + 4] = rb1;
    __syncthreads();

    const int NT = C / 32;  // 24 k-tiles of 16 words (32 bf16)
    for (int t = 0; t < NT; t++) {
        int buf = t & 1;
        if (t < NT - 1) {
            const uint32_t* Ap = Aptr + (t + 1) * 16;
            const uint32_t* Bp = Bptr + (t + 1) * 16;
            ra0 = *(const uint4*)Ap; ra1 = *(const uint4*)(Ap + 4);
            rb0 = *(const uint4*)Bp; rb1 = *(const uint4*)(Bp + 4);
        }
#pragma unroll
        for (int ks = 0; ks < 16; ks += 8) {
            uint32_t afr[4][4];
#pragma unroll
            for (int mt = 0; mt < 4; mt++) {
                int r = mW + mt * 16 + g;
                afr[mt][0] = sA[buf][r    ][ks + tig];
                afr[mt][1] = sA[buf][r + 8][ks + tig];
                afr[mt][2] = sA[buf][r    ][ks + tig + 4];
                afr[mt][3] = sA[buf][r + 8][ks + tig + 4];
            }
            uint32_t bfr[4][2];
#pragma unroll
            for (int nt = 0; nt < 4; nt++) {
                int nc = nW + nt * 8 + g;
                bfr[nt][0] = sB[buf][nc][ks + tig];
                bfr[nt][1] = sB[buf][nc][ks + tig + 4];
            }
#pragma unroll
            for (int mt = 0; mt < 4; mt++)
#pragma unroll
                for (int nt = 0; nt < 4; nt++)
                    mma_bf16(acc[mt][nt], afr[mt][0], afr[mt][1], afr[mt][2], afr[mt][3],
                             bfr[nt][0], bfr[nt][1]);
        }
        if (t < NT - 1) {
            int nb = buf ^ 1;
            *(uint4*)&sA[nb][row][wd]     = ra0;
            *(uint4*)&sA[nb][row][wd + 4] = ra1;
            *(uint4*)&sB[nb][row][wd]     = rb0;
            *(uint4*)&sB[nb][row][wd + 4] = rb1;
            __syncthreads();
        }
    }

#pragma unroll
    for (int mt = 0; mt < 4; mt++) {
        int r = m0 + mW + mt * 16 + g;
#pragma unroll
        for (int nt = 0; nt < 4; nt++) {
            int cw = (n0 + nW) / 2 + nt * 4 + tig;
            float p0 = fmaxf(acc[mt][nt][0], 0.f), p1 = fmaxf(acc[mt][nt][1], 0.f);
            float p2 = fmaxf(acc[mt][nt][2], 0.f), p3 = fmaxf(acc[mt][nt][3], 0.f);
            Hout[(size_t)r * CW + cw]       = pack_bf16x2(p0, p1);
            Hout[(size_t)(r + 8) * CW + cw] = pack_bf16x2(p2, p3);
        }
    }
}

// ---------------- GEMM2 bf16 (Q,K): out = Hb_z @ W2_z ----------------
__global__ __launch_bounds__(256) void gemm2_bf16() {
    int z = blockIdx.z;
    const uint32_t* A = g_Hb + (size_t)z * RTOT * CW;
    const uint32_t* B = g_W2b + (size_t)z * E * CW;
    uint32_t* O = z ? g_Kb : g_Qb;

    __shared__ uint32_t sA[2][64][20];
    __shared__ uint32_t sB[2][96][20];

    int tid = threadIdx.x;
    int w = tid >> 5, lane = tid & 31;
    int g = lane >> 2, tig = lane & 3;
    int warpM = w >> 2, warpN = w & 3;
    int mW = warpM * 32, nW = warpN * 24;
    int m0 = blockIdx.y * 64;

    int arow = tid >> 2, aw = (tid & 3) * 4;
    const uint32_t* Aptr = A + (size_t)(m0 + arow) * CW + aw;
    int bi0 = tid, bi1 = tid + 256;          // of 384 uint4 in B tile (96 rows x 16 words)
    int br0 = bi0 >> 2, bw0 = (bi0 & 3) * 4;
    int br1 = bi1 >> 2, bw1 = (bi1 & 3) * 4;
    bool hb1 = (bi1 < 384);

    float acc[2][3][4];
#pragma unroll
    for (int i = 0; i < 2; i++)
#pragma unroll
        for (int j = 0; j < 3; j++)
#pragma unroll
            for (int k = 0; k < 4; k++) acc[i][j][k] = 0.f;

    uint4 pa, pb0, pb1;
    *(uint4*)&sA[0][arow][aw] = *(const uint4*)Aptr;
    *(uint4*)&sB[0][br0][bw0] = *(const uint4*)&B[(size_t)br0 * CW + bw0];
    if (hb1) *(uint4*)&sB[0][br1][bw1] = *(const uint4*)&B[(size_t)br1 * CW + bw1];
    __syncthreads();

    const int NT = C / 32;  // 24
    for (int t = 0; t < NT; t++) {
        int buf = t & 1;
        if (t < NT - 1) {
            int kt = (t + 1) * 16;
            pa  = *(const uint4*)(Aptr + kt);
            pb0 = *(const uint4*)&B[(size_t)br0 * CW + kt + bw0];
            if (hb1) pb1 = *(const uint4*)&B[(size_t)br1 * CW + kt + bw1];
        }
#pragma unroll
        for (int ks = 0; ks < 16; ks += 8) {
            uint32_t afr[2][4];
#pragma unroll
            for (int mt = 0; mt < 2; mt++) {
                int r = mW + mt * 16 + g;
                afr[mt][0] = sA[buf][r    ][ks + tig];
                afr[mt][1] = sA[buf][r + 8][ks + tig];
                afr[mt][2] = sA[buf][r    ][ks + tig + 4];
                afr[mt][3] = sA[buf][r + 8][ks + tig + 4];
            }
#pragma unroll
            for (int nt = 0; nt < 3; nt++) {
                int nc = nW + nt * 8 + g;
                uint32_t b0 = sB[buf][nc][ks + tig];
                uint32_t b1 = sB[buf][nc][ks + tig + 4];
#pragma unroll
                for (int mt = 0; mt < 2; mt++)
                    mma_bf16(acc[mt][nt], afr[mt][0], afr[mt][1], afr[mt][2], afr[mt][3], b0, b1);
            }
        }
        if (t < NT - 1) {
            int nb = buf ^ 1;
            *(uint4*)&sA[nb][arow][aw] = pa;
            *(uint4*)&sB[nb][br0][bw0] = pb0;
            if (hb1) *(uint4*)&sB[nb][br1][bw1] = pb1;
            __syncthreads();
        }
    }

#pragma unroll
    for (int mt = 0; mt < 2; mt++) {
        int r = m0 + mW + mt * 16 + g;
#pragma unroll
        for (int nt = 0; nt < 3; nt++) {
            int cw = nW / 2 + nt * 4 + tig;
            O[(size_t)r * (E / 2) + cw]       = pack_bf16x2(acc[mt][nt][0], acc[mt][nt][1]);
            O[(size_t)(r + 8) * (E / 2) + cw] = pack_bf16x2(acc[mt][nt][2], acc[mt][nt][3]);
        }
    }
}

// ---------------- GEMM1 tf32 (V chain): Ht = tf32(relu(X @ W1v)) ----------------
__global__ __launch_bounds__(256) void gemm1_relu_tc() {
    const uint32_t* A = g_X;
    const uint32_t* B = g_Wt;
    uint32_t* Hout = g_Ht;

    __shared__ uint32_t sA[2][128][20];
    __shared__ uint32_t sB[2][16][132];

    int tid = threadIdx.x;
    int w = tid >> 5, lane = tid & 31;
    int g = lane >> 2, tig = lane & 3;
    int warpM = w >> 2, warpN = w & 3;
    int mW = warpM * 64, nW = warpN * 32;
    int m0 = blockIdx.y * 128, n0 = blockIdx.x * 128;

    int arow = tid >> 1, ak8 = (tid & 1) * 8;
    int bkr = tid >> 4, bn8 = (tid & 15) * 8;
    const uint32_t* Aptr = A + (size_t)(m0 + arow) * C + ak8;
    const uint32_t* Bptr = B + (size_t)bkr * C + n0 + bn8;

    float acc[4][4][4];
#pragma unroll
    for (int i = 0; i < 4; i++)
#pragma unroll
        for (int j = 0; j < 4; j++)
#pragma unroll
            for (int k = 0; k < 4; k++) acc[i][j][k] = 0.f;

    uint4 ra0, ra1, rb0, rb1;
    ra0 = *(const uint4*)Aptr;       ra1 = *(const uint4*)(Aptr + 4);
    rb0 = *(const uint4*)Bptr;       rb1 = *(const uint4*)(Bptr + 4);
    *(uint4*)&sA[0][arow][ak8]     = ra0;
    *(uint4*)&sA[0][arow][ak8 + 4] = ra1;
    *(uint4*)&sB[0][bkr][bn8]      = rb0;
    *(uint4*)&sB[0][bkr][bn8 + 4]  = rb1;
    __syncthreads();

    const int NT = C / 16;  // 48
    for (int t = 0; t < NT; t++) {
        int buf = t & 1;
        if (t < NT - 1) {
            const uint32_t* Ap = Aptr + (t + 1) * 16;
            const uint32_t* Bp = Bptr + (size_t)(t + 1) * 16 * C;
            ra0 = *(const uint4*)Ap; ra1 = *(const uint4*)(Ap + 4);
            rb0 = *(const uint4*)Bp; rb1 = *(const uint4*)(Bp + 4);
        }
#pragma unroll
        for (int ks = 0; ks < 16; ks += 8) {
            uint32_t afr[4][4];
#pragma unroll
            for (int mt = 0; mt < 4; mt++) {
                int r = mW + mt * 16 + g;
                afr[mt][0] = sA[buf][r    ][ks + tig];
                afr[mt][1] = sA[buf][r + 8][ks + tig];
                afr[mt][2] = sA[buf][r    ][ks + tig + 4];
                afr[mt][3] = sA[buf][r + 8][ks + tig + 4];
            }
            uint32_t bfr[4][2];
#pragma unroll
            for (int nt = 0; nt < 4; nt++) {
                int ncol = nW + nt * 8 + g;
                bfr[nt][0] = sB[buf][ks + tig    ][ncol];
                bfr[nt][1] = sB[buf][ks + tig + 4][ncol];
            }
#pragma unroll
            for (int mt = 0; mt < 4; mt++)
#pragma unroll
                for (int nt = 0; nt < 4; nt++)
                    mma_tf32(acc[mt][nt], afr[mt][0], afr[mt][1], afr[mt][2], afr[mt][3],
                             bfr[nt][0], bfr[nt][1]);
        }
        if (t < NT - 1) {
            int nb = buf ^ 1;
            *(uint4*)&sA[nb][arow][ak8]     = ra0;
            *(uint4*)&sA[nb][arow][ak8 + 4] = ra1;
            *(uint4*)&sB[nb][bkr][bn8]      = rb0;
            *(uint4*)&sB[nb][bkr][bn8 + 4]  = rb1;
            __syncthreads();
        }
    }

#pragma unroll
    for (int mt = 0; mt < 4; mt++) {
        int r = m0 + mW + mt * 16 + g;
#pragma unroll
        for (int nt = 0; nt < 4; nt++) {
            int cc = n0 + nW + nt * 8 + tig * 2;
            uint2 lo, hi;
            lo.x = f2tf32(fmaxf(acc[mt][nt][0], 0.f)); lo.y = f2tf32(fmaxf(acc[mt][nt][1], 0.f));
            hi.x = f2tf32(fmaxf(acc[mt][nt][2], 0.f)); hi.y = f2tf32(fmaxf(acc[mt][nt][3], 0.f));
            *(uint2*)&Hout[(size_t)r * C + cc]       = lo;
            *(uint2*)&Hout[(size_t)(r + 8) * C + cc] = hi;
        }
    }
}

// ---------------- GEMM2 tf32 (V): g_V = Ht @ W2v (fp32 out) ----------------
__global__ __launch_bounds__(256) void gemm2_tc() {
    const uint32_t* A = g_Ht;
    const uint32_t* B = g_W2t;

    __shared__ uint32_t sA[2][64][20];
    __shared__ uint32_t sB[2][16][100];

    int tid = threadIdx.x;
    int w = tid >> 5, lane = tid & 31;
    int g = lane >> 2, tig = lane & 3;
    int warpM = w >> 2, warpN = w & 3;
    int mW = warpM * 32, nW = warpN * 24;
    int m0 = blockIdx.y * 64;

    int arow = tid >> 2, ak = (tid & 3) * 4;
    const uint32_t* Aptr = A + (size_t)(m0 + arow) * C + ak;

    float acc[2][3][4];
#pragma unroll
    for (int i = 0; i < 2; i++)
#pragma unroll
        for (int j = 0; j < 3; j++)
#pragma unroll
            for (int k = 0; k < 4; k++) acc[i][j][k] = 0.f;

    uint4 pa, pb0, pb1;
    int bi0 = tid, bi1 = tid + 256;
    int br0 = bi0 / 24, bc0 = (bi0 % 24) * 4;
    int br1 = bi1 / 24, bc1 = (bi1 % 24) * 4;
    bool hb1 = (bi1 < 384);

    *(uint4*)&sA[0][arow][ak] = *(const uint4*)Aptr;
    *(uint4*)&sB[0][br0][bc0] = *(const uint4*)&B[(size_t)br0 * E + bc0];
    if (hb1) *(uint4*)&sB[0][br1][bc1] = *(const uint4*)&B[(size_t)br1 * E + bc1];
    __syncthreads();

    const int NT = C / 16;  // 48
    for (int t = 0; t < NT; t++) {
        int buf = t & 1;
        if (t < NT - 1) {
            int kt = (t + 1) * 16;
            pa  = *(const uint4*)(Aptr + kt);
            pb0 = *(const uint4*)&B[(size_t)(kt + br0) * E + bc0];
            if (hb1) pb1 = *(const uint4*)&B[(size_t)(kt + br1) * E + bc1];
        }
#pragma unroll
        for (int ks = 0; ks < 16; ks += 8) {
            uint32_t afr[2][4];
#pragma unroll
            for (int mt = 0; mt < 2; mt++) {
                int r = mW + mt * 16 + g;
                afr[mt][0] = sA[buf][r    ][ks + tig];
                afr[mt][1] = sA[buf][r + 8][ks + tig];
                afr[mt][2] = sA[buf][r    ][ks + tig + 4];
                afr[mt][3] = sA[buf][r + 8][ks + tig + 4];
            }
#pragma unroll
            for (int nt = 0; nt < 3; nt++) {
                int ncol = nW + nt * 8 + g;
                uint32_t b0 = sB[buf][ks + tig    ][ncol];
                uint32_t b1 = sB[buf][ks + tig + 4][ncol];
#pragma unroll
                for (int mt = 0; mt < 2; mt++)
                    mma_tf32(acc[mt][nt], afr[mt][0], afr[mt][1], afr[mt][2], afr[mt][3], b0, b1);
            }
        }
        if (t < NT - 1) {
            int nb = buf ^ 1;
            *(uint4*)&sA[nb][arow][ak] = pa;
            *(uint4*)&sB[nb][br0][bc0] = pb0;
            if (hb1) *(uint4*)&sB[nb][br1][bc1] = pb1;
            __syncthreads();
        }
    }

#pragma unroll
    for (int mt = 0; mt < 2; mt++) {
        int r = m0 + mW + mt * 16 + g;
#pragma unroll
        for (int nt = 0; nt < 3; nt++) {
            int cc = nW + nt * 8 + tig * 2;
            float2 lo, hi;
            lo.x = acc[mt][nt][0]; lo.y = acc[mt][nt][1];
            hi.x = acc[mt][nt][2]; hi.y = acc[mt][nt][3];
            *(float2*)&g_V[(size_t)r * E + cc]       = lo;
            *(float2*)&g_V[(size_t)(r + 8) * E + cc] = hi;
        }
    }
}

// ---------------- pair kernel: bf16 TC attention, softmax-free (unchanged) ----------------
__global__ __launch_bounds__(256, 3) void pair_tc(float* __restrict__ out) {
    extern __shared__ uint32_t smbuf[];
    uint32_t* uQ   = smbuf;
    uint32_t* uK   = uQ + S * QS;
    uint32_t* uVt  = uK + S * QS;
    float*    wsum = (float*)(uVt + E * PS);
    uint32_t* uP   = uQ;
    float*    part = (float*)uK;

    int a = blockIdx.x, b = blockIdx.y;
    int tid = threadIdx.x, w = tid >> 5, lane = tid & 31;
    int g = lane >> 2, tig = lane & 3;
    const float scale = 0.10206207261596577f;

    int mt = w >> 1, half = w & 1;
    int raQ = mt * 16 + g;
    int ntBeg = half * 4;
    int ntCnt = half ? 3 : 4;

    float res0 = 0.f, res1 = 0.f;

#pragma unroll 1
    for (int dir = 0; dir < 2; dir++) {
        int qi = dir ? a : (NB + b);
        int ki = dir ? (NB + b) : a;

        {
            const uint32_t* q = g_Qb + (size_t)qi * S * (E/2);
            const uint32_t* k = g_Kb + (size_t)ki * S * (E/2);
            for (int idx = tid; idx < S * 12; idx += 256) {
                int r = idx / 12, c4 = (idx % 12) * 4;
                *(uint4*)&uQ[r * QS + c4] = *(const uint4*)&q[r * (E/2) + c4];
                *(uint4*)&uK[r * QS + c4] = *(const uint4*)&k[r * (E/2) + c4];
            }
            const uint32_t* vt = g_Vt + (size_t)ki * E * VTW;
            for (int idx = tid; idx < E * 8; idx += 256) {
                int r = idx / 8, c4 = (idx % 8) * 4;
                *(uint4*)&uVt[r * PS + c4] = *(const uint4*)&vt[r * VTW + c4];
            }
        }
        __syncthreads();

        float sc[4][4];
        {
#pragma unroll
            for (int i = 0; i < 4; i++)
#pragma unroll
                for (int j = 0; j < 4; j++) sc[i][j] = 0.f;
#pragma unroll
            for (int kk = 0; kk < 6; kk++) {
                int kw = kk * 8;
                uint32_t a0 = uQ[raQ * QS + kw + tig];
                uint32_t a1 = uQ[(raQ + 8) * QS + kw + tig];
                uint32_t a2 = uQ[raQ * QS + kw + tig + 4];
                uint32_t a3 = uQ[(raQ + 8) * QS + kw + tig + 4];
#pragma unroll
                for (int n2 = 0; n2 < 4; n2++) {
                    if (n2 < ntCnt) {
                        int nc = (ntBeg + n2) * 8 + g;
                        uint32_t b0 = uK[nc * QS + kw + tig];
                        uint32_t b1 = uK[nc * QS + kw + tig + 4];
                        mma_bf16(sc[n2], a0, a1, a2, a3, b0, b1);
                    }
                }
            }
        }
        __syncthreads();

        {
#pragma unroll
            for (int n2 = 0; n2 < 4; n2++) {
                if (n2 < ntCnt) {
                    int nt = ntBeg + n2;
                    int wd = nt * 4 + tig;
                    float p0 = __expf(fminf(sc[n2][0] * scale, 40.f));
                    float p1 = __expf(fminf(sc[n2][1] * scale, 40.f));
                    float p2 = __expf(fminf(sc[n2][2] * scale, 40.f));
                    float p3 = __expf(fminf(sc[n2][3] * scale, 40.f));
                    int c0 = wd * 2, c1 = wd * 2 + 1;
                    if (c0 >= S) { p0 = 0.f; p2 = 0.f; }
                    if (c1 >= S) { p1 = 0.f; p3 = 0.f; }
                    uP[raQ * PS + wd]       = pack_bf16x2(p0, p1);
                    uP[(raQ + 8) * PS + wd] = pack_bf16x2(p2, p3);
                }
            }
            if (half == 1) {
                uP[raQ * PS + 28 + tig]       = 0u;
                uP[(raQ + 8) * PS + 28 + tig] = 0u;
            }
        }
        __syncthreads();

        {
            float alc[6][4];
#pragma unroll
            for (int i = 0; i < 6; i++)
#pragma unroll
                for (int j = 0; j < 4; j++) alc[i][j] = 0.f;
            int etBeg = half * 6;
#pragma unroll
            for (int kk = 0; kk < 4; kk++) {
                int kw = kk * 8;
                uint32_t a0 = uP[raQ * PS + kw + tig];
                uint32_t a1 = uP[(raQ + 8) * PS + kw + tig];
                uint32_t a2 = uP[raQ * PS + kw + tig + 4];
                uint32_t a3 = uP[(raQ + 8) * PS + kw + tig + 4];
#pragma unroll
                for (int e = 0; e < 6; e++) {
                    int nc = (etBeg + e) * 8 + g;
                    uint32_t b0 = uVt[nc * PS + kw + tig];
                    uint32_t b1 = uVt[nc * PS + kw + tig + 4];
                    mma_bf16(alc[e], a0, a1, a2, a3, b0, b1);
                }
            }

            const float* vref = g_V + (size_t)qi * S * E;
            int r0 = raQ, r1 = raQ + 8;
            bool ok0 = (r0 < S), ok1 = (r1 < S);
            float n0 = 0.f, d0 = 0.f, c0 = 0.f;
            float n1 = 0.f, d1 = 0.f, c1 = 0.f;
#pragma unroll
            for (int e = 0; e < 6; e++) {
                int col = (etBeg + e) * 8 + tig * 2;
                if (ok0) {
                    float2 vc = *(const float2*)&vref[r0 * E + col];
                    n0 += alc[e][0] * vc.x + alc[e][1] * vc.y;
                    d0 += alc[e][0] * alc[e][0] + alc[e][1] * alc[e][1];
                    c0 += vc.x * vc.x + vc.y * vc.y;
                }
                if (ok1) {
                    float2 vc = *(const float2*)&vref[r1 * E + col];
                    n1 += alc[e][2] * vc.x + alc[e][3] * vc.y;
                    d1 += alc[e][2] * alc[e][2] + alc[e][3] * alc[e][3];
                    c1 += vc.x * vc.x + vc.y * vc.y;
                }
            }
#pragma unroll
            for (int o = 1; o <= 2; o <<= 1) {
                n0 += __shfl_xor_sync(0xffffffffu, n0, o);
                d0 += __shfl_xor_sync(0xffffffffu, d0, o);
                c0 += __shfl_xor_sync(0xffffffffu, c0, o);
                n1 += __shfl_xor_sync(0xffffffffu, n1, o);
                d1 += __shfl_xor_sync(0xffffffffu, d1, o);
                c1 += __shfl_xor_sync(0xffffffffu, c1, o);
            }
            if (tig == 0) {
                if (ok0) {
                    part[r0 * 8 + half * 3 + 0] = n0;
                    part[r0 * 8 + half * 3 + 1] = d0;
                    part[r0 * 8 + half * 3 + 2] = c0;
                }
                if (ok1) {
                    part[r1 * 8 + half * 3 + 0] = n1;
                    part[r1 * 8 + half * 3 + 1] = d1;
                    part[r1 * 8 + half * 3 + 2] = c1;
                }
            }
        }
        __syncthreads();

        {
            float cosv = 0.f;
            if (tid < S) {
                const float* p = &part[tid * 8];
                float num = p[0] + p[3];
                float da  = p[1] + p[4];
                float dc  = p[2] + p[5];
                float na = fmaxf(sqrtf(da), EPSC);
                float nc = fmaxf(sqrtf(dc), EPSC);
                cosv = num / (na * nc);
            }
#pragma unroll
            for (int o = 16; o; o >>= 1) cosv += __shfl_xor_sync(0xffffffffu, cosv, o);
            if (lane == 0) wsum[w] = cosv;
        }
        __syncthreads();
        if (tid == 0) {
            float tot = wsum[0] + wsum[1];
            if (dir == 0) res0 = tot; else res1 = tot;
        }
        __syncthreads();
    }
    if (tid == 0) out[b * NB + a] = (res0 + res1) * (1.0f / S);
}

// ---------------- launch ----------------
extern "C" void kernel_launch(void* const* d_in, const int* in_sizes, int n_in,
                              void* d_out, int out_size) {
    const float* fa  = (const float*)d_in[0];
    const float* fb  = (const float*)d_in[1];
    const float* Wq1 = (const float*)d_in[2];
    const float* Wq2 = (const float*)d_in[3];
    const float* Wk1 = (const float*)d_in[4];
    const float* Wk2 = (const float*)d_in[5];
    const float* Wv1 = (const float*)d_in[6];
    const float* Wv2 = (const float*)d_in[7];
    float* out = (float*)d_out;

    void *pW1b, *pW2b;
    cudaGetSymbolAddress(&pW1b, g_W1b);
    cudaGetSymbolAddress(&pW2b, g_W2b);

    const int smem_pair = (S * QS * 2 + E * PS + 8) * (int)sizeof(uint32_t);  // ~34.2 KB
    cudaFuncSetAttribute(pair_tc, cudaFuncAttributeMaxDynamicSharedMemorySize, smem_pair);

    transpose_kernel<<<dim3(24, 128, 2), 256>>>(fa, fb);
    convw_v<<<dim3(576, 2), 256>>>(Wv1, Wv2);
    convwb<<<dim3(24, 24, 2), 256>>>(Wq1, Wk1, (uint32_t*)pW1b, C, (size_t)C * CW);
    convwb<<<dim3(24, 3, 2), 256>>>(Wq2, Wk2, (uint32_t*)pW2b, E, (size_t)E * CW);

    gemm1_relu_bf16<<<dim3(C / 128, RTOT / 128, 2), 256>>>();
    gemm1_relu_tc<<<dim3(C / 128, RTOT / 128), 256>>>();

    gemm2_bf16<<<dim3(1, RTOT / 64, 2), 256>>>();
    gemm2_tc<<<dim3(1, RTOT / 64), 256>>>();

    vtrans_kernel<<<2 * NB, 256>>>();

    pair_tc<<<dim3(NB, NB), 256, smem_pair>>>(out);
}

// round 12
// speedup vs baseline: 5.7668x; 1.1533x over previous
#include <cuda_runtime.h>
#include <math.h>
#include <stdint.h>

#define NB 128
#define S  49
#define C  768
#define CW (C/2)   // 384 packed bf16x2 words
#define E  96
#define RTOT (2*NB*S)   // 12544
#define EPSC 1e-8f

#define QS 52    // pair Q/K smem stride (words)
#define PS 36    // pair P / Vt stride
#define VTW 32   // g_Vt words per row

// ---------------- scratch ----------------
__device__ uint32_t g_Xb [(size_t)RTOT * CW];       // bf16x2 features
__device__ uint32_t g_Hb [(size_t)3 * RTOT * CW];   // bf16x2 hidden (q,k,v)
__device__ uint32_t g_Qb [(size_t)RTOT * (E/2)];    // bf16x2 Q
__device__ uint32_t g_Kb [(size_t)RTOT * (E/2)];    // bf16x2 K
__device__ float    g_V  [(size_t)RTOT * E];        // fp32 V (cosine ref values)
__device__ uint32_t g_Vt [(size_t)2 * NB * E * VTW];// bf16x2 V-transposed
__device__ uint32_t g_W1b[(size_t)3 * C * CW];      // bf16x2 W1{q,k,v} transposed [n][kw]
__device__ uint32_t g_W2b[(size_t)3 * E * CW];      // bf16x2 W2{q,k,v} transposed [n][kw]

// ---------------- helpers ----------------
__device__ __forceinline__ uint32_t pack_bf16x2(float lo, float hi) {
    uint32_t r; asm("cvt.rn.bf16x2.f32 %0, %1, %2;" : "=r"(r) : "f"(hi), "f"(lo)); return r;
}
__device__ __forceinline__ void mma_bf16(float c[4], uint32_t a0, uint32_t a1, uint32_t a2, uint32_t a3,
                                         uint32_t b0, uint32_t b1) {
    asm volatile("mma.sync.aligned.m16n8k16.row.col.f32.bf16.bf16.f32 "
                 "{%0,%1,%2,%3}, {%4,%5,%6,%7}, {%8,%9}, {%0,%1,%2,%3};"
                 : "+f"(c[0]), "+f"(c[1]), "+f"(c[2]), "+f"(c[3])
                 : "r"(a0), "r"(a1), "r"(a2), "r"(a3), "r"(b0), "r"(b1));
}

// ---------------- transpose: [B,C,S] -> Xb[row][kw] (bf16x2) ----------------
__global__ __launch_bounds__(256) void transpose_kernel(const float* __restrict__ fa,
                                                        const float* __restrict__ fb) {
    __shared__ float t[32][S + 1];
    int ct = blockIdx.x, b = blockIdx.y, set = blockIdx.z;
    const float* F = set ? fb : fa;
    int c0 = ct * 32;
    const float* src = F + ((size_t)b * C + c0) * S;
    for (int idx = threadIdx.x; idx < 32 * S; idx += blockDim.x) {
        int i = idx / S, s = idx % S;
        t[i][s] = src[i * S + s];
    }
    __syncthreads();
    int rowbase = set * NB * S + b * S;
    for (int idx = threadIdx.x; idx < S * 16; idx += blockDim.x) {
        int s = idx >> 4, i2 = idx & 15;
        g_Xb[(size_t)(rowbase + s) * CW + (c0 >> 1) + i2] = pack_bf16x2(t[2 * i2][s], t[2 * i2 + 1][s]);
    }
}

// ---------------- weights -> bf16x2 transposed [n][kw] ----------------
__global__ __launch_bounds__(256) void convwb(const float* __restrict__ Wa, const float* __restrict__ Wb,
                                              const float* __restrict__ Wc,
                                              uint32_t* __restrict__ dstBase, int N, size_t zstride) {
    const float* W = (blockIdx.z == 0) ? Wa : (blockIdx.z == 1) ? Wb : Wc;
    uint32_t* d = dstBase + blockIdx.z * zstride;
    int k0 = blockIdx.x * 32, n0 = blockIdx.y * 32;
    __shared__ float sm[32][33];
    for (int idx = threadIdx.x; idx < 1024; idx += 256) {
        int i = idx >> 5, j = idx & 31;
        sm[i][j] = W[(size_t)(k0 + i) * N + n0 + j];
    }
    __syncthreads();
    for (int idx = threadIdx.x; idx < 512; idx += 256) {
        int j = idx >> 4, i2 = idx & 15;
        d[(size_t)(n0 + j) * CW + (k0 >> 1) + i2] = pack_bf16x2(sm[2 * i2][j], sm[2 * i2 + 1][j]);
    }
}

// ---------------- V transpose per image -> bf16x2 along k ----------------
__global__ __launch_bounds__(256) void vtrans_kernel() {
    __shared__ float sm[E][S + 1];
    int img = blockIdx.x;
    const float* src = g_V + (size_t)img * S * E;
    for (int idx = threadIdx.x; idx < S * E; idx += 256) {
        int k = idx / E, e = idx % E;
        sm[e][k] = src[idx];
    }
    __syncthreads();
    uint32_t* dst = g_Vt + (size_t)img * E * VTW;
    for (int idx = threadIdx.x; idx < E * VTW; idx += 256) {
        int e = idx / VTW, kw = idx % VTW;
        int k0 = kw * 2, k1 = kw * 2 + 1;
        float v0 = (k0 < S) ? sm[e][k0] : 0.f;
        float v1 = (k1 < S) ? sm[e][k1] : 0.f;
        dst[idx] = pack_bf16x2(v0, v1);
    }
}

// ---------------- GEMM1 bf16 (all 3 chains): Hb_z = bf16(relu(Xb @ W1_z)) ----------------
__global__ __launch_bounds__(256) void gemm1_relu_bf16() {
    int z = blockIdx.z;
    const uint32_t* B = g_W1b + (size_t)z * C * CW;
    uint32_t* Hout = g_Hb + (size_t)z * RTOT * CW;

    __shared__ uint32_t sA[2][128][20];
    __shared__ uint32_t sB[2][128][20];

    int tid = threadIdx.x;
    int w = tid >> 5, lane = tid & 31;
    int g = lane >> 2, tig = lane & 3;
    int warpM = w >> 2, warpN = w & 3;
    int mW = warpM * 64, nW = warpN * 32;
    int m0 = blockIdx.y * 128, n0 = blockIdx.x * 128;

    int row = tid >> 1, wd = (tid & 1) * 8;
    const uint32_t* Aptr = g_Xb + (size_t)(m0 + row) * CW + wd;
    const uint32_t* Bptr = B + (size_t)(n0 + row) * CW + wd;

    float acc[4][4][4];
#pragma unroll
    for (int i = 0; i < 4; i++)
#pragma unroll
        for (int j = 0; j < 4; j++)
#pragma unroll
            for (int k = 0; k < 4; k++) acc[i][j][k] = 0.f;

    uint4 ra0, ra1, rb0, rb1;
    ra0 = *(const uint4*)Aptr;     ra1 = *(const uint4*)(Aptr + 4);
    rb0 = *(const uint4*)Bptr;     rb1 = *(const uint4*)(Bptr + 4);
    *(uint4*)&sA[0][row][wd]     = ra0;
    *(uint4*)&sA[0][row][wd + 4] = ra1;
    *(uint4*)&sB[0][row][wd]     = rb0;
    *(uint4*)&sB[0][row][wd + 4] = rb1;
    __syncthreads();

    const int NT = C / 32;  // 24
    for (int t = 0; t < NT; t++) {
        int buf = t & 1;
        if (t < NT - 1) {
            const uint32_t* Ap = Aptr + (t + 1) * 16;
            const uint32_t* Bp = Bptr + (t + 1) * 16;
            ra0 = *(const uint4*)Ap; ra1 = *(const uint4*)(Ap + 4);
            rb0 = *(const uint4*)Bp; rb1 = *(const uint4*)(Bp + 4);
        }
#pragma unroll
        for (int ks = 0; ks < 16; ks += 8) {
            uint32_t afr[4][4];
#pragma unroll
            for (int mt = 0; mt < 4; mt++) {
                int r = mW + mt * 16 + g;
                afr[mt][0] = sA[buf][r    ][ks + tig];
                afr[mt][1] = sA[buf][r + 8][ks + tig];
                afr[mt][2] = sA[buf][r    ][ks + tig + 4];
                afr[mt][3] = sA[buf][r + 8][ks + tig + 4];
            }
            uint32_t bfr[4][2];
#pragma unroll
            for (int nt = 0; nt < 4; nt++) {
                int nc = nW + nt * 8 + g;
                bfr[nt][0] = sB[buf][nc][ks + tig];
                bfr[nt][1] = sB[buf][nc][ks + tig + 4];
            }
#pragma unroll
            for (int mt = 0; mt < 4; mt++)
#pragma unroll
                for (int nt = 0; nt < 4; nt++)
                    mma_bf16(acc[mt][nt], afr[mt][0], afr[mt][1], afr[mt][2], afr[mt][3],
                             bfr[nt][0], bfr[nt][1]);
        }
        if (t < NT - 1) {
            int nb = buf ^ 1;
            *(uint4*)&sA[nb][row][wd]     = ra0;
            *(uint4*)&sA[nb][row][wd + 4] = ra1;
            *(uint4*)&sB[nb][row][wd]     = rb0;
            *(uint4*)&sB[nb][row][wd + 4] = rb1;
            __syncthreads();
        }
    }

#pragma unroll
    for (int mt = 0; mt < 4; mt++) {
        int r = m0 + mW + mt * 16 + g;
#pragma unroll
        for (int nt = 0; nt < 4; nt++) {
            int cw = (n0 + nW) / 2 + nt * 4 + tig;
            float p0 = fmaxf(acc[mt][nt][0], 0.f), p1 = fmaxf(acc[mt][nt][1], 0.f);
            float p2 = fmaxf(acc[mt][nt][2], 0.f), p3 = fmaxf(acc[mt][nt][3], 0.f);
            Hout[(size_t)r * CW + cw]       = pack_bf16x2(p0, p1);
            Hout[(size_t)(r + 8) * CW + cw] = pack_bf16x2(p2, p3);
        }
    }
}

// ---------------- GEMM2 bf16 (all 3): Q,K -> bf16x2; V -> fp32 ----------------
__global__ __launch_bounds__(256) void gemm2_bf16() {
    int z = blockIdx.z;
    const uint32_t* A = g_Hb + (size_t)z * RTOT * CW;
    const uint32_t* B = g_W2b + (size_t)z * E * CW;

    __shared__ uint32_t sA[2][64][20];
    __shared__ uint32_t sB[2][96][20];

    int tid = threadIdx.x;
    int w = tid >> 5, lane = tid & 31;
    int g = lane >> 2, tig = lane & 3;
    int warpM = w >> 2, warpN = w & 3;
    int mW = warpM * 32, nW = warpN * 24;
    int m0 = blockIdx.y * 64;

    int arow = tid >> 2, aw = (tid & 3) * 4;
    const uint32_t* Aptr = A + (size_t)(m0 + arow) * CW + aw;
    int bi0 = tid, bi1 = tid + 256;
    int br0 = bi0 >> 2, bw0 = (bi0 & 3) * 4;
    int br1 = bi1 >> 2, bw1 = (bi1 & 3) * 4;
    bool hb1 = (bi1 < 384);

    float acc[2][3][4];
#pragma unroll
    for (int i = 0; i < 2; i++)
#pragma unroll
        for (int j = 0; j < 3; j++)
#pragma unroll
            for (int k = 0; k < 4; k++) acc[i][j][k] = 0.f;

    uint4 pa, pb0, pb1;
    *(uint4*)&sA[0][arow][aw] = *(const uint4*)Aptr;
    *(uint4*)&sB[0][br0][bw0] = *(const uint4*)&B[(size_t)br0 * CW + bw0];
    if (hb1) *(uint4*)&sB[0][br1][bw1] = *(const uint4*)&B[(size_t)br1 * CW + bw1];
    __syncthreads();

    const int NT = C / 32;  // 24
    for (int t = 0; t < NT; t++) {
        int buf = t & 1;
        if (t < NT - 1) {
            int kt = (t + 1) * 16;
            pa  = *(const uint4*)(Aptr + kt);
            pb0 = *(const uint4*)&B[(size_t)br0 * CW + kt + bw0];
            if (hb1) pb1 = *(const uint4*)&B[(size_t)br1 * CW + kt + bw1];
        }
#pragma unroll
        for (int ks = 0; ks < 16; ks += 8) {
            uint32_t afr[2][4];
#pragma unroll
            for (int mt = 0; mt < 2; mt++) {
                int r = mW + mt * 16 + g;
                afr[mt][0] = sA[buf][r    ][ks + tig];
                afr[mt][1] = sA[buf][r + 8][ks + tig];
                afr[mt][2] = sA[buf][r    ][ks + tig + 4];
                afr[mt][3] = sA[buf][r + 8][ks + tig + 4];
            }
#pragma unroll
            for (int nt = 0; nt < 3; nt++) {
                int nc = nW + nt * 8 + g;
                uint32_t b0 = sB[buf][nc][ks + tig];
                uint32_t b1 = sB[buf][nc][ks + tig + 4];
#pragma unroll
                for (int mt = 0; mt < 2; mt++)
                    mma_bf16(acc[mt][nt], afr[mt][0], afr[mt][1], afr[mt][2], afr[mt][3], b0, b1);
            }
        }
        if (t < NT - 1) {
            int nb = buf ^ 1;
            *(uint4*)&sA[nb][arow][aw] = pa;
            *(uint4*)&sB[nb][br0][bw0] = pb0;
            if (hb1) *(uint4*)&sB[nb][br1][bw1] = pb1;
            __syncthreads();
        }
    }

#pragma unroll
    for (int mt = 0; mt < 2; mt++) {
        int r = m0 + mW + mt * 16 + g;
#pragma unroll
        for (int nt = 0; nt < 3; nt++) {
            if (z < 2) {
                uint32_t* O = z ? g_Kb : g_Qb;
                int cw = nW / 2 + nt * 4 + tig;
                O[(size_t)r * (E / 2) + cw]       = pack_bf16x2(acc[mt][nt][0], acc[mt][nt][1]);
                O[(size_t)(r + 8) * (E / 2) + cw] = pack_bf16x2(acc[mt][nt][2], acc[mt][nt][3]);
            } else {
                int cc = nW + nt * 8 + tig * 2;
                float2 lo, hi;
                lo.x = acc[mt][nt][0]; lo.y = acc[mt][nt][1];
                hi.x = acc[mt][nt][2]; hi.y = acc[mt][nt][3];
                *(float2*)&g_V[(size_t)r * E + cc]       = lo;
                *(float2*)&g_V[(size_t)(r + 8) * E + cc] = hi;
            }
        }
    }
}

// ---------------- pair kernel: bf16 TC attention, softmax-free ----------------
__global__ __launch_bounds__(256, 3) void pair_tc(float* __restrict__ out) {
    extern __shared__ uint32_t smbuf[];
    uint32_t* uQ   = smbuf;
    uint32_t* uK   = uQ + S * QS;
    uint32_t* uVt  = uK + S * QS;
    float*    wsum = (float*)(uVt + E * PS);
    uint32_t* uP   = uQ;
    float*    part = (float*)uK;

    int a = blockIdx.x, b = blockIdx.y;
    int tid = threadIdx.x, w = tid >> 5, lane = tid & 31;
    int g = lane >> 2, tig = lane & 3;
    const float scale = 0.10206207261596577f;

    int mt = w >> 1, half = w & 1;
    int raQ = mt * 16 + g;
    int ntBeg = half * 4;
    int ntCnt = half ? 3 : 4;

    float res0 = 0.f, res1 = 0.f;

#pragma unroll 1
    for (int dir = 0; dir < 2; dir++) {
        int qi = dir ? a : (NB + b);
        int ki = dir ? (NB + b) : a;

        {
            const uint32_t* q = g_Qb + (size_t)qi * S * (E/2);
            const uint32_t* k = g_Kb + (size_t)ki * S * (E/2);
            for (int idx = tid; idx < S * 12; idx += 256) {
                int r = idx / 12, c4 = (idx % 12) * 4;
                *(uint4*)&uQ[r * QS + c4] = *(const uint4*)&q[r * (E/2) + c4];
                *(uint4*)&uK[r * QS + c4] = *(const uint4*)&k[r * (E/2) + c4];
            }
            const uint32_t* vt = g_Vt + (size_t)ki * E * VTW;
            for (int idx = tid; idx < E * 8; idx += 256) {
                int r = idx / 8, c4 = (idx % 8) * 4;
                *(uint4*)&uVt[r * PS + c4] = *(const uint4*)&vt[r * VTW + c4];
            }
        }
        __syncthreads();

        float sc[4][4];
        {
#pragma unroll
            for (int i = 0; i < 4; i++)
#pragma unroll
                for (int j = 0; j < 4; j++) sc[i][j] = 0.f;
#pragma unroll
            for (int kk = 0; kk < 6; kk++) {
                int kw = kk * 8;
                uint32_t a0 = uQ[raQ * QS + kw + tig];
                uint32_t a1 = uQ[(raQ + 8) * QS + kw + tig];
                uint32_t a2 = uQ[raQ * QS + kw + tig + 4];
                uint32_t a3 = uQ[(raQ + 8) * QS + kw + tig + 4];
#pragma unroll
                for (int n2 = 0; n2 < 4; n2++) {
                    if (n2 < ntCnt) {
                        int nc = (ntBeg + n2) * 8 + g;
                        uint32_t b0 = uK[nc * QS + kw + tig];
                        uint32_t b1 = uK[nc * QS + kw + tig + 4];
                        mma_bf16(sc[n2], a0, a1, a2, a3, b0, b1);
                    }
                }
            }
        }
        __syncthreads();

        {
#pragma unroll
            for (int n2 = 0; n2 < 4; n2++) {
                if (n2 < ntCnt) {
                    int nt = ntBeg + n2;
                    int wd = nt * 4 + tig;
                    float p0 = __expf(fminf(sc[n2][0] * scale, 40.f));
                    float p1 = __expf(fminf(sc[n2][1] * scale, 40.f));
                    float p2 = __expf(fminf(sc[n2][2] * scale, 40.f));
                    float p3 = __expf(fminf(sc[n2][3] * scale, 40.f));
                    int c0 = wd * 2, c1 = wd * 2 + 1;
                    if (c0 >= S) { p0 = 0.f; p2 = 0.f; }
                    if (c1 >= S) { p1 = 0.f; p3 = 0.f; }
                    uP[raQ * PS + wd]       = pack_bf16x2(p0, p1);
                    uP[(raQ + 8) * PS + wd] = pack_bf16x2(p2, p3);
                }
            }
            if (half == 1) {
                uP[raQ * PS + 28 + tig]       = 0u;
                uP[(raQ + 8) * PS + 28 + tig] = 0u;
            }
        }
        __syncthreads();

        {
            float alc[6][4];
#pragma unroll
            for (int i = 0; i < 6; i++)
#pragma unroll
                for (int j = 0; j < 4; j++) alc[i][j] = 0.f;
            int etBeg = half * 6;
#pragma unroll
            for (int kk = 0; kk < 4; kk++) {
                int kw = kk * 8;
                uint32_t a0 = uP[raQ * PS + kw + tig];
                uint32_t a1 = uP[(raQ + 8) * PS + kw + tig];
                uint32_t a2 = uP[raQ * PS + kw + tig + 4];
                uint32_t a3 = uP[(raQ + 8) * PS + kw + tig + 4];
#pragma unroll
                for (int e = 0; e < 6; e++) {
                    int nc = (etBeg + e) * 8 + g;
                    uint32_t b0 = uVt[nc * PS + kw + tig];
                    uint32_t b1 = uVt[nc * PS + kw + tig + 4];
                    mma_bf16(alc[e], a0, a1, a2, a3, b0, b1);
                }
            }

            const float* vref = g_V + (size_t)qi * S * E;
            int r0 = raQ, r1 = raQ + 8;
            bool ok0 = (r0 < S), ok1 = (r1 < S);
            float n0 = 0.f, d0 = 0.f, c0 = 0.f;
            float n1 = 0.f, d1 = 0.f, c1 = 0.f;
#pragma unroll
            for (int e = 0; e < 6; e++) {
                int col = (etBeg + e) * 8 + tig * 2;
                if (ok0) {
                    float2 vc = *(const float2*)&vref[r0 * E + col];
                    n0 += alc[e][0] * vc.x + alc[e][1] * vc.y;
                    d0 += alc[e][0] * alc[e][0] + alc[e][1] * alc[e][1];
                    c0 += vc.x * vc.x + vc.y * vc.y;
                }
                if (ok1) {
                    float2 vc = *(const float2*)&vref[r1 * E + col];
                    n1 += alc[e][2] * vc.x + alc[e][3] * vc.y;
                    d1 += alc[e][2] * alc[e][2] + alc[e][3] * alc[e][3];
                    c1 += vc.x * vc.x + vc.y * vc.y;
                }
            }
#pragma unroll
            for (int o = 1; o <= 2; o <<= 1) {
                n0 += __shfl_xor_sync(0xffffffffu, n0, o);
                d0 += __shfl_xor_sync(0xffffffffu, d0, o);
                c0 += __shfl_xor_sync(0xffffffffu, c0, o);
                n1 += __shfl_xor_sync(0xffffffffu, n1, o);
                d1 += __shfl_xor_sync(0xffffffffu, d1, o);
                c1 += __shfl_xor_sync(0xffffffffu, c1, o);
            }
            if (tig == 0) {
                if (ok0) {
                    part[r0 * 8 + half * 3 + 0] = n0;
                    part[r0 * 8 + half * 3 + 1] = d0;
                    part[r0 * 8 + half * 3 + 2] = c0;
                }
                if (ok1) {
                    part[r1 * 8 + half * 3 + 0] = n1;
                    part[r1 * 8 + half * 3 + 1] = d1;
                    part[r1 * 8 + half * 3 + 2] = c1;
                }
            }
        }
        __syncthreads();

        {
            float cosv = 0.f;
            if (tid < S) {
                const float* p = &part[tid * 8];
                float num = p[0] + p[3];
                float da  = p[1] + p[4];
                float dc  = p[2] + p[5];
                float na = fmaxf(sqrtf(da), EPSC);
                float nc = fmaxf(sqrtf(dc), EPSC);
                cosv = num / (na * nc);
            }
#pragma unroll
            for (int o = 16; o; o >>= 1) cosv += __shfl_xor_sync(0xffffffffu, cosv, o);
            if (lane == 0) wsum[w] = cosv;
        }
        __syncthreads();
        if (tid == 0) {
            float tot = wsum[0] + wsum[1];
            if (dir == 0) res0 = tot; else res1 = tot;
        }
        __syncthreads();
    }
    if (tid == 0) out[b * NB + a] = (res0 + res1) * (1.0f / S);
}

// ---------------- launch ----------------
extern "C" void kernel_launch(void* const* d_in, const int* in_sizes, int n_in,
                              void* d_out, int out_size) {
    const float* fa  = (const float*)d_in[0];
    const float* fb  = (const float*)d_in[1];
    const float* Wq1 = (const float*)d_in[2];
    const float* Wq2 = (const float*)d_in[3];
    const float* Wk1 = (const float*)d_in[4];
    const float* Wk2 = (const float*)d_in[5];
    const float* Wv1 = (const float*)d_in[6];
    const float* Wv2 = (const float*)d_in[7];
    float* out = (float*)d_out;

    void *pW1b, *pW2b;
    cudaGetSymbolAddress(&pW1b, g_W1b);
    cudaGetSymbolAddress(&pW2b, g_W2b);

    const int smem_pair = (S * QS * 2 + E * PS + 8) * (int)sizeof(uint32_t);  // ~34.2 KB
    cudaFuncSetAttribute(pair_tc, cudaFuncAttributeMaxDynamicSharedMemorySize, smem_pair);

    transpose_kernel<<<dim3(24, 128, 2), 256>>>(fa, fb);
    convwb<<<dim3(24, 24, 3), 256>>>(Wq1, Wk1, Wv1, (uint32_t*)pW1b, C, (size_t)C * CW);
    convwb<<<dim3(24, 3, 3), 256>>>(Wq2, Wk2, Wv2, (uint32_t*)pW2b, E, (size_t)E * CW);

    gemm1_relu_bf16<<<dim3(C / 128, RTOT / 128, 3), 256>>>();
    gemm2_bf16<<<dim3(1, RTOT / 64, 3), 256>>>();

    vtrans_kernel<<<2 * NB, 256>>>();

    pair_tc<<<dim3(NB, NB), 256, smem_pair>>>(out);
}

// round 14
// speedup vs baseline: 6.0364x; 1.0468x over previous
#include <cuda_runtime.h>
#include <math.h>
#include <stdint.h>

#define NB 128
#define S  49
#define C  768
#define CW (C/2)   // 384 packed bf16x2 words
#define E  96
#define RTOT (2*NB*S)   // 12544
#define EPSC 1e-8f

#define QS 52    // pair Q/K smem stride (words)
#define PS 36    // pair P / Vt stride
#define VTW 32   // g_Vt words per row

// ---------------- scratch ----------------
__device__ uint32_t g_Xb [(size_t)RTOT * CW];       // bf16x2 features
__device__ uint32_t g_Hb [(size_t)3 * RTOT * CW];   // bf16x2 hidden (q,k,v)
__device__ uint32_t g_Qb [(size_t)RTOT * (E/2)];    // bf16x2 Q
__device__ uint32_t g_Kb [(size_t)RTOT * (E/2)];    // bf16x2 K
__device__ float    g_V  [(size_t)RTOT * E];        // fp32 V (cosine ref values)
__device__ uint32_t g_Vt [(size_t)2 * NB * E * VTW];// bf16x2 V-transposed
__device__ uint32_t g_W1b[(size_t)3 * C * CW];      // bf16x2 W1{q,k,v} transposed [n][kw]
__device__ uint32_t g_W2b[(size_t)3 * E * CW];      // bf16x2 W2{q,k,v} transposed [n][kw]

// ---------------- helpers ----------------
__device__ __forceinline__ uint32_t pack_bf16x2(float lo, float hi) {
    uint32_t r; asm("cvt.rn.bf16x2.f32 %0, %1, %2;" : "=r"(r) : "f"(hi), "f"(lo)); return r;
}
__device__ __forceinline__ void mma_bf16(float c[4], uint32_t a0, uint32_t a1, uint32_t a2, uint32_t a3,
                                         uint32_t b0, uint32_t b1) {
    asm volatile("mma.sync.aligned.m16n8k16.row.col.f32.bf16.bf16.f32 "
                 "{%0,%1,%2,%3}, {%4,%5,%6,%7}, {%8,%9}, {%0,%1,%2,%3};"
                 : "+f"(c[0]), "+f"(c[1]), "+f"(c[2]), "+f"(c[3])
                 : "r"(a0), "r"(a1), "r"(a2), "r"(a3), "r"(b0), "r"(b1));
}

// ---------------- transpose: [B,C,S] -> Xb[row][kw] (bf16x2) ----------------
__global__ __launch_bounds__(256) void transpose_kernel(const float* __restrict__ fa,
                                                        const float* __restrict__ fb) {
    __shared__ float t[32][S + 1];
    int ct = blockIdx.x, b = blockIdx.y, set = blockIdx.z;
    const float* F = set ? fb : fa;
    int c0 = ct * 32;
    const float* src = F + ((size_t)b * C + c0) * S;
    for (int idx = threadIdx.x; idx < 32 * S; idx += blockDim.x) {
        int i = idx / S, s = idx % S;
        t[i][s] = src[i * S + s];
    }
    __syncthreads();
    int rowbase = set * NB * S + b * S;
    for (int idx = threadIdx.x; idx < S * 16; idx += blockDim.x) {
        int s = idx >> 4, i2 = idx & 15;
        g_Xb[(size_t)(rowbase + s) * CW + (c0 >> 1) + i2] = pack_bf16x2(t[2 * i2][s], t[2 * i2 + 1][s]);
    }
}

// ---------------- weights -> bf16x2 transposed [n][kw] ----------------
__global__ __launch_bounds__(256) void convwb(const float* __restrict__ Wa, const float* __restrict__ Wb,
                                              const float* __restrict__ Wc,
                                              uint32_t* __restrict__ dstBase, int N, size_t zstride) {
    const float* W = (blockIdx.z == 0) ? Wa : (blockIdx.z == 1) ? Wb : Wc;
    uint32_t* d = dstBase + blockIdx.z * zstride;
    int k0 = blockIdx.x * 32, n0 = blockIdx.y * 32;
    __shared__ float sm[32][33];
    for (int idx = threadIdx.x; idx < 1024; idx += 256) {
        int i = idx >> 5, j = idx & 31;
        sm[i][j] = W[(size_t)(k0 + i) * N + n0 + j];
    }
    __syncthreads();
    for (int idx = threadIdx.x; idx < 512; idx += 256) {
        int j = idx >> 4, i2 = idx & 15;
        d[(size_t)(n0 + j) * CW + (k0 >> 1) + i2] = pack_bf16x2(sm[2 * i2][j], sm[2 * i2 + 1][j]);
    }
}

// ---------------- V transpose per image -> bf16x2 along k ----------------
__global__ __launch_bounds__(256) void vtrans_kernel() {
    __shared__ float sm[E][S + 1];
    int img = blockIdx.x;
    const float* src = g_V + (size_t)img * S * E;
    for (int idx = threadIdx.x; idx < S * E; idx += 256) {
        int k = idx / E, e = idx % E;
        sm[e][k] = src[idx];
    }
    __syncthreads();
    uint32_t* dst = g_Vt + (size_t)img * E * VTW;
    for (int idx = threadIdx.x; idx < E * VTW; idx += 256) {
        int e = idx / VTW, kw = idx % VTW;
        int k0 = kw * 2, k1 = kw * 2 + 1;
        float v0 = (k0 < S) ? sm[e][k0] : 0.f;
        float v1 = (k1 < S) ? sm[e][k1] : 0.f;
        dst[idx] = pack_bf16x2(v0, v1);
    }
}

// ---------------- GEMM1 bf16 (all 3 chains): Hb_z = bf16(relu(Xb @ W1_z)) ----------------
__global__ __launch_bounds__(256) void gemm1_relu_bf16() {
    int z = blockIdx.z;
    const uint32_t* B = g_W1b + (size_t)z * C * CW;
    uint32_t* Hout = g_Hb + (size_t)z * RTOT * CW;

    __shared__ uint32_t sA[2][128][20];
    __shared__ uint32_t sB[2][128][20];

    int tid = threadIdx.x;
    int w = tid >> 5, lane = tid & 31;
    int g = lane >> 2, tig = lane & 3;
    int warpM = w >> 2, warpN = w & 3;
    int mW = warpM * 64, nW = warpN * 32;
    int m0 = blockIdx.y * 128, n0 = blockIdx.x * 128;

    int row = tid >> 1, wd = (tid & 1) * 8;
    const uint32_t* Aptr = g_Xb + (size_t)(m0 + row) * CW + wd;
    const uint32_t* Bptr = B + (size_t)(n0 + row) * CW + wd;

    float acc[4][4][4];
#pragma unroll
    for (int i = 0; i < 4; i++)
#pragma unroll
        for (int j = 0; j < 4; j++)
#pragma unroll
            for (int k = 0; k < 4; k++) acc[i][j][k] = 0.f;

    uint4 ra0, ra1, rb0, rb1;
    ra0 = *(const uint4*)Aptr;     ra1 = *(const uint4*)(Aptr + 4);
    rb0 = *(const uint4*)Bptr;     rb1 = *(const uint4*)(Bptr + 4);
    *(uint4*)&sA[0][row][wd]     = ra0;
    *(uint4*)&sA[0][row][wd + 4] = ra1;
    *(uint4*)&sB[0][row][wd]     = rb0;
    *(uint4*)&sB[0][row][wd + 4] = rb1;
    __syncthreads();

    const int NT = C / 32;  // 24
    for (int t = 0; t < NT; t++) {
        int buf = t & 1;
        if (t < NT - 1) {
            const uint32_t* Ap = Aptr + (t + 1) * 16;
            const uint32_t* Bp = Bptr + (t + 1) * 16;
            ra0 = *(const uint4*)Ap; ra1 = *(const uint4*)(Ap + 4);
            rb0 = *(const uint4*)Bp; rb1 = *(const uint4*)(Bp + 4);
        }
#pragma unroll
        for (int ks = 0; ks < 16; ks += 8) {
            uint32_t afr[4][4];
#pragma unroll
            for (int mt = 0; mt < 4; mt++) {
                int r = mW + mt * 16 + g;
                afr[mt][0] = sA[buf][r    ][ks + tig];
                afr[mt][1] = sA[buf][r + 8][ks + tig];
                afr[mt][2] = sA[buf][r    ][ks + tig + 4];
                afr[mt][3] = sA[buf][r + 8][ks + tig + 4];
            }
            uint32_t bfr[4][2];
#pragma unroll
            for (int nt = 0; nt < 4; nt++) {
                int nc = nW + nt * 8 + g;
                bfr[nt][0] = sB[buf][nc][ks + tig];
                bfr[nt][1] = sB[buf][nc][ks + tig + 4];
            }
#pragma unroll
            for (int mt = 0; mt < 4; mt++)
#pragma unroll
                for (int nt = 0; nt < 4; nt++)
                    mma_bf16(acc[mt][nt], afr[mt][0], afr[mt][1], afr[mt][2], afr[mt][3],
                             bfr[nt][0], bfr[nt][1]);
        }
        if (t < NT - 1) {
            int nb = buf ^ 1;
            *(uint4*)&sA[nb][row][wd]     = ra0;
            *(uint4*)&sA[nb][row][wd + 4] = ra1;
            *(uint4*)&sB[nb][row][wd]     = rb0;
            *(uint4*)&sB[nb][row][wd + 4] = rb1;
            __syncthreads();
        }
    }

#pragma unroll
    for (int mt = 0; mt < 4; mt++) {
        int r = m0 + mW + mt * 16 + g;
#pragma unroll
        for (int nt = 0; nt < 4; nt++) {
            int cw = (n0 + nW) / 2 + nt * 4 + tig;
            float p0 = fmaxf(acc[mt][nt][0], 0.f), p1 = fmaxf(acc[mt][nt][1], 0.f);
            float p2 = fmaxf(acc[mt][nt][2], 0.f), p3 = fmaxf(acc[mt][nt][3], 0.f);
            Hout[(size_t)r * CW + cw]       = pack_bf16x2(p0, p1);
            Hout[(size_t)(r + 8) * CW + cw] = pack_bf16x2(p2, p3);
        }
    }
}

// ---------------- GEMM2 bf16 (all 3): Q,K -> bf16x2; V -> fp32 ----------------
__global__ __launch_bounds__(256) void gemm2_bf16() {
    int z = blockIdx.z;
    const uint32_t* A = g_Hb + (size_t)z * RTOT * CW;
    const uint32_t* B = g_W2b + (size_t)z * E * CW;

    __shared__ uint32_t sA[2][64][20];
    __shared__ uint32_t sB[2][96][20];

    int tid = threadIdx.x;
    int w = tid >> 5, lane = tid & 31;
    int g = lane >> 2, tig = lane & 3;
    int warpM = w >> 2, warpN = w & 3;
    int mW = warpM * 32, nW = warpN * 24;
    int m0 = blockIdx.y * 64;

    int arow = tid >> 2, aw = (tid & 3) * 4;
    const uint32_t* Aptr = A + (size_t)(m0 + arow) * CW + aw;
    int bi0 = tid, bi1 = tid + 256;
    int br0 = bi0 >> 2, bw0 = (bi0 & 3) * 4;
    int br1 = bi1 >> 2, bw1 = (bi1 & 3) * 4;
    bool hb1 = (bi1 < 384);

    float acc[2][3][4];
#pragma unroll
    for (int i = 0; i < 2; i++)
#pragma unroll
        for (int j = 0; j < 3; j++)
#pragma unroll
            for (int k = 0; k < 4; k++) acc[i][j][k] = 0.f;

    uint4 pa, pb0, pb1;
    *(uint4*)&sA[0][arow][aw] = *(const uint4*)Aptr;
    *(uint4*)&sB[0][br0][bw0] = *(const uint4*)&B[(size_t)br0 * CW + bw0];
    if (hb1) *(uint4*)&sB[0][br1][bw1] = *(const uint4*)&B[(size_t)br1 * CW + bw1];
    __syncthreads();

    const int NT = C / 32;  // 24
    for (int t = 0; t < NT; t++) {
        int buf = t & 1;
        if (t < NT - 1) {
            int kt = (t + 1) * 16;
            pa  = *(const uint4*)(Aptr + kt);
            pb0 = *(const uint4*)&B[(size_t)br0 * CW + kt + bw0];
            if (hb1) pb1 = *(const uint4*)&B[(size_t)br1 * CW + kt + bw1];
        }
#pragma unroll
        for (int ks = 0; ks < 16; ks += 8) {
            uint32_t afr[2][4];
#pragma unroll
            for (int mt = 0; mt < 2; mt++) {
                int r = mW + mt * 16 + g;
                afr[mt][0] = sA[buf][r    ][ks + tig];
                afr[mt][1] = sA[buf][r + 8][ks + tig];
                afr[mt][2] = sA[buf][r    ][ks + tig + 4];
                afr[mt][3] = sA[buf][r + 8][ks + tig + 4];
            }
#pragma unroll
            for (int nt = 0; nt < 3; nt++) {
                int nc = nW + nt * 8 + g;
                uint32_t b0 = sB[buf][nc][ks + tig];
                uint32_t b1 = sB[buf][nc][ks + tig + 4];
#pragma unroll
                for (int mt = 0; mt < 2; mt++)
                    mma_bf16(acc[mt][nt], afr[mt][0], afr[mt][1], afr[mt][2], afr[mt][3], b0, b1);
            }
        }
        if (t < NT - 1) {
            int nb = buf ^ 1;
            *(uint4*)&sA[nb][arow][aw] = pa;
            *(uint4*)&sB[nb][br0][bw0] = pb0;
            if (hb1) *(uint4*)&sB[nb][br1][bw1] = pb1;
            __syncthreads();
        }
    }

#pragma unroll
    for (int mt = 0; mt < 2; mt++) {
        int r = m0 + mW + mt * 16 + g;
#pragma unroll
        for (int nt = 0; nt < 3; nt++) {
            if (z < 2) {
                uint32_t* O = z ? g_Kb : g_Qb;
                int cw = nW / 2 + nt * 4 + tig;
                O[(size_t)r * (E / 2) + cw]       = pack_bf16x2(acc[mt][nt][0], acc[mt][nt][1]);
                O[(size_t)(r + 8) * (E / 2) + cw] = pack_bf16x2(acc[mt][nt][2], acc[mt][nt][3]);
            } else {
                int cc = nW + nt * 8 + tig * 2;
                float2 lo, hi;
                lo.x = acc[mt][nt][0]; lo.y = acc[mt][nt][1];
                hi.x = acc[mt][nt][2]; hi.y = acc[mt][nt][3];
                *(float2*)&g_V[(size_t)r * E + cc]       = lo;
                *(float2*)&g_V[(size_t)(r + 8) * E + cc] = hi;
            }
        }
    }
}

// ---------------- pair-kernel helpers (inlined; per-warp tile roles) ----------------
__device__ __forceinline__ void score_tiles(const uint32_t* uQ, const uint32_t* uK,
                                            float sc[4][4], int raQ, int ntBeg, int ntCnt,
                                            int g, int tig) {
#pragma unroll
    for (int i = 0; i < 4; i++)
#pragma unroll
        for (int j = 0; j < 4; j++) sc[i][j] = 0.f;
#pragma unroll
    for (int kk = 0; kk < 6; kk++) {
        int kw = kk * 8;
        uint32_t a0 = uQ[raQ * QS + kw + tig];
        uint32_t a1 = uQ[(raQ + 8) * QS + kw + tig];
        uint32_t a2 = uQ[raQ * QS + kw + tig + 4];
        uint32_t a3 = uQ[(raQ + 8) * QS + kw + tig + 4];
#pragma unroll
        for (int n2 = 0; n2 < 4; n2++) {
            if (n2 < ntCnt) {
                int nc = (ntBeg + n2) * 8 + g;
                uint32_t b0 = uK[nc * QS + kw + tig];
                uint32_t b1 = uK[nc * QS + kw + tig + 4];
                mma_bf16(sc[n2], a0, a1, a2, a3, b0, b1);
            }
        }
    }
}

__device__ __forceinline__ void exp_write(const float sc[4][4], uint32_t* uP,
                                          int raQ, int ntBeg, int ntCnt, int tig, int half) {
    const float scale = 0.10206207261596577f;  // 1/sqrt(96)
#pragma unroll
    for (int n2 = 0; n2 < 4; n2++) {
        if (n2 < ntCnt) {
            int nt = ntBeg + n2;
            int wd = nt * 4 + tig;
            float p0 = __expf(fminf(sc[n2][0] * scale, 40.f));
            float p1 = __expf(fminf(sc[n2][1] * scale, 40.f));
            float p2 = __expf(fminf(sc[n2][2] * scale, 40.f));
            float p3 = __expf(fminf(sc[n2][3] * scale, 40.f));
            int c0 = wd * 2, c1 = wd * 2 + 1;
            if (c0 >= S) { p0 = 0.f; p2 = 0.f; }
            if (c1 >= S) { p1 = 0.f; p3 = 0.f; }
            uP[raQ * PS + wd]       = pack_bf16x2(p0, p1);
            uP[(raQ + 8) * PS + wd] = pack_bf16x2(p2, p3);
        }
    }
    if (half == 1) {   // zero words 28..31 (K-cols 56..63) never covered by nt tiles
        uP[raQ * PS + 28 + tig]       = 0u;
        uP[(raQ + 8) * PS + 28 + tig] = 0u;
    }
}

__device__ __forceinline__ void pv_cos(const uint32_t* uP, const uint32_t* uVt,
                                       const float* __restrict__ vref, float* part,
                                       int raQ, int half, int g, int tig) {
    float alc[6][4];
#pragma unroll
    for (int i = 0; i < 6; i++)
#pragma unroll
        for (int j = 0; j < 4; j++) alc[i][j] = 0.f;
    int etBeg = half * 6;
#pragma unroll
    for (int kk = 0; kk < 4; kk++) {
        int kw = kk * 8;
        uint32_t a0 = uP[raQ * PS + kw + tig];
        uint32_t a1 = uP[(raQ + 8) * PS + kw + tig];
        uint32_t a2 = uP[raQ * PS + kw + tig + 4];
        uint32_t a3 = uP[(raQ + 8) * PS + kw + tig + 4];
#pragma unroll
        for (int e = 0; e < 6; e++) {
            int nc = (etBeg + e) * 8 + g;
            uint32_t b0 = uVt[nc * PS + kw + tig];
            uint32_t b1 = uVt[nc * PS + kw + tig + 4];
            mma_bf16(alc[e], a0, a1, a2, a3, b0, b1);
        }
    }

    int r0 = raQ, r1 = raQ + 8;
    bool ok0 = (r0 < S), ok1 = (r1 < S);
    float n0 = 0.f, d0 = 0.f, c0 = 0.f;
    float n1 = 0.f, d1 = 0.f, c1 = 0.f;
#pragma unroll
    for (int e = 0; e < 6; e++) {
        int col = (etBeg + e) * 8 + tig * 2;
        if (ok0) {
            float2 vc = *(const float2*)&vref[r0 * E + col];
            n0 += alc[e][0] * vc.x + alc[e][1] * vc.y;
            d0 += alc[e][0] * alc[e][0] + alc[e][1] * alc[e][1];
            c0 += vc.x * vc.x + vc.y * vc.y;
        }
        if (ok1) {
            float2 vc = *(const float2*)&vref[r1 * E + col];
            n1 += alc[e][2] * vc.x + alc[e][3] * vc.y;
            d1 += alc[e][2] * alc[e][2] + alc[e][3] * alc[e][3];
            c1 += vc.x * vc.x + vc.y * vc.y;
        }
    }
#pragma unroll
    for (int o = 1; o <= 2; o <<= 1) {
        n0 += __shfl_xor_sync(0xffffffffu, n0, o);
        d0 += __shfl_xor_sync(0xffffffffu, d0, o);
        c0 += __shfl_xor_sync(0xffffffffu, c0, o);
        n1 += __shfl_xor_sync(0xffffffffu, n1, o);
        d1 += __shfl_xor_sync(0xffffffffu, d1, o);
        c1 += __shfl_xor_sync(0xffffffffu, c1, o);
    }
    if (tig == 0) {
        if (ok0) {
            part[r0 * 8 + half * 3 + 0] = n0;
            part[r0 * 8 + half * 3 + 1] = d0;
            part[r0 * 8 + half * 3 + 2] = c0;
        }
        if (ok1) {
            part[r1 * 8 + half * 3 + 0] = n1;
            part[r1 * 8 + half * 3 + 1] = d1;
            part[r1 * 8 + half * 3 + 2] = c1;
        }
    }
}

// ---------------- pair kernel: both directions fused, 5 barriers ----------------
__global__ __launch_bounds__(256, 3) void pair_tc(float* __restrict__ out) {
    extern __shared__ uint32_t smbuf[];
    uint32_t* uQa  = smbuf;              // 2548   (later part1 overlay)
    uint32_t* uQb  = uQa + S * QS;       // 2548   (later part0 overlay)
    uint32_t* uKa  = uQb + S * QS;       // 2548   (later P0 overlay)
    uint32_t* uKb  = uKa + S * QS;       // 2548   (later P1 overlay)
    uint32_t* uVta = uKb + S * QS;       // 3456
    uint32_t* uVtb = uVta + E * PS;      // 3456
    float*    wsum = (float*)(uVtb + E * PS);  // 16
    uint32_t* uP0  = uKa;
    uint32_t* uP1  = uKb;
    float*    part0 = (float*)uQb;
    float*    part1 = (float*)uQa;

    int a = blockIdx.x, b = blockIdx.y;
    int ia = a, ib = NB + b;
    int tid = threadIdx.x, w = tid >> 5, lane = tid & 31;
    int g = lane >> 2, tig = lane & 3;

    int mt = w >> 1, half = w & 1;
    int raQ = mt * 16 + g;
    int ntBeg = half * 4;
    int ntCnt = half ? 3 : 4;

    // ---- load all 6 tiles ----
    {
        const uint32_t* qa = g_Qb + (size_t)ia * S * (E / 2);
        const uint32_t* qb = g_Qb + (size_t)ib * S * (E / 2);
        const uint32_t* ka = g_Kb + (size_t)ia * S * (E / 2);
        const uint32_t* kb = g_Kb + (size_t)ib * S * (E / 2);
        for (int idx = tid; idx < S * 12; idx += 256) {
            int r = idx / 12, c4 = (idx % 12) * 4;
            int off = r * (E / 2) + c4;
            int so = r * QS + c4;
            *(uint4*)&uQa[so] = *(const uint4*)&qa[off];
            *(uint4*)&uQb[so] = *(const uint4*)&qb[off];
            *(uint4*)&uKa[so] = *(const uint4*)&ka[off];
            *(uint4*)&uKb[so] = *(const uint4*)&kb[off];
        }
        const uint32_t* vta = g_Vt + (size_t)ia * E * VTW;
        const uint32_t* vtb = g_Vt + (size_t)ib * E * VTW;
        for (int idx = tid; idx < E * 8; idx += 256) {
            int r = idx / 8, c4 = (idx % 8) * 4;
            *(uint4*)&uVta[r * PS + c4] = *(const uint4*)&vta[r * VTW + c4];
            *(uint4*)&uVtb[r * PS + c4] = *(const uint4*)&vtb[r * VTW + c4];
        }
    }
    __syncthreads();

    // ---- both score phases (independent MMA streams) ----
    float sc0[4][4], sc1[4][4];
    score_tiles(uQb, uKa, sc0, raQ, ntBeg, ntCnt, g, tig);   // dir0: Q_b x K_a
    score_tiles(uQa, uKb, sc1, raQ, ntBeg, ntCnt, g, tig);   // dir1: Q_a x K_b
    __syncthreads();   // all Q/K reads done -> safe to overlay P

    // ---- exp + write both P matrices ----
    exp_write(sc0, uP0, raQ, ntBeg, ntCnt, tig, half);
    exp_write(sc1, uP1, raQ, ntBeg, ntCnt, tig, half);
    __syncthreads();

    // ---- both PV + cosine-partial phases (Q tiles dead -> part overlays) ----
    pv_cos(uP0, uVta, g_V + (size_t)ib * S * E, part0, raQ, half, g, tig);  // dir0 ref = V_b
    pv_cos(uP1, uVtb, g_V + (size_t)ia * S * E, part1, raQ, half, g, tig);  // dir1 ref = V_a
    __syncthreads();

    // ---- per-row cosine + block reduction for both dirs ----
    {
        float cos0 = 0.f, cos1 = 0.f;
        if (tid < S) {
            const float* p0 = &part0[tid * 8];
            float na0 = fmaxf(sqrtf(p0[1] + p0[4]), EPSC);
            float nc0 = fmaxf(sqrtf(p0[2] + p0[5]), EPSC);
            cos0 = (p0[0] + p0[3]) / (na0 * nc0);
            const float* p1 = &part1[tid * 8];
            float na1 = fmaxf(sqrtf(p1[1] + p1[4]), EPSC);
            float nc1 = fmaxf(sqrtf(p1[2] + p1[5]), EPSC);
            cos1 = (p1[0] + p1[3]) / (na1 * nc1);
        }
#pragma unroll
        for (int o = 16; o; o >>= 1) {
            cos0 += __shfl_xor_sync(0xffffffffu, cos0, o);
            cos1 += __shfl_xor_sync(0xffffffffu, cos1, o);
        }
        if (lane == 0) { wsum[w] = cos0; wsum[8 + w] = cos1; }
    }
    __syncthreads();
    if (tid == 0)
        out[b * NB + a] = (wsum[0] + wsum[1] + wsum[8] + wsum[9]) * (1.0f / S);
}

// ---------------- launch ----------------
extern "C" void kernel_launch(void* const* d_in, const int* in_sizes, int n_in,
                              void* d_out, int out_size) {
    const float* fa  = (const float*)d_in[0];
    const float* fb  = (const float*)d_in[1];
    const float* Wq1 = (const float*)d_in[2];
    const float* Wq2 = (const float*)d_in[3];
    const float* Wk1 = (const float*)d_in[4];
    const float* Wk2 = (const float*)d_in[5];
    const float* Wv1 = (const float*)d_in[6];
    const float* Wv2 = (const float*)d_in[7];
    float* out = (float*)d_out;

    void *pW1b, *pW2b;
    cudaGetSymbolAddress(&pW1b, g_W1b);
    cudaGetSymbolAddress(&pW2b, g_W2b);

    const int smem_pair = (4 * S * QS + 2 * E * PS + 16) * (int)sizeof(uint32_t);  // ~68.5 KB
    cudaFuncSetAttribute(pair_tc, cudaFuncAttributeMaxDynamicSharedMemorySize, smem_pair);

    transpose_kernel<<<dim3(24, 128, 2), 256>>>(fa, fb);
    convwb<<<dim3(24, 24, 3), 256>>>(Wq1, Wk1, Wv1, (uint32_t*)pW1b, C, (size_t)C * CW);
    convwb<<<dim3(24, 3, 3), 256>>>(Wq2, Wk2, Wv2, (uint32_t*)pW2b, E, (size_t)E * CW);

    gemm1_relu_bf16<<<dim3(C / 128, RTOT / 128, 3), 256>>>();
    gemm2_bf16<<<dim3(1, RTOT / 64, 3), 256>>>();

    vtrans_kernel<<<2 * NB, 256>>>();

    pair_tc<<<dim3(NB, NB), 256, smem_pair>>>(out);
}